// round 6
// baseline (speedup 1.0000x reference)
#include <cuda_runtime.h>
#include <math.h>
#include <stdint.h>

// ---------------- problem constants ----------------
#define Bb 2
#define Sb 1024
#define Hd 2048
#define NH 16
#define NOPE 128
#define ROPE 64
#define VD 128
#define QKD 192
#define QLR 1536
#define KVLR 512
#define DATT 576
#define MBS (Bb*Sb)

// ---------------- scratch ----------------
__device__ float g_qa    [MBS * QLR];
__device__ float g_qaln  [MBS * QLR];
__device__ float g_kva   [MBS * DATT];
__device__ float g_q     [MBS * NH * QKD];
__device__ float g_qattn [MBS * NH * DATT];
__device__ float g_kattn [MBS * DATT];
__device__ float g_scores[(size_t)Bb*NH*Sb*Sb];
__device__ float g_ctx   [MBS * NH * KVLR];
__device__ float g_outfl [MBS * NH * VD];
__device__ float g_wukT  [NH * KVLR * NOPE];   // [h][512][128] rounded
__device__ float g_wuvT  [NH * VD * KVLR];     // [h][128][512] rounded
__device__ float g_kcT   [Bb * KVLR * Sb];     // [b][512][1024] rounded
// pre-rounded copies of external inputs
__device__ float g_hid   [MBS * Hd];
__device__ float g_wqa   [QLR * Hd];
__device__ float g_wqb   [NH * QKD * QLR];
__device__ float g_wkva  [DATT * Hd];
__device__ float g_wo    [Hd * NH * VD];

// ---------------- helpers ----------------
__device__ __forceinline__ uint32_t su32(const void* p) {
    uint32_t a;
    asm("{ .reg .u64 t; cvta.to.shared.u64 t, %1; cvt.u32.u64 %0, t; }" : "=r"(a) : "l"(p));
    return a;
}
__device__ __forceinline__ float rtf(float f) {
    uint32_t u; asm("cvt.rna.tf32.f32 %0, %1;" : "=r"(u) : "f"(f));
    return __uint_as_float(u);
}
__device__ __forceinline__ void mma_tf32(float c[4], const uint32_t a[4], const uint32_t b[2]) {
    asm volatile(
        "mma.sync.aligned.m16n8k8.row.col.f32.tf32.tf32.f32 "
        "{%0,%1,%2,%3},{%4,%5,%6,%7},{%8,%9},{%0,%1,%2,%3};"
        : "+f"(c[0]), "+f"(c[1]), "+f"(c[2]), "+f"(c[3])
        : "r"(a[0]), "r"(a[1]), "r"(a[2]), "r"(a[3]), "r"(b[0]), "r"(b[1]));
}
#define CP_ASYNC16(dst, src, sz) \
    asm volatile("cp.async.cg.shared.global [%0], [%1], 16, %2;" \
                 :: "r"(dst), "l"(src), "r"(sz) : "memory")
#define CP_COMMIT() asm volatile("cp.async.commit_group;" ::: "memory")
#define CP_WAIT(n)  asm volatile("cp.async.wait_group %0;" :: "n"(n) : "memory")

// ---------------- tf32 mma GEMM: 128x128 block, 4 warps (64x64 warp tile) ----
// C[m,n] = sum_k A[m,k] * B[n,k]  (A [M,K] row-major, B [N,K] row-major)
// Operands MUST already be tf32-rounded in global memory.
// batched via z offsets: off = (z / dX) * sXd + (z % mX) * sXm
#define BM 128
#define BN 128
#define BKK 32
#define LDS_STRIDE 36
#define TILE_F (BM * LDS_STRIDE)

__global__ void __launch_bounds__(128, 2)
mma_gemm(const float* __restrict__ A, int lda, long long sAd, int dA, long long sAm, int mA,
         const float* __restrict__ B, int ldb, long long sBd, int dB, long long sBm, int mB,
         float*       __restrict__ C, int ldc, long long sCd, int dC, long long sCm, int mC,
         int M, int N, int K, int causal, int trunck, int roundC)
{
    const int mBase = blockIdx.y * BM;
    const int nBase = blockIdx.x * BN;
    if (causal && nBase > mBase + BM - 1) return;

    extern __shared__ float sm[];                 // [A0][A1][B0][B1]
    float* Abuf = sm;
    float* Bbuf = sm + 2 * TILE_F;
    const uint32_t sAbase = su32(Abuf);
    const uint32_t sBbase = su32(Bbuf);

    const int z = blockIdx.z;
    const float* Ab = A + (size_t)(z / dA) * sAd + (size_t)(z % mA) * sAm;
    const float* Bp = B + (size_t)(z / dB) * sBd + (size_t)(z % mB) * sBm;
    float*       Cb = C + (size_t)(z / dC) * sCd + (size_t)(z % mC) * sCm;

    const int tid  = threadIdx.x;       // 0..127
    const int lane = tid & 31;
    const int warp = tid >> 5;          // 0..3
    const int wm   = warp & 1;          // 2 warps in M (64 rows each)
    const int wn   = warp >> 1;         // 2 warps in N (64 cols each)
    const int g    = lane >> 2;
    const int tig  = lane & 3;

    float acc[4][8][4];
#pragma unroll
    for (int i = 0; i < 4; i++)
#pragma unroll
        for (int j = 0; j < 8; j++)
#pragma unroll
            for (int r = 0; r < 4; r++) acc[i][j][r] = 0.f;

    int Ke = K;
    if (trunck) { int lim = mBase + BM; if (lim < Ke) Ke = lim; }
    const int nc = Ke / BKK;

    auto copy_chunk = [&](int ci, int p) {
        const int k0 = ci * BKK;
        const uint32_t aD = sAbase + (uint32_t)p * TILE_F * 4;
        const uint32_t bD = sBbase + (uint32_t)p * TILE_F * 4;
#pragma unroll
        for (int q = 0; q < 8; q++) {
            int slot = tid + q * 128;           // 0..1023
            int row  = slot >> 3;               // 0..127
            int c4   = (slot & 7) << 2;
            uint32_t soff = (uint32_t)(row * LDS_STRIDE + c4) * 4;
            CP_ASYNC16(aD + soff, Ab + (size_t)(mBase + row) * lda + k0 + c4, 16);
            int gn = nBase + row;
            const float* bsrc = (gn < N) ? (Bp + (size_t)gn * ldb + k0 + c4) : Bp;
            int sz = (gn < N) ? 16 : 0;         // sz=0 -> zero-fill
            CP_ASYNC16(bD + soff, bsrc, sz);
        }
        CP_COMMIT();
    };

    copy_chunk(0, 0);

    for (int i = 0; i < nc; i++) {
        const int p = i & 1;
        if (i + 1 < nc) { copy_chunk(i + 1, p ^ 1); CP_WAIT(1); }
        else            { CP_WAIT(0); }
        __syncthreads();

        const float* As = Abuf + p * TILE_F;
        const float* Bs = Bbuf + p * TILE_F;
#pragma unroll
        for (int ks = 0; ks < 4; ks++) {
            const int kc = ks * 8;
            uint32_t a[4][4], b[8][2];
#pragma unroll
            for (int ii = 0; ii < 4; ii++) {
                int r0 = wm * 64 + ii * 16 + g;
                a[ii][0] = __float_as_uint(As[(r0)     * LDS_STRIDE + kc + tig]);
                a[ii][1] = __float_as_uint(As[(r0 + 8) * LDS_STRIDE + kc + tig]);
                a[ii][2] = __float_as_uint(As[(r0)     * LDS_STRIDE + kc + tig + 4]);
                a[ii][3] = __float_as_uint(As[(r0 + 8) * LDS_STRIDE + kc + tig + 4]);
            }
#pragma unroll
            for (int jj = 0; jj < 8; jj++) {
                int n0 = wn * 64 + jj * 8 + g;
                b[jj][0] = __float_as_uint(Bs[n0 * LDS_STRIDE + kc + tig]);
                b[jj][1] = __float_as_uint(Bs[n0 * LDS_STRIDE + kc + tig + 4]);
            }
#pragma unroll
            for (int ii = 0; ii < 4; ii++)
#pragma unroll
                for (int jj = 0; jj < 8; jj++)
                    mma_tf32(acc[ii][jj], a[ii], b[jj]);
        }
        __syncthreads();
    }

    // ---- epilogue ----
#pragma unroll
    for (int i = 0; i < 4; i++) {
        int r0 = mBase + (wm << 6) + (i << 4) + g;
#pragma unroll
        for (int j = 0; j < 8; j++) {
            int col = nBase + (wn << 6) + (j << 3) + (tig << 1);
            if (col < N) {
                float v0 = acc[i][j][0], v1 = acc[i][j][1];
                float v2 = acc[i][j][2], v3 = acc[i][j][3];
                if (roundC) { v0 = rtf(v0); v1 = rtf(v1); v2 = rtf(v2); v3 = rtf(v3); }
                *(float2*)(Cb + (size_t)r0 * ldc + col)       = make_float2(v0, v1);
                *(float2*)(Cb + (size_t)(r0 + 8) * ldc + col) = make_float2(v2, v3);
            }
        }
    }
}

// ---------------- tf32 rounding pass (n % 4 == 0) ----------------
__global__ void round_pass(const float* __restrict__ in, float* __restrict__ out, int n4)
{
    int stride = gridDim.x * blockDim.x;
    for (int i = blockIdx.x * blockDim.x + threadIdx.x; i < n4; i += stride) {
        float4 v = ((const float4*)in)[i];
        v.x = rtf(v.x); v.y = rtf(v.y); v.z = rtf(v.z); v.w = rtf(v.w);
        ((float4*)out)[i] = v;
    }
}

// ---------------- transpose (+tf32 round): out[z][n][m] = in[z][m][n] --------
__global__ void transpose_k(const float* __restrict__ in, long long sIn, int ldin,
                            float* __restrict__ out, long long sOut, int ldout)
{
    __shared__ float t[32][33];
    const float* ib = in + (size_t)blockIdx.z * sIn;
    float* ob = out + (size_t)blockIdx.z * sOut;
    int x0 = blockIdx.x * 32, y0 = blockIdx.y * 32;
    int tx = threadIdx.x, ty = threadIdx.y;
#pragma unroll
    for (int j = 0; j < 32; j += 8)
        t[ty + j][tx] = ib[(size_t)(y0 + ty + j) * ldin + x0 + tx];
    __syncthreads();
#pragma unroll
    for (int j = 0; j < 32; j += 8)
        ob[(size_t)(x0 + ty + j) * ldout + y0 + tx] = rtf(t[tx][ty + j]);
}

// ---------------- LayerNorm (tf32-rounded output) ----------------
__global__ void ln_rows(const float* __restrict__ in, int ldin,
                        const float* __restrict__ w,
                        float* __restrict__ out, int ldout, int dim)
{
    int r = blockIdx.x;
    const float* x = in + (size_t)r * ldin;
    float* y = out + (size_t)r * ldout;
    __shared__ float red[256];
    int tid = threadIdx.x;

    float s = 0.f;
    for (int i = tid; i < dim; i += 256) s += x[i];
    red[tid] = s; __syncthreads();
    for (int o = 128; o > 0; o >>= 1) { if (tid < o) red[tid] += red[tid + o]; __syncthreads(); }
    float mean = red[0] / dim;
    __syncthreads();

    float v = 0.f;
    for (int i = tid; i < dim; i += 256) { float d = x[i] - mean; v += d * d; }
    red[tid] = v; __syncthreads();
    for (int o = 128; o > 0; o >>= 1) { if (tid < o) red[tid] += red[tid + o]; __syncthreads(); }
    float rstd = rsqrtf(red[0] / dim + 1e-5f);

    for (int i = tid; i < dim; i += 256)
        y[i] = rtf((x[i] - mean) * rstd * w[i]);
}

// ---------------- RoPE k_pe (rounded) ----------------
__global__ void rope_k(const float* __restrict__ cosb, const float* __restrict__ sinb)
{
    int r = blockIdx.x;
    int i = threadIdx.x;
    const float* src = g_kva + (size_t)r * DATT + KVLR;
    float x = src[i];
    float other = src[(i < 32) ? (i + 32) : (i - 32)];
    float rot = (i < 32) ? -other : other;
    g_kattn[(size_t)r * DATT + KVLR + i] = rtf(x * cosb[r * ROPE + i] + rot * sinb[r * ROPE + i]);
}

// ---------------- RoPE q_pe (rounded) ----------------
__global__ void rope_q(const float* __restrict__ cosb, const float* __restrict__ sinb)
{
    int bs = blockIdx.x >> 4;
    int h  = blockIdx.x & 15;
    int i  = threadIdx.x;
    const float* src = g_q + (size_t)bs * (NH * QKD) + h * QKD + NOPE;
    float x = src[i];
    float other = src[(i < 32) ? (i + 32) : (i - 32)];
    float rot = (i < 32) ? -other : other;
    g_qattn[(size_t)bs * (NH * DATT) + h * DATT + KVLR + i] =
        rtf(x * cosb[bs * ROPE + i] + rot * sinb[bs * ROPE + i]);
}

// ---------------- causal softmax (scale folded, rounded, fill to 128) --------
__global__ void softmax_causal()
{
    int r = blockIdx.x;
    int q = r & (Sb - 1);
    float* row = g_scores + (size_t)r * Sb;
    int n = q + 1;
    int nfill = ((q >> 7) + 1) << 7;
    const float scale = 0.07216878364870323f; // 1/sqrt(192)
    __shared__ float red[256];
    int tid = threadIdx.x;

    float mx = -3.4e38f;
    for (int i = tid; i < n; i += 256) mx = fmaxf(mx, row[i] * scale);
    red[tid] = mx; __syncthreads();
    for (int o = 128; o > 0; o >>= 1) { if (tid < o) red[tid] = fmaxf(red[tid], red[tid + o]); __syncthreads(); }
    mx = red[0];
    __syncthreads();

    float s = 0.f;
    for (int i = tid; i < n; i += 256) {
        float e = expf(row[i] * scale - mx);
        row[i] = e;
        s += e;
    }
    red[tid] = s; __syncthreads();
    for (int o = 128; o > 0; o >>= 1) { if (tid < o) red[tid] += red[tid + o]; __syncthreads(); }
    float inv = 1.f / red[0];

    for (int i = tid; i < n; i += 256) row[i] = rtf(row[i] * inv);
    for (int i = n + tid; i < nfill; i += 256) row[i] = 0.f;
}

// ---------------- launch ----------------
extern "C" void kernel_launch(void* const* d_in, const int* in_sizes, int n_in,
                              void* d_out, int out_size)
{
    const float* hidden  = (const float*)d_in[0];
    const float* cosb    = (const float*)d_in[1];
    const float* sinb    = (const float*)d_in[2];
    const float* w_qa    = (const float*)d_in[3];
    const float* qalnw   = (const float*)d_in[4];
    const float* w_qb    = (const float*)d_in[5];
    const float* w_kva   = (const float*)d_in[6];
    const float* kvalnw  = (const float*)d_in[7];
    const float* W_UK_T  = (const float*)d_in[8];
    const float* W_UV    = (const float*)d_in[9];
    const float* w_o     = (const float*)d_in[10];
    float* out = (float*)d_out;

    float *p_qa, *p_qaln, *p_kva, *p_q, *p_qattn, *p_kattn, *p_sc, *p_ctx, *p_of;
    float *p_wukT, *p_wuvT, *p_kcT, *p_hid, *p_wqa, *p_wqb, *p_wkva, *p_wo;
    cudaGetSymbolAddress((void**)&p_qa,    g_qa);
    cudaGetSymbolAddress((void**)&p_qaln,  g_qaln);
    cudaGetSymbolAddress((void**)&p_kva,   g_kva);
    cudaGetSymbolAddress((void**)&p_q,     g_q);
    cudaGetSymbolAddress((void**)&p_qattn, g_qattn);
    cudaGetSymbolAddress((void**)&p_kattn, g_kattn);
    cudaGetSymbolAddress((void**)&p_sc,    g_scores);
    cudaGetSymbolAddress((void**)&p_ctx,   g_ctx);
    cudaGetSymbolAddress((void**)&p_of,    g_outfl);
    cudaGetSymbolAddress((void**)&p_wukT,  g_wukT);
    cudaGetSymbolAddress((void**)&p_wuvT,  g_wuvT);
    cudaGetSymbolAddress((void**)&p_kcT,   g_kcT);
    cudaGetSymbolAddress((void**)&p_hid,   g_hid);
    cudaGetSymbolAddress((void**)&p_wqa,   g_wqa);
    cudaGetSymbolAddress((void**)&p_wqb,   g_wqb);
    cudaGetSymbolAddress((void**)&p_wkva,  g_wkva);
    cudaGetSymbolAddress((void**)&p_wo,    g_wo);

    const int SMEM = 4 * TILE_F * 4;   // 73728 bytes
    cudaFuncSetAttribute(mma_gemm, cudaFuncAttributeMaxDynamicSharedMemorySize, SMEM);

    auto grid = [](int M, int N, int z) {
        return dim3((N + BN - 1) / BN, M / BM, z);
    };
    const int T = 128;

    // ---- pre-round external inputs to tf32 ----
    round_pass<<<592, 256>>>(hidden, p_hid,  MBS * Hd / 4);
    round_pass<<<592, 256>>>(w_qa,   p_wqa,  QLR * Hd / 4);
    round_pass<<<592, 256>>>(w_qb,   p_wqb,  NH * QKD * QLR / 4);
    round_pass<<<592, 256>>>(w_kva,  p_wkva, DATT * Hd / 4);
    round_pass<<<592, 256>>>(w_o,    p_wo,   Hd * NH * VD / 4);

    // 1) qa = hid @ wqa^T   [2048,1536] K=2048  (no round: feeds LN only)
    mma_gemm<<<grid(MBS, QLR, 1), T, SMEM>>>(
        p_hid, Hd, 0,1,0,1,  p_wqa, Hd, 0,1,0,1,  p_qa, QLR, 0,1,0,1,  MBS, QLR, Hd, 0, 0, 0);

    // 2) kva = hid @ wkva^T [2048,576] K=2048  (no round: feeds LN/rope)
    mma_gemm<<<grid(MBS, DATT, 1), T, SMEM>>>(
        p_hid, Hd, 0,1,0,1,  p_wkva, Hd, 0,1,0,1,  p_kva, DATT, 0,1,0,1,  MBS, DATT, Hd, 0, 0, 0);

    // 3) LN(qa) -> rounded
    ln_rows<<<MBS, 256>>>(p_qa, QLR, qalnw, p_qaln, QLR, QLR);

    // 4) LN(kv_c) -> kattn[:, :512] rounded
    ln_rows<<<MBS, 256>>>(p_kva, DATT, kvalnw, p_kattn, DATT, KVLR);

    // 5) rope(k_pe) rounded
    rope_k<<<MBS, 64>>>(cosb, sinb);

    // T1) W_UK_T -> g_wukT (rounded)
    transpose_k<<<dim3(16, 4, NH), dim3(32, 8)>>>(
        W_UK_T, (long long)NOPE * KVLR, KVLR, p_wukT, (long long)KVLR * NOPE, NOPE);

    // T2) W_UV -> g_wuvT (rounded)
    transpose_k<<<dim3(4, 16, NH), dim3(32, 8)>>>(
        W_UV, (long long)KVLR * VD, VD, p_wuvT, (long long)VD * KVLR, KVLR);

    // T3) kv_c -> g_kcT (rounded; input already rounded)
    transpose_k<<<dim3(16, 32, Bb), dim3(32, 8)>>>(
        p_kattn, (long long)Sb * DATT, DATT, p_kcT, (long long)KVLR * Sb, Sb);

    // 6) q = qaln @ wqb^T   [2048,3072] K=1536  (round: feeds GEMM 8 A)
    mma_gemm<<<grid(MBS, NH * QKD, 1), T, SMEM>>>(
        p_qaln, QLR, 0,1,0,1,  p_wqb, QLR, 0,1,0,1,  p_q, NH * QKD, 0,1,0,1,  MBS, NH * QKD, QLR, 0, 0, 1);

    // 7) rope(q_pe) rounded
    rope_q<<<MBS * NH, 64>>>(cosb, sinb);

    // 8) q_lat: per h, q_nope @ wukT[h]^T  M=2048,N=512,K=128  (round)
    mma_gemm<<<grid(MBS, KVLR, NH), T, SMEM>>>(
        p_q, NH * QKD, 0,1, QKD, NH,
        p_wukT, NOPE, 0,1, (long long)KVLR * NOPE, NH,
        p_qattn, NH * DATT, 0,1, DATT, NH,
        MBS, KVLR, NOPE, 0, 0, 1);

    // 9) scores [1024,1024] K=576, causal  (no round: softmax rounds)
    mma_gemm<<<grid(Sb, Sb, Bb * NH), T, SMEM>>>(
        p_qattn, NH * DATT, (long long)Sb * NH * DATT, NH, DATT, NH,
        p_kattn, DATT, (long long)Sb * DATT, NH, 0, 1,
        p_sc, Sb, (long long)Sb * Sb, 1, 0, 1,
        Sb, Sb, DATT, 1, 0, 0);

    // 10) causal softmax (rounded output)
    softmax_causal<<<Bb * NH * Sb, 256>>>();

    // 11) ctx [1024,512] K trunc  (round: feeds GEMM 12 A)
    mma_gemm<<<grid(Sb, KVLR, Bb * NH), T, SMEM>>>(
        p_sc, Sb, (long long)Sb * Sb, 1, 0, 1,
        p_kcT, Sb, (long long)KVLR * Sb, NH, 0, 1,
        p_ctx, NH * KVLR, (long long)Sb * NH * KVLR, NH, KVLR, NH,
        Sb, KVLR, Sb, 0, 1, 1);

    // 12) out: ctx @ wuvT[h]^T [1024,128] K=512  (round: feeds GEMM 13 A)
    mma_gemm<<<grid(Sb, VD, Bb * NH), T, SMEM>>>(
        p_ctx, NH * KVLR, (long long)Sb * NH * KVLR, NH, KVLR, NH,
        p_wuvT, KVLR, 0,1, (long long)VD * KVLR, NH,
        p_of, NH * VD, (long long)Sb * NH * VD, NH, VD, NH,
        Sb, VD, KVLR, 0, 0, 1);

    // 13) final [2048,2048] K=2048  (no round: final output)
    mma_gemm<<<grid(MBS, Hd, 1), T, SMEM>>>(
        p_of, NH * VD, 0,1,0,1,  p_wo, NH * VD, 0,1,0,1,  out, Hd, 0,1,0,1,  MBS, Hd, NH * VD, 0, 0, 0);
}

// round 7
// speedup vs baseline: 1.4688x; 1.4688x over previous
#include <cuda_runtime.h>
#include <math.h>
#include <stdint.h>

// ---------------- problem constants ----------------
#define Bb 2
#define Sb 1024
#define Hd 2048
#define NH 16
#define NOPE 128
#define ROPE 64
#define VD 128
#define QKD 192
#define QLR 1536
#define KVLR 512
#define DATT 576
#define MBS (Bb*Sb)

// ---------------- scratch ----------------
__device__ float g_qa    [MBS * QLR];
__device__ float g_qaln  [MBS * QLR];
__device__ float g_kva   [MBS * DATT];
__device__ float g_q     [MBS * NH * QKD];
__device__ float g_qattn [MBS * NH * DATT];
__device__ float g_kattn [MBS * DATT];
__device__ float g_scores[(size_t)Bb*NH*Sb*Sb];
__device__ float g_ctx   [MBS * NH * KVLR];
__device__ float g_outfl [MBS * NH * VD];
__device__ float g_wukT  [NH * KVLR * NOPE];   // [h][512][128] rounded
__device__ float g_wuvT  [NH * VD * KVLR];     // [h][128][512] rounded
__device__ float g_kcT   [Bb * KVLR * Sb];     // [b][512][1024] rounded
// pre-rounded copies of external inputs
__device__ float g_hid   [MBS * Hd];
__device__ float g_wqa   [QLR * Hd];
__device__ float g_wqb   [NH * QKD * QLR];
__device__ float g_wkva  [DATT * Hd];
__device__ float g_wo    [Hd * NH * VD];

// ---------------- helpers ----------------
__device__ __forceinline__ uint32_t su32(const void* p) {
    uint32_t a;
    asm("{ .reg .u64 t; cvta.to.shared.u64 t, %1; cvt.u32.u64 %0, t; }" : "=r"(a) : "l"(p));
    return a;
}
__device__ __forceinline__ float rtf(float f) {
    uint32_t u; asm("cvt.rna.tf32.f32 %0, %1;" : "=r"(u) : "f"(f));
    return __uint_as_float(u);
}
__device__ __forceinline__ void mma_tf32(float c[4], const uint32_t a[4], const uint32_t b[2]) {
    asm volatile(
        "mma.sync.aligned.m16n8k8.row.col.f32.tf32.tf32.f32 "
        "{%0,%1,%2,%3},{%4,%5,%6,%7},{%8,%9},{%0,%1,%2,%3};"
        : "+f"(c[0]), "+f"(c[1]), "+f"(c[2]), "+f"(c[3])
        : "r"(a[0]), "r"(a[1]), "r"(a[2]), "r"(a[3]), "r"(b[0]), "r"(b[1]));
}
#define CP_ASYNC16(dst, src, sz) \
    asm volatile("cp.async.cg.shared.global [%0], [%1], 16, %2;" \
                 :: "r"(dst), "l"(src), "r"(sz) : "memory")
#define CP_COMMIT() asm volatile("cp.async.commit_group;" ::: "memory")
#define CP_WAIT(n)  asm volatile("cp.async.wait_group %0;" :: "n"(n) : "memory")

// ---------------- tf32 mma GEMM: 128x128 block, 8 warps (64x32 warp tile) ----
// C[m,n] = sum_k A[m,k] * B[n,k]  (A [M,K] row-major, B [N,K] row-major)
// Operands MUST already be tf32-rounded in global memory.
// batched via z offsets: off = (z / dX) * sXd + (z % mX) * sXm
#define BM 128
#define BN 128
#define BKK 32
#define LDS_STRIDE 36
#define TILE_F (BM * LDS_STRIDE)

__global__ void __launch_bounds__(256, 2)
mma_gemm(const float* __restrict__ A, int lda, long long sAd, int dA, long long sAm, int mA,
         const float* __restrict__ B, int ldb, long long sBd, int dB, long long sBm, int mB,
         float*       __restrict__ C, int ldc, long long sCd, int dC, long long sCm, int mC,
         int M, int N, int K, int causal, int trunck, int roundC)
{
    const int mBase = blockIdx.y * BM;
    const int nBase = blockIdx.x * BN;
    if (causal && nBase > mBase + BM - 1) return;

    extern __shared__ float sm[];                 // [A0][A1][B0][B1]
    float* Abuf = sm;
    float* Bbuf = sm + 2 * TILE_F;
    const uint32_t sAbase = su32(Abuf);
    const uint32_t sBbase = su32(Bbuf);

    const int z = blockIdx.z;
    const float* Ab = A + (size_t)(z / dA) * sAd + (size_t)(z % mA) * sAm;
    const float* Bp = B + (size_t)(z / dB) * sBd + (size_t)(z % mB) * sBm;
    float*       Cb = C + (size_t)(z / dC) * sCd + (size_t)(z % mC) * sCm;

    const int tid  = threadIdx.x;       // 0..255
    const int lane = tid & 31;
    const int warp = tid >> 5;          // 0..7
    const int wm   = warp & 1;          // 2 warps in M (64 rows)
    const int wn   = warp >> 1;         // 4 warps in N (32 cols)
    const int g    = lane >> 2;
    const int tig  = lane & 3;

    float acc[4][4][4];
#pragma unroll
    for (int i = 0; i < 4; i++)
#pragma unroll
        for (int j = 0; j < 4; j++)
#pragma unroll
            for (int r = 0; r < 4; r++) acc[i][j][r] = 0.f;

    int Ke = K;
    if (trunck) { int lim = mBase + BM; if (lim < Ke) Ke = lim; }
    const int nc = Ke / BKK;

    auto copy_chunk = [&](int ci, int p) {
        const int k0 = ci * BKK;
        const uint32_t aD = sAbase + (uint32_t)p * TILE_F * 4;
        const uint32_t bD = sBbase + (uint32_t)p * TILE_F * 4;
#pragma unroll
        for (int q = 0; q < 4; q++) {
            int slot = tid + q * 256;           // 0..1023
            int row  = slot >> 3;               // 0..127
            int c4   = (slot & 7) << 2;
            uint32_t soff = (uint32_t)(row * LDS_STRIDE + c4) * 4;
            CP_ASYNC16(aD + soff, Ab + (size_t)(mBase + row) * lda + k0 + c4, 16);
            int gn = nBase + row;
            const float* bsrc = (gn < N) ? (Bp + (size_t)gn * ldb + k0 + c4) : Bp;
            int sz = (gn < N) ? 16 : 0;         // sz=0 -> zero-fill
            CP_ASYNC16(bD + soff, bsrc, sz);
        }
        CP_COMMIT();
    };

    copy_chunk(0, 0);

    for (int i = 0; i < nc; i++) {
        const int p = i & 1;
        if (i + 1 < nc) { copy_chunk(i + 1, p ^ 1); CP_WAIT(1); }
        else            { CP_WAIT(0); }
        __syncthreads();

        const float* As = Abuf + p * TILE_F;
        const float* Bs = Bbuf + p * TILE_F;
#pragma unroll
        for (int ks = 0; ks < 4; ks++) {
            const int kc = ks * 8;
            uint32_t a[4][4], b[4][2];
#pragma unroll
            for (int ii = 0; ii < 4; ii++) {
                int r0 = wm * 64 + ii * 16 + g;
                a[ii][0] = __float_as_uint(As[(r0)     * LDS_STRIDE + kc + tig]);
                a[ii][1] = __float_as_uint(As[(r0 + 8) * LDS_STRIDE + kc + tig]);
                a[ii][2] = __float_as_uint(As[(r0)     * LDS_STRIDE + kc + tig + 4]);
                a[ii][3] = __float_as_uint(As[(r0 + 8) * LDS_STRIDE + kc + tig + 4]);
            }
#pragma unroll
            for (int jj = 0; jj < 4; jj++) {
                int n0 = wn * 32 + jj * 8 + g;
                b[jj][0] = __float_as_uint(Bs[n0 * LDS_STRIDE + kc + tig]);
                b[jj][1] = __float_as_uint(Bs[n0 * LDS_STRIDE + kc + tig + 4]);
            }
#pragma unroll
            for (int ii = 0; ii < 4; ii++)
#pragma unroll
                for (int jj = 0; jj < 4; jj++)
                    mma_tf32(acc[ii][jj], a[ii], b[jj]);
        }
        __syncthreads();
    }

    // ---- epilogue ----
#pragma unroll
    for (int i = 0; i < 4; i++) {
        int r0 = mBase + (wm << 6) + (i << 4) + g;
#pragma unroll
        for (int j = 0; j < 4; j++) {
            int col = nBase + (wn << 5) + (j << 3) + (tig << 1);
            if (col < N) {
                float v0 = acc[i][j][0], v1 = acc[i][j][1];
                float v2 = acc[i][j][2], v3 = acc[i][j][3];
                if (roundC) { v0 = rtf(v0); v1 = rtf(v1); v2 = rtf(v2); v3 = rtf(v3); }
                *(float2*)(Cb + (size_t)r0 * ldc + col)       = make_float2(v0, v1);
                *(float2*)(Cb + (size_t)(r0 + 8) * ldc + col) = make_float2(v2, v3);
            }
        }
    }
}

// ---------------- tf32 rounding pass (n % 4 == 0) ----------------
__global__ void round_pass(const float* __restrict__ in, float* __restrict__ out, int n4)
{
    int stride = gridDim.x * blockDim.x;
    for (int i = blockIdx.x * blockDim.x + threadIdx.x; i < n4; i += stride) {
        float4 v = ((const float4*)in)[i];
        v.x = rtf(v.x); v.y = rtf(v.y); v.z = rtf(v.z); v.w = rtf(v.w);
        ((float4*)out)[i] = v;
    }
}

// ---------------- transpose (+tf32 round): out[z][n][m] = in[z][m][n] --------
__global__ void transpose_k(const float* __restrict__ in, long long sIn, int ldin,
                            float* __restrict__ out, long long sOut, int ldout)
{
    __shared__ float t[32][33];
    const float* ib = in + (size_t)blockIdx.z * sIn;
    float* ob = out + (size_t)blockIdx.z * sOut;
    int x0 = blockIdx.x * 32, y0 = blockIdx.y * 32;
    int tx = threadIdx.x, ty = threadIdx.y;
#pragma unroll
    for (int j = 0; j < 32; j += 8)
        t[ty + j][tx] = ib[(size_t)(y0 + ty + j) * ldin + x0 + tx];
    __syncthreads();
#pragma unroll
    for (int j = 0; j < 32; j += 8)
        ob[(size_t)(x0 + ty + j) * ldout + y0 + tx] = rtf(t[tx][ty + j]);
}

// ---------------- LayerNorm (tf32-rounded output) ----------------
__global__ void ln_rows(const float* __restrict__ in, int ldin,
                        const float* __restrict__ w,
                        float* __restrict__ out, int ldout, int dim)
{
    int r = blockIdx.x;
    const float* x = in + (size_t)r * ldin;
    float* y = out + (size_t)r * ldout;
    __shared__ float red[256];
    int tid = threadIdx.x;

    float s = 0.f;
    for (int i = tid; i < dim; i += 256) s += x[i];
    red[tid] = s; __syncthreads();
    for (int o = 128; o > 0; o >>= 1) { if (tid < o) red[tid] += red[tid + o]; __syncthreads(); }
    float mean = red[0] / dim;
    __syncthreads();

    float v = 0.f;
    for (int i = tid; i < dim; i += 256) { float d = x[i] - mean; v += d * d; }
    red[tid] = v; __syncthreads();
    for (int o = 128; o > 0; o >>= 1) { if (tid < o) red[tid] += red[tid + o]; __syncthreads(); }
    float rstd = rsqrtf(red[0] / dim + 1e-5f);

    for (int i = tid; i < dim; i += 256)
        y[i] = rtf((x[i] - mean) * rstd * w[i]);
}

// ---------------- RoPE k_pe (rounded) ----------------
__global__ void rope_k(const float* __restrict__ cosb, const float* __restrict__ sinb)
{
    int r = blockIdx.x;
    int i = threadIdx.x;
    const float* src = g_kva + (size_t)r * DATT + KVLR;
    float x = src[i];
    float other = src[(i < 32) ? (i + 32) : (i - 32)];
    float rot = (i < 32) ? -other : other;
    g_kattn[(size_t)r * DATT + KVLR + i] = rtf(x * cosb[r * ROPE + i] + rot * sinb[r * ROPE + i]);
}

// ---------------- RoPE q_pe (rounded) ----------------
__global__ void rope_q(const float* __restrict__ cosb, const float* __restrict__ sinb)
{
    int bs = blockIdx.x >> 4;
    int h  = blockIdx.x & 15;
    int i  = threadIdx.x;
    const float* src = g_q + (size_t)bs * (NH * QKD) + h * QKD + NOPE;
    float x = src[i];
    float other = src[(i < 32) ? (i + 32) : (i - 32)];
    float rot = (i < 32) ? -other : other;
    g_qattn[(size_t)bs * (NH * DATT) + h * DATT + KVLR + i] =
        rtf(x * cosb[bs * ROPE + i] + rot * sinb[bs * ROPE + i]);
}

// ---------------- causal softmax (scale folded, rounded, fill to 128) --------
__global__ void softmax_causal()
{
    int r = blockIdx.x;
    int q = r & (Sb - 1);
    float* row = g_scores + (size_t)r * Sb;
    int n = q + 1;
    int nfill = ((q >> 7) + 1) << 7;
    const float scale = 0.07216878364870323f; // 1/sqrt(192)
    __shared__ float red[256];
    int tid = threadIdx.x;

    float mx = -3.4e38f;
    for (int i = tid; i < n; i += 256) mx = fmaxf(mx, row[i] * scale);
    red[tid] = mx; __syncthreads();
    for (int o = 128; o > 0; o >>= 1) { if (tid < o) red[tid] = fmaxf(red[tid], red[tid + o]); __syncthreads(); }
    mx = red[0];
    __syncthreads();

    float s = 0.f;
    for (int i = tid; i < n; i += 256) {
        float e = expf(row[i] * scale - mx);
        row[i] = e;
        s += e;
    }
    red[tid] = s; __syncthreads();
    for (int o = 128; o > 0; o >>= 1) { if (tid < o) red[tid] += red[tid + o]; __syncthreads(); }
    float inv = 1.f / red[0];

    for (int i = tid; i < n; i += 256) row[i] = rtf(row[i] * inv);
    for (int i = n + tid; i < nfill; i += 256) row[i] = 0.f;
}

// ---------------- launch ----------------
extern "C" void kernel_launch(void* const* d_in, const int* in_sizes, int n_in,
                              void* d_out, int out_size)
{
    const float* hidden  = (const float*)d_in[0];
    const float* cosb    = (const float*)d_in[1];
    const float* sinb    = (const float*)d_in[2];
    const float* w_qa    = (const float*)d_in[3];
    const float* qalnw   = (const float*)d_in[4];
    const float* w_qb    = (const float*)d_in[5];
    const float* w_kva   = (const float*)d_in[6];
    const float* kvalnw  = (const float*)d_in[7];
    const float* W_UK_T  = (const float*)d_in[8];
    const float* W_UV    = (const float*)d_in[9];
    const float* w_o     = (const float*)d_in[10];
    float* out = (float*)d_out;

    float *p_qa, *p_qaln, *p_kva, *p_q, *p_qattn, *p_kattn, *p_sc, *p_ctx, *p_of;
    float *p_wukT, *p_wuvT, *p_kcT, *p_hid, *p_wqa, *p_wqb, *p_wkva, *p_wo;
    cudaGetSymbolAddress((void**)&p_qa,    g_qa);
    cudaGetSymbolAddress((void**)&p_qaln,  g_qaln);
    cudaGetSymbolAddress((void**)&p_kva,   g_kva);
    cudaGetSymbolAddress((void**)&p_q,     g_q);
    cudaGetSymbolAddress((void**)&p_qattn, g_qattn);
    cudaGetSymbolAddress((void**)&p_kattn, g_kattn);
    cudaGetSymbolAddress((void**)&p_sc,    g_scores);
    cudaGetSymbolAddress((void**)&p_ctx,   g_ctx);
    cudaGetSymbolAddress((void**)&p_of,    g_outfl);
    cudaGetSymbolAddress((void**)&p_wukT,  g_wukT);
    cudaGetSymbolAddress((void**)&p_wuvT,  g_wuvT);
    cudaGetSymbolAddress((void**)&p_kcT,   g_kcT);
    cudaGetSymbolAddress((void**)&p_hid,   g_hid);
    cudaGetSymbolAddress((void**)&p_wqa,   g_wqa);
    cudaGetSymbolAddress((void**)&p_wqb,   g_wqb);
    cudaGetSymbolAddress((void**)&p_wkva,  g_wkva);
    cudaGetSymbolAddress((void**)&p_wo,    g_wo);

    const int SMEM = 4 * TILE_F * 4;   // 73728 bytes
    cudaFuncSetAttribute(mma_gemm, cudaFuncAttributeMaxDynamicSharedMemorySize, SMEM);

    auto grid = [](int M, int N, int z) {
        return dim3((N + BN - 1) / BN, M / BM, z);
    };
    const int T = 256;

    // ---- pre-round external inputs to tf32 ----
    round_pass<<<592, 256>>>(hidden, p_hid,  MBS * Hd / 4);
    round_pass<<<592, 256>>>(w_qa,   p_wqa,  QLR * Hd / 4);
    round_pass<<<592, 256>>>(w_qb,   p_wqb,  NH * QKD * QLR / 4);
    round_pass<<<592, 256>>>(w_kva,  p_wkva, DATT * Hd / 4);
    round_pass<<<592, 256>>>(w_o,    p_wo,   Hd * NH * VD / 4);

    // 1) qa = hid @ wqa^T   [2048,1536] K=2048  (no round: feeds LN only)
    mma_gemm<<<grid(MBS, QLR, 1), T, SMEM>>>(
        p_hid, Hd, 0,1,0,1,  p_wqa, Hd, 0,1,0,1,  p_qa, QLR, 0,1,0,1,  MBS, QLR, Hd, 0, 0, 0);

    // 2) kva = hid @ wkva^T [2048,576] K=2048  (no round: feeds LN/rope)
    mma_gemm<<<grid(MBS, DATT, 1), T, SMEM>>>(
        p_hid, Hd, 0,1,0,1,  p_wkva, Hd, 0,1,0,1,  p_kva, DATT, 0,1,0,1,  MBS, DATT, Hd, 0, 0, 0);

    // 3) LN(qa) -> rounded
    ln_rows<<<MBS, 256>>>(p_qa, QLR, qalnw, p_qaln, QLR, QLR);

    // 4) LN(kv_c) -> kattn[:, :512] rounded
    ln_rows<<<MBS, 256>>>(p_kva, DATT, kvalnw, p_kattn, DATT, KVLR);

    // 5) rope(k_pe) rounded
    rope_k<<<MBS, 64>>>(cosb, sinb);

    // T1) W_UK_T -> g_wukT (rounded)
    transpose_k<<<dim3(16, 4, NH), dim3(32, 8)>>>(
        W_UK_T, (long long)NOPE * KVLR, KVLR, p_wukT, (long long)KVLR * NOPE, NOPE);

    // T2) W_UV -> g_wuvT (rounded)
    transpose_k<<<dim3(4, 16, NH), dim3(32, 8)>>>(
        W_UV, (long long)KVLR * VD, VD, p_wuvT, (long long)VD * KVLR, KVLR);

    // T3) kv_c -> g_kcT (rounded; input already rounded)
    transpose_k<<<dim3(16, 32, Bb), dim3(32, 8)>>>(
        p_kattn, (long long)Sb * DATT, DATT, p_kcT, (long long)KVLR * Sb, Sb);

    // 6) q = qaln @ wqb^T   [2048,3072] K=1536  (round: feeds GEMM 8 A)
    mma_gemm<<<grid(MBS, NH * QKD, 1), T, SMEM>>>(
        p_qaln, QLR, 0,1,0,1,  p_wqb, QLR, 0,1,0,1,  p_q, NH * QKD, 0,1,0,1,  MBS, NH * QKD, QLR, 0, 0, 1);

    // 7) rope(q_pe) rounded
    rope_q<<<MBS * NH, 64>>>(cosb, sinb);

    // 8) q_lat: per h, q_nope @ wukT[h]^T  M=2048,N=512,K=128  (round)
    mma_gemm<<<grid(MBS, KVLR, NH), T, SMEM>>>(
        p_q, NH * QKD, 0,1, QKD, NH,
        p_wukT, NOPE, 0,1, (long long)KVLR * NOPE, NH,
        p_qattn, NH * DATT, 0,1, DATT, NH,
        MBS, KVLR, NOPE, 0, 0, 1);

    // 9) scores [1024,1024] K=576, causal  (no round: softmax rounds)
    mma_gemm<<<grid(Sb, Sb, Bb * NH), T, SMEM>>>(
        p_qattn, NH * DATT, (long long)Sb * NH * DATT, NH, DATT, NH,
        p_kattn, DATT, (long long)Sb * DATT, NH, 0, 1,
        p_sc, Sb, (long long)Sb * Sb, 1, 0, 1,
        Sb, Sb, DATT, 1, 0, 0);

    // 10) causal softmax (rounded output)
    softmax_causal<<<Bb * NH * Sb, 256>>>();

    // 11) ctx [1024,512] K trunc  (round: feeds GEMM 12 A)
    mma_gemm<<<grid(Sb, KVLR, Bb * NH), T, SMEM>>>(
        p_sc, Sb, (long long)Sb * Sb, 1, 0, 1,
        p_kcT, Sb, (long long)KVLR * Sb, NH, 0, 1,
        p_ctx, NH * KVLR, (long long)Sb * NH * KVLR, NH, KVLR, NH,
        Sb, KVLR, Sb, 0, 1, 1);

    // 12) out: ctx @ wuvT[h]^T [1024,128] K=512  (round: feeds GEMM 13 A)
    mma_gemm<<<grid(Sb, VD, Bb * NH), T, SMEM>>>(
        p_ctx, NH * KVLR, (long long)Sb * NH * KVLR, NH, KVLR, NH,
        p_wuvT, KVLR, 0,1, (long long)VD * KVLR, NH,
        p_of, NH * VD, (long long)Sb * NH * VD, NH, VD, NH,
        Sb, VD, KVLR, 0, 0, 1);

    // 13) final [2048,2048] K=2048  (no round: final output)
    mma_gemm<<<grid(MBS, Hd, 1), T, SMEM>>>(
        p_of, NH * VD, 0,1,0,1,  p_wo, NH * VD, 0,1,0,1,  out, Hd, 0,1,0,1,  MBS, Hd, NH * VD, 0, 0, 0);
}

// round 8
// speedup vs baseline: 2.3746x; 1.6167x over previous
#include <cuda_runtime.h>
#include <cuda_fp16.h>
#include <math.h>
#include <stdint.h>

// ---------------- problem constants ----------------
#define Bb 2
#define Sb 1024
#define Hd 2048
#define NH 16
#define NOPE 128
#define ROPE 64
#define VD 128
#define QKD 192
#define QLR 1536
#define KVLR 512
#define DATT 576
#define MBS (Bb*Sb)

// ---------------- scratch ----------------
// f32
__device__ float  g_qa    [MBS * QLR];
__device__ float  g_kva   [MBS * DATT];
__device__ float  g_scores[(size_t)Bb*NH*Sb*Sb];
// fp16 operands
__device__ __half g_hid   [MBS * Hd];
__device__ __half g_wqa   [QLR * Hd];
__device__ __half g_wqb   [NH * QKD * QLR];
__device__ __half g_wkva  [DATT * Hd];
__device__ __half g_wo    [Hd * NH * VD];
__device__ __half g_qaln  [MBS * QLR];
__device__ __half g_q     [MBS * NH * QKD];
__device__ __half g_qattn [MBS * NH * DATT];
__device__ __half g_kattn [MBS * DATT];
__device__ __half g_p     [(size_t)Bb*NH*Sb*Sb];
__device__ __half g_ctx   [MBS * NH * KVLR];
__device__ __half g_outfl [MBS * NH * VD];
__device__ __half g_wukT  [NH * KVLR * NOPE];   // [h][512][128]
__device__ __half g_wuvT  [NH * VD * KVLR];     // [h][128][512]
__device__ __half g_kcT   [Bb * KVLR * Sb];     // [b][512][1024]

// ---------------- helpers ----------------
__device__ __forceinline__ uint32_t su32(const void* p) {
    uint32_t a;
    asm("{ .reg .u64 t; cvta.to.shared.u64 t, %1; cvt.u32.u64 %0, t; }" : "=r"(a) : "l"(p));
    return a;
}
__device__ __forceinline__ void mma_f16(float c[4], const uint32_t a[4], const uint32_t b[2]) {
    asm volatile(
        "mma.sync.aligned.m16n8k16.row.col.f32.f16.f16.f32 "
        "{%0,%1,%2,%3},{%4,%5,%6,%7},{%8,%9},{%0,%1,%2,%3};"
        : "+f"(c[0]), "+f"(c[1]), "+f"(c[2]), "+f"(c[3])
        : "r"(a[0]), "r"(a[1]), "r"(a[2]), "r"(a[3]), "r"(b[0]), "r"(b[1]));
}
#define CP_ASYNC16(dst, src, sz) \
    asm volatile("cp.async.cg.shared.global [%0], [%1], 16, %2;" \
                 :: "r"(dst), "l"(src), "r"(sz) : "memory")
#define CP_COMMIT() asm volatile("cp.async.commit_group;" ::: "memory")
#define CP_WAIT(n)  asm volatile("cp.async.wait_group %0;" :: "n"(n) : "memory")

// ---------------- fp16 mma GEMM: 128x128 block, 8 warps (64x32 warp tile) ----
// C[m,n] = sum_k A[m,k] * B[n,k]  (A [M,K] half row-major, B [N,K] half row-major)
// batched via z offsets: off = (z / dX) * sXd + (z % mX) * sXm  (element units)
#define BM 128
#define BN 128
#define BKK 64
#define WSH 36                 // uint32 words per smem row (64 halves + 8 pad)
#define TILE_W (BM * WSH)      // words per tile buffer (18432 B)

__global__ void __launch_bounds__(256, 2)
mma_gemm(const __half* __restrict__ A, int lda, long long sAd, int dA, long long sAm, int mA,
         const __half* __restrict__ B, int ldb, long long sBd, int dB, long long sBm, int mB,
         void*         __restrict__ Cv, int ldc, long long sCd, int dC, long long sCm, int mC,
         int M, int N, int K, int causal, int trunck, int outHalf)
{
    const int mBase = blockIdx.y * BM;
    const int nBase = blockIdx.x * BN;
    if (causal && nBase > mBase + BM - 1) return;

    extern __shared__ uint32_t smw[];           // [A0][A1][B0][B1]
    const uint32_t sAbase = su32(smw);
    const uint32_t sBbase = sAbase + 2u * TILE_W * 4u;

    const int z = blockIdx.z;
    const __half* Ab = A + (size_t)(z / dA) * sAd + (size_t)(z % mA) * sAm;
    const __half* Bp = B + (size_t)(z / dB) * sBd + (size_t)(z % mB) * sBm;
    const size_t  cOff = (size_t)(z / dC) * sCd + (size_t)(z % mC) * sCm;

    const int tid  = threadIdx.x;       // 0..255
    const int lane = tid & 31;
    const int warp = tid >> 5;          // 0..7
    const int wm   = warp & 1;          // 2 warps in M (64 rows)
    const int wn   = warp >> 1;         // 4 warps in N (32 cols)
    const int g    = lane >> 2;
    const int tig  = lane & 3;

    float acc[4][4][4];
#pragma unroll
    for (int i = 0; i < 4; i++)
#pragma unroll
        for (int j = 0; j < 4; j++)
#pragma unroll
            for (int r = 0; r < 4; r++) acc[i][j][r] = 0.f;

    int Ke = K;
    if (trunck) { int lim = mBase + BM; if (lim < Ke) Ke = lim; }
    const int nc = Ke / BKK;

    auto copy_chunk = [&](int ci, int p) {
        const int k0 = ci * BKK;
        const uint32_t aD = sAbase + (uint32_t)p * TILE_W * 4u;
        const uint32_t bD = sBbase + (uint32_t)p * TILE_W * 4u;
#pragma unroll
        for (int q = 0; q < 4; q++) {
            int slot = tid + q * 256;           // 0..1023
            int row  = slot >> 3;               // 0..127
            int c8   = (slot & 7) << 3;         // 0..56 (halves)
            uint32_t soff = (uint32_t)(row * (WSH * 4) + c8 * 2);
            CP_ASYNC16(aD + soff, Ab + (size_t)(mBase + row) * lda + k0 + c8, 16);
            int gn = nBase + row;
            const __half* bsrc = (gn < N) ? (Bp + (size_t)gn * ldb + k0 + c8) : Bp;
            int sz = (gn < N) ? 16 : 0;         // sz=0 -> zero-fill
            CP_ASYNC16(bD + soff, bsrc, sz);
        }
        CP_COMMIT();
    };

    copy_chunk(0, 0);

    for (int i = 0; i < nc; i++) {
        const int p = i & 1;
        if (i + 1 < nc) { copy_chunk(i + 1, p ^ 1); CP_WAIT(1); }
        else            { CP_WAIT(0); }
        __syncthreads();

        const uint32_t* Aw = smw + (size_t)p * TILE_W;
        const uint32_t* Bw = smw + 2 * TILE_W + (size_t)p * TILE_W;
#pragma unroll
        for (int ks = 0; ks < 4; ks++) {
            const int kw = ks * 8;              // word offset within row (16 halves)
            uint32_t a[4][4], b[4][2];
#pragma unroll
            for (int ii = 0; ii < 4; ii++) {
                int r0 = wm * 64 + ii * 16 + g;
                a[ii][0] = Aw[(r0)     * WSH + kw + tig];
                a[ii][1] = Aw[(r0 + 8) * WSH + kw + tig];
                a[ii][2] = Aw[(r0)     * WSH + kw + tig + 4];
                a[ii][3] = Aw[(r0 + 8) * WSH + kw + tig + 4];
            }
#pragma unroll
            for (int jj = 0; jj < 4; jj++) {
                int n0 = wn * 32 + jj * 8 + g;
                b[jj][0] = Bw[n0 * WSH + kw + tig];
                b[jj][1] = Bw[n0 * WSH + kw + tig + 4];
            }
#pragma unroll
            for (int ii = 0; ii < 4; ii++)
#pragma unroll
                for (int jj = 0; jj < 4; jj++)
                    mma_f16(acc[ii][jj], a[ii], b[jj]);
        }
        __syncthreads();
    }

    // ---- epilogue ----
    if (outHalf) {
        __half* Ch = (__half*)Cv + cOff;
#pragma unroll
        for (int i = 0; i < 4; i++) {
            int r0 = mBase + (wm << 6) + (i << 4) + g;
#pragma unroll
            for (int j = 0; j < 4; j++) {
                int col = nBase + (wn << 5) + (j << 3) + (tig << 1);
                if (col < N) {
                    *(__half2*)(Ch + (size_t)r0 * ldc + col) =
                        __floats2half2_rn(acc[i][j][0], acc[i][j][1]);
                    *(__half2*)(Ch + (size_t)(r0 + 8) * ldc + col) =
                        __floats2half2_rn(acc[i][j][2], acc[i][j][3]);
                }
            }
        }
    } else {
        float* Cf = (float*)Cv + cOff;
#pragma unroll
        for (int i = 0; i < 4; i++) {
            int r0 = mBase + (wm << 6) + (i << 4) + g;
#pragma unroll
            for (int j = 0; j < 4; j++) {
                int col = nBase + (wn << 5) + (j << 3) + (tig << 1);
                if (col < N) {
                    *(float2*)(Cf + (size_t)r0 * ldc + col)       = make_float2(acc[i][j][0], acc[i][j][1]);
                    *(float2*)(Cf + (size_t)(r0 + 8) * ldc + col) = make_float2(acc[i][j][2], acc[i][j][3]);
                }
            }
        }
    }
}

// ---------------- f32 -> f16 conversion pass (n % 4 == 0) ----------------
__global__ void cvt_pass(const float* __restrict__ in, __half* __restrict__ out, int n4)
{
    int stride = gridDim.x * blockDim.x;
    for (int i = blockIdx.x * blockDim.x + threadIdx.x; i < n4; i += stride) {
        float4 v = ((const float4*)in)[i];
        __half2 h0 = __floats2half2_rn(v.x, v.y);
        __half2 h1 = __floats2half2_rn(v.z, v.w);
        ((__half2*)out)[2 * i]     = h0;
        ((__half2*)out)[2 * i + 1] = h1;
    }
}

// ---------------- transpose f32 -> f16: out[z][n][m] = in[z][m][n] ----------
__global__ void transpose_f32h(const float* __restrict__ in, long long sIn, int ldin,
                               __half* __restrict__ out, long long sOut, int ldout)
{
    __shared__ float t[32][33];
    const float* ib = in + (size_t)blockIdx.z * sIn;
    __half* ob = out + (size_t)blockIdx.z * sOut;
    int x0 = blockIdx.x * 32, y0 = blockIdx.y * 32;
    int tx = threadIdx.x, ty = threadIdx.y;
#pragma unroll
    for (int j = 0; j < 32; j += 8)
        t[ty + j][tx] = ib[(size_t)(y0 + ty + j) * ldin + x0 + tx];
    __syncthreads();
#pragma unroll
    for (int j = 0; j < 32; j += 8)
        ob[(size_t)(x0 + ty + j) * ldout + y0 + tx] = __float2half_rn(t[tx][ty + j]);
}

// ---------------- transpose f16 -> f16 ----------------
__global__ void transpose_hh(const __half* __restrict__ in, long long sIn, int ldin,
                             __half* __restrict__ out, long long sOut, int ldout)
{
    __shared__ float t[32][33];
    const __half* ib = in + (size_t)blockIdx.z * sIn;
    __half* ob = out + (size_t)blockIdx.z * sOut;
    int x0 = blockIdx.x * 32, y0 = blockIdx.y * 32;
    int tx = threadIdx.x, ty = threadIdx.y;
#pragma unroll
    for (int j = 0; j < 32; j += 8)
        t[ty + j][tx] = __half2float(ib[(size_t)(y0 + ty + j) * ldin + x0 + tx]);
    __syncthreads();
#pragma unroll
    for (int j = 0; j < 32; j += 8)
        ob[(size_t)(x0 + ty + j) * ldout + y0 + tx] = __float2half_rn(t[tx][ty + j]);
}

// ---------------- LayerNorm: f32 in -> f16 out ----------------
__global__ void ln_rows(const float* __restrict__ in, int ldin,
                        const float* __restrict__ w,
                        __half* __restrict__ out, int ldout, int dim)
{
    int r = blockIdx.x;
    const float* x = in + (size_t)r * ldin;
    __half* y = out + (size_t)r * ldout;
    __shared__ float red[256];
    int tid = threadIdx.x;

    float s = 0.f;
    for (int i = tid; i < dim; i += 256) s += x[i];
    red[tid] = s; __syncthreads();
    for (int o = 128; o > 0; o >>= 1) { if (tid < o) red[tid] += red[tid + o]; __syncthreads(); }
    float mean = red[0] / dim;
    __syncthreads();

    float v = 0.f;
    for (int i = tid; i < dim; i += 256) { float d = x[i] - mean; v += d * d; }
    red[tid] = v; __syncthreads();
    for (int o = 128; o > 0; o >>= 1) { if (tid < o) red[tid] += red[tid + o]; __syncthreads(); }
    float rstd = rsqrtf(red[0] / dim + 1e-5f);

    for (int i = tid; i < dim; i += 256)
        y[i] = __float2half_rn((x[i] - mean) * rstd * w[i]);
}

// ---------------- RoPE k_pe: f32 kva -> f16 kattn ----------------
__global__ void rope_k(const float* __restrict__ cosb, const float* __restrict__ sinb)
{
    int r = blockIdx.x;
    int i = threadIdx.x;
    const float* src = g_kva + (size_t)r * DATT + KVLR;
    float x = src[i];
    float other = src[(i < 32) ? (i + 32) : (i - 32)];
    float rot = (i < 32) ? -other : other;
    g_kattn[(size_t)r * DATT + KVLR + i] =
        __float2half_rn(x * cosb[r * ROPE + i] + rot * sinb[r * ROPE + i]);
}

// ---------------- RoPE q_pe: f16 q -> f16 qattn ----------------
__global__ void rope_q(const float* __restrict__ cosb, const float* __restrict__ sinb)
{
    int bs = blockIdx.x >> 4;
    int h  = blockIdx.x & 15;
    int i  = threadIdx.x;
    const __half* src = g_q + (size_t)bs * (NH * QKD) + h * QKD + NOPE;
    float x = __half2float(src[i]);
    float other = __half2float(src[(i < 32) ? (i + 32) : (i - 32)]);
    float rot = (i < 32) ? -other : other;
    g_qattn[(size_t)bs * (NH * DATT) + h * DATT + KVLR + i] =
        __float2half_rn(x * cosb[bs * ROPE + i] + rot * sinb[bs * ROPE + i]);
}

// ---------------- causal softmax: f32 scores -> f16 p (fill to 128) ---------
__global__ void softmax_causal()
{
    int r = blockIdx.x;
    int q = r & (Sb - 1);
    float* row = g_scores + (size_t)r * Sb;
    __half* prow = g_p + (size_t)r * Sb;
    int n = q + 1;
    int nfill = ((q >> 7) + 1) << 7;
    const float scale = 0.07216878364870323f; // 1/sqrt(192)
    __shared__ float red[256];
    int tid = threadIdx.x;

    float mx = -3.4e38f;
    for (int i = tid; i < n; i += 256) mx = fmaxf(mx, row[i] * scale);
    red[tid] = mx; __syncthreads();
    for (int o = 128; o > 0; o >>= 1) { if (tid < o) red[tid] = fmaxf(red[tid], red[tid + o]); __syncthreads(); }
    mx = red[0];
    __syncthreads();

    float s = 0.f;
    for (int i = tid; i < n; i += 256) {
        float e = expf(row[i] * scale - mx);
        row[i] = e;
        s += e;
    }
    red[tid] = s; __syncthreads();
    for (int o = 128; o > 0; o >>= 1) { if (tid < o) red[tid] += red[tid + o]; __syncthreads(); }
    float inv = 1.f / red[0];

    for (int i = tid; i < n; i += 256) prow[i] = __float2half_rn(row[i] * inv);
    for (int i = n + tid; i < nfill; i += 256) prow[i] = __float2half_rn(0.f);
}

// ---------------- launch ----------------
extern "C" void kernel_launch(void* const* d_in, const int* in_sizes, int n_in,
                              void* d_out, int out_size)
{
    const float* hidden  = (const float*)d_in[0];
    const float* cosb    = (const float*)d_in[1];
    const float* sinb    = (const float*)d_in[2];
    const float* w_qa    = (const float*)d_in[3];
    const float* qalnw   = (const float*)d_in[4];
    const float* w_qb    = (const float*)d_in[5];
    const float* w_kva   = (const float*)d_in[6];
    const float* kvalnw  = (const float*)d_in[7];
    const float* W_UK_T  = (const float*)d_in[8];
    const float* W_UV    = (const float*)d_in[9];
    const float* w_o     = (const float*)d_in[10];
    float* out = (float*)d_out;

    float *p_qa, *p_kva, *p_sc;
    __half *p_hid, *p_wqa, *p_wqb, *p_wkva, *p_wo;
    __half *p_qaln, *p_q, *p_qattn, *p_kattn, *p_p, *p_ctx, *p_of, *p_wukT, *p_wuvT, *p_kcT;
    cudaGetSymbolAddress((void**)&p_qa,    g_qa);
    cudaGetSymbolAddress((void**)&p_kva,   g_kva);
    cudaGetSymbolAddress((void**)&p_sc,    g_scores);
    cudaGetSymbolAddress((void**)&p_hid,   g_hid);
    cudaGetSymbolAddress((void**)&p_wqa,   g_wqa);
    cudaGetSymbolAddress((void**)&p_wqb,   g_wqb);
    cudaGetSymbolAddress((void**)&p_wkva,  g_wkva);
    cudaGetSymbolAddress((void**)&p_wo,    g_wo);
    cudaGetSymbolAddress((void**)&p_qaln,  g_qaln);
    cudaGetSymbolAddress((void**)&p_q,     g_q);
    cudaGetSymbolAddress((void**)&p_qattn, g_qattn);
    cudaGetSymbolAddress((void**)&p_kattn, g_kattn);
    cudaGetSymbolAddress((void**)&p_p,     g_p);
    cudaGetSymbolAddress((void**)&p_ctx,   g_ctx);
    cudaGetSymbolAddress((void**)&p_of,    g_outfl);
    cudaGetSymbolAddress((void**)&p_wukT,  g_wukT);
    cudaGetSymbolAddress((void**)&p_wuvT,  g_wuvT);
    cudaGetSymbolAddress((void**)&p_kcT,   g_kcT);

    const int SMEM = 4 * TILE_W * 4;   // 73728 bytes
    cudaFuncSetAttribute(mma_gemm, cudaFuncAttributeMaxDynamicSharedMemorySize, SMEM);

    auto grid = [](int M, int N, int z) {
        return dim3((N + BN - 1) / BN, M / BM, z);
    };
    const int T = 256;

    // ---- convert external inputs to fp16 ----
    cvt_pass<<<592, 256>>>(hidden, p_hid,  MBS * Hd / 4);
    cvt_pass<<<592, 256>>>(w_qa,   p_wqa,  QLR * Hd / 4);
    cvt_pass<<<592, 256>>>(w_qb,   p_wqb,  NH * QKD * QLR / 4);
    cvt_pass<<<592, 256>>>(w_kva,  p_wkva, DATT * Hd / 4);
    cvt_pass<<<592, 256>>>(w_o,    p_wo,   Hd * NH * VD / 4);

    // 1) qa(f32) = hid @ wqa^T   [2048,1536] K=2048
    mma_gemm<<<grid(MBS, QLR, 1), T, SMEM>>>(
        p_hid, Hd, 0,1,0,1,  p_wqa, Hd, 0,1,0,1,  p_qa, QLR, 0,1,0,1,  MBS, QLR, Hd, 0, 0, 0);

    // 2) kva(f32) = hid @ wkva^T [2048,576] K=2048
    mma_gemm<<<grid(MBS, DATT, 1), T, SMEM>>>(
        p_hid, Hd, 0,1,0,1,  p_wkva, Hd, 0,1,0,1,  p_kva, DATT, 0,1,0,1,  MBS, DATT, Hd, 0, 0, 0);

    // 3) LN(qa) -> qaln(h)
    ln_rows<<<MBS, 256>>>(p_qa, QLR, qalnw, p_qaln, QLR, QLR);

    // 4) LN(kv_c) -> kattn(h)[:, :512]
    ln_rows<<<MBS, 256>>>(p_kva, DATT, kvalnw, p_kattn, DATT, KVLR);

    // 5) rope(k_pe) -> kattn(h)[:, 512:576]
    rope_k<<<MBS, 64>>>(cosb, sinb);

    // T1) W_UK_T(f32) -> wukT(h) [h][512][128]
    transpose_f32h<<<dim3(16, 4, NH), dim3(32, 8)>>>(
        W_UK_T, (long long)NOPE * KVLR, KVLR, p_wukT, (long long)KVLR * NOPE, NOPE);

    // T2) W_UV(f32) -> wuvT(h) [h][128][512]
    transpose_f32h<<<dim3(4, 16, NH), dim3(32, 8)>>>(
        W_UV, (long long)KVLR * VD, VD, p_wuvT, (long long)VD * KVLR, KVLR);

    // T3) kattn(h)[:, :512] -> kcT(h) [b][512][1024]
    transpose_hh<<<dim3(16, 32, Bb), dim3(32, 8)>>>(
        p_kattn, (long long)Sb * DATT, DATT, p_kcT, (long long)KVLR * Sb, Sb);

    // 6) q(h) = qaln @ wqb^T   [2048,3072] K=1536
    mma_gemm<<<grid(MBS, NH * QKD, 1), T, SMEM>>>(
        p_qaln, QLR, 0,1,0,1,  p_wqb, QLR, 0,1,0,1,  p_q, NH * QKD, 0,1,0,1,  MBS, NH * QKD, QLR, 0, 0, 1);

    // 7) rope(q_pe) -> qattn(h)[:,:,512:576]
    rope_q<<<MBS * NH, 64>>>(cosb, sinb);

    // 8) qattn(h)[:,:,h,0:512] = q_nope @ wukT[h]^T  M=2048,N=512,K=128
    mma_gemm<<<grid(MBS, KVLR, NH), T, SMEM>>>(
        p_q, NH * QKD, 0,1, QKD, NH,
        p_wukT, NOPE, 0,1, (long long)KVLR * NOPE, NH,
        p_qattn, NH * DATT, 0,1, DATT, NH,
        MBS, KVLR, NOPE, 0, 0, 1);

    // 9) scores(f32) [1024,1024] K=576, causal skip
    mma_gemm<<<grid(Sb, Sb, Bb * NH), T, SMEM>>>(
        p_qattn, NH * DATT, (long long)Sb * NH * DATT, NH, DATT, NH,
        p_kattn, DATT, (long long)Sb * DATT, NH, 0, 1,
        p_sc, Sb, (long long)Sb * Sb, 1, 0, 1,
        Sb, Sb, DATT, 1, 0, 0);

    // 10) causal softmax -> p(h)
    softmax_causal<<<Bb * NH * Sb, 256>>>();

    // 11) ctx(h) = p @ kcT^T   [1024,512] K trunc
    mma_gemm<<<grid(Sb, KVLR, Bb * NH), T, SMEM>>>(
        p_p, Sb, (long long)Sb * Sb, 1, 0, 1,
        p_kcT, Sb, (long long)KVLR * Sb, NH, 0, 1,
        p_ctx, NH * KVLR, (long long)Sb * NH * KVLR, NH, KVLR, NH,
        Sb, KVLR, Sb, 0, 1, 1);

    // 12) outfl(h) = ctx @ wuvT[h]^T  [1024,128] K=512
    mma_gemm<<<grid(Sb, VD, Bb * NH), T, SMEM>>>(
        p_ctx, NH * KVLR, (long long)Sb * NH * KVLR, NH, KVLR, NH,
        p_wuvT, KVLR, 0,1, (long long)VD * KVLR, NH,
        p_of, NH * VD, (long long)Sb * NH * VD, NH, VD, NH,
        Sb, VD, KVLR, 0, 0, 1);

    // 13) out(f32) = outfl @ wo^T  [2048,2048] K=2048
    mma_gemm<<<grid(MBS, Hd, 1), T, SMEM>>>(
        p_of, NH * VD, 0,1,0,1,  p_wo, NH * VD, 0,1,0,1,  out, Hd, 0,1,0,1,  MBS, Hd, NH * VD, 0, 0, 0);
}

// round 9
// speedup vs baseline: 2.5426x; 1.0707x over previous
#include <cuda_runtime.h>
#include <cuda_fp16.h>
#include <math.h>
#include <stdint.h>

// ---------------- problem constants ----------------
#define Bb 2
#define Sb 1024
#define Hd 2048
#define NH 16
#define NOPE 128
#define ROPE 64
#define VD 128
#define QKD 192
#define QLR 1536
#define KVLR 512
#define DATT 576
#define MBS (Bb*Sb)
#define SCALE 0.07216878364870323f   // 1/sqrt(192)

// ---------------- scratch ----------------
__device__ float  g_qa    [MBS * QLR];
__device__ float  g_kva   [MBS * DATT];
__device__ float  g_scores[(size_t)Bb*NH*Sb*Sb];
__device__ __half g_hid   [MBS * Hd];
__device__ __half g_wqa   [QLR * Hd];
__device__ __half g_wqb   [NH * QKD * QLR];
__device__ __half g_wkva  [DATT * Hd];
__device__ __half g_wo    [Hd * NH * VD];
__device__ __half g_qaln  [MBS * QLR];
__device__ __half g_q     [MBS * NH * QKD];
__device__ __half g_qattn [MBS * NH * DATT];
__device__ __half g_kattn [MBS * DATT];
__device__ __half g_p     [(size_t)Bb*NH*Sb*Sb];
__device__ __half g_ctx   [MBS * NH * KVLR];
__device__ __half g_outfl [MBS * NH * VD];
__device__ __half g_wukT  [NH * KVLR * NOPE];
__device__ __half g_wuvT  [NH * VD * KVLR];
__device__ __half g_kcT   [Bb * KVLR * Sb];

// ---------------- helpers ----------------
__device__ __forceinline__ uint32_t su32(const void* p) {
    uint32_t a;
    asm("{ .reg .u64 t; cvta.to.shared.u64 t, %1; cvt.u32.u64 %0, t; }" : "=r"(a) : "l"(p));
    return a;
}
__device__ __forceinline__ void mma_f16(float c[4], const uint32_t a[4], const uint32_t b[2]) {
    asm volatile(
        "mma.sync.aligned.m16n8k16.row.col.f32.f16.f16.f32 "
        "{%0,%1,%2,%3},{%4,%5,%6,%7},{%8,%9},{%0,%1,%2,%3};"
        : "+f"(c[0]), "+f"(c[1]), "+f"(c[2]), "+f"(c[3])
        : "r"(a[0]), "r"(a[1]), "r"(a[2]), "r"(a[3]), "r"(b[0]), "r"(b[1]));
}
#define LDSM_X4(r0, r1, r2, r3, addr) \
    asm volatile("ldmatrix.sync.aligned.m8n8.x4.shared.b16 {%0,%1,%2,%3}, [%4];" \
                 : "=r"(r0), "=r"(r1), "=r"(r2), "=r"(r3) : "r"(addr))
#define CP_ASYNC16(dst, src, sz) \
    asm volatile("cp.async.cg.shared.global [%0], [%1], 16, %2;" \
                 :: "r"(dst), "l"(src), "r"(sz) : "memory")
#define CP_COMMIT() asm volatile("cp.async.commit_group;" ::: "memory")
#define CP_WAIT(n)  asm volatile("cp.async.wait_group %0;" :: "n"(n) : "memory")

// ---------------- fp16 mma GEMM: 128x128 block, 8 warps (64x32 warp tile) ----
#define BM 128
#define BN 128
#define BKK 64
#define WSH 36                 // uint32 words per smem row (64 halves + 8 pad)
#define TILE_W (BM * WSH)

__global__ void __launch_bounds__(256, 2)
mma_gemm(const __half* __restrict__ A, int lda, long long sAd, int dA, long long sAm, int mA,
         const __half* __restrict__ B, int ldb, long long sBd, int dB, long long sBm, int mB,
         void*         __restrict__ Cv, int ldc, long long sCd, int dC, long long sCm, int mC,
         int M, int N, int K, int causal, int trunck, int outHalf, float cscale)
{
    const int mBase = blockIdx.y * BM;
    const int nBase = blockIdx.x * BN;
    if (causal && nBase > mBase + BM - 1) return;

    extern __shared__ uint32_t smw[];           // [A0][A1][B0][B1]
    const uint32_t sAbase = su32(smw);
    const uint32_t sBbase = sAbase + 2u * TILE_W * 4u;

    const int z = blockIdx.z;
    const __half* Ab = A + (size_t)(z / dA) * sAd + (size_t)(z % mA) * sAm;
    const __half* Bp = B + (size_t)(z / dB) * sBd + (size_t)(z % mB) * sBm;
    const size_t  cOff = (size_t)(z / dC) * sCd + (size_t)(z % mC) * sCm;

    const int tid  = threadIdx.x;
    const int lane = tid & 31;
    const int warp = tid >> 5;
    const int wm   = warp & 1;          // 2 warps in M
    const int wn   = warp >> 1;         // 4 warps in N
    const int g    = lane >> 2;
    const int tig  = lane & 3;

    // ldmatrix per-lane base addresses (byte offsets into tile buffer 0)
    // A tile ii: rows (wm*64 + ii*16 + (lane&15)), col word (lane>>4)*4
    uint32_t aAddr[4];
#pragma unroll
    for (int ii = 0; ii < 4; ii++)
        aAddr[ii] = sAbase +
            (uint32_t)(((wm * 64 + ii * 16 + (lane & 15)) * WSH + ((lane >> 4) << 2)) * 4);
    // B pair q: rows (wn*32 + q*16 + (lane&7) + ((lane>>4)<<3)), col word ((lane>>3)&1)*4
    uint32_t bAddr[2];
#pragma unroll
    for (int q = 0; q < 2; q++)
        bAddr[q] = sBbase +
            (uint32_t)(((wn * 32 + q * 16 + (lane & 7) + ((lane >> 4) << 3)) * WSH
                        + (((lane >> 3) & 1) << 2)) * 4);

    float acc[4][4][4];
#pragma unroll
    for (int i = 0; i < 4; i++)
#pragma unroll
        for (int j = 0; j < 4; j++)
#pragma unroll
            for (int r = 0; r < 4; r++) acc[i][j][r] = 0.f;

    int Ke = K;
    if (trunck) { int lim = mBase + BM; if (lim < Ke) Ke = lim; }
    const int nc = Ke / BKK;

    auto copy_chunk = [&](int ci, int p) {
        const int k0 = ci * BKK;
        const uint32_t aD = sAbase + (uint32_t)p * TILE_W * 4u;
        const uint32_t bD = sBbase + (uint32_t)p * TILE_W * 4u;
#pragma unroll
        for (int q = 0; q < 4; q++) {
            int slot = tid + q * 256;
            int row  = slot >> 3;
            int c8   = (slot & 7) << 3;
            uint32_t soff = (uint32_t)(row * (WSH * 4) + c8 * 2);
            CP_ASYNC16(aD + soff, Ab + (size_t)(mBase + row) * lda + k0 + c8, 16);
            int gn = nBase + row;
            const __half* bsrc = (gn < N) ? (Bp + (size_t)gn * ldb + k0 + c8) : Bp;
            int sz = (gn < N) ? 16 : 0;
            CP_ASYNC16(bD + soff, bsrc, sz);
        }
        CP_COMMIT();
    };

    copy_chunk(0, 0);

    for (int i = 0; i < nc; i++) {
        const int p = i & 1;
        if (i + 1 < nc) { copy_chunk(i + 1, p ^ 1); CP_WAIT(1); }
        else            { CP_WAIT(0); }
        __syncthreads();

        const uint32_t pOff = (uint32_t)p * TILE_W * 4u;
#pragma unroll
        for (int ks = 0; ks < 4; ks++) {
            const uint32_t kOff = pOff + (uint32_t)ks * 32u;   // 8 words = 32 B
            uint32_t a[4][4], b[4][2];
#pragma unroll
            for (int ii = 0; ii < 4; ii++)
                LDSM_X4(a[ii][0], a[ii][1], a[ii][2], a[ii][3], aAddr[ii] + kOff);
            LDSM_X4(b[0][0], b[0][1], b[1][0], b[1][1], bAddr[0] + kOff);
            LDSM_X4(b[2][0], b[2][1], b[3][0], b[3][1], bAddr[1] + kOff);
#pragma unroll
            for (int ii = 0; ii < 4; ii++)
#pragma unroll
                for (int jj = 0; jj < 4; jj++)
                    mma_f16(acc[ii][jj], a[ii], b[jj]);
        }
        __syncthreads();
    }

    // ---- epilogue ----
    if (outHalf) {
        __half* Ch = (__half*)Cv + cOff;
#pragma unroll
        for (int i = 0; i < 4; i++) {
            int r0 = mBase + (wm << 6) + (i << 4) + g;
#pragma unroll
            for (int j = 0; j < 4; j++) {
                int col = nBase + (wn << 5) + (j << 3) + (tig << 1);
                if (col < N) {
                    *(__half2*)(Ch + (size_t)r0 * ldc + col) =
                        __floats2half2_rn(acc[i][j][0] * cscale, acc[i][j][1] * cscale);
                    *(__half2*)(Ch + (size_t)(r0 + 8) * ldc + col) =
                        __floats2half2_rn(acc[i][j][2] * cscale, acc[i][j][3] * cscale);
                }
            }
        }
    } else {
        float* Cf = (float*)Cv + cOff;
#pragma unroll
        for (int i = 0; i < 4; i++) {
            int r0 = mBase + (wm << 6) + (i << 4) + g;
#pragma unroll
            for (int j = 0; j < 4; j++) {
                int col = nBase + (wn << 5) + (j << 3) + (tig << 1);
                if (col < N) {
                    *(float2*)(Cf + (size_t)r0 * ldc + col)       = make_float2(acc[i][j][0], acc[i][j][1]);
                    *(float2*)(Cf + (size_t)(r0 + 8) * ldc + col) = make_float2(acc[i][j][2], acc[i][j][3]);
                }
            }
        }
    }
}

// ---------------- f32 -> f16 conversion pass ----------------
__global__ void cvt_pass(const float* __restrict__ in, __half* __restrict__ out, int n4)
{
    int stride = gridDim.x * blockDim.x;
    for (int i = blockIdx.x * blockDim.x + threadIdx.x; i < n4; i += stride) {
        float4 v = ((const float4*)in)[i];
        ((__half2*)out)[2 * i]     = __floats2half2_rn(v.x, v.y);
        ((__half2*)out)[2 * i + 1] = __floats2half2_rn(v.z, v.w);
    }
}

// ---------------- transpose f32 -> f16 ----------------
__global__ void transpose_f32h(const float* __restrict__ in, long long sIn, int ldin,
                               __half* __restrict__ out, long long sOut, int ldout)
{
    __shared__ float t[32][33];
    const float* ib = in + (size_t)blockIdx.z * sIn;
    __half* ob = out + (size_t)blockIdx.z * sOut;
    int x0 = blockIdx.x * 32, y0 = blockIdx.y * 32;
    int tx = threadIdx.x, ty = threadIdx.y;
#pragma unroll
    for (int j = 0; j < 32; j += 8)
        t[ty + j][tx] = ib[(size_t)(y0 + ty + j) * ldin + x0 + tx];
    __syncthreads();
#pragma unroll
    for (int j = 0; j < 32; j += 8)
        ob[(size_t)(x0 + ty + j) * ldout + y0 + tx] = __float2half_rn(t[tx][ty + j]);
}

// ---------------- transpose f16 -> f16 ----------------
__global__ void transpose_hh(const __half* __restrict__ in, long long sIn, int ldin,
                             __half* __restrict__ out, long long sOut, int ldout)
{
    __shared__ float t[32][33];
    const __half* ib = in + (size_t)blockIdx.z * sIn;
    __half* ob = out + (size_t)blockIdx.z * sOut;
    int x0 = blockIdx.x * 32, y0 = blockIdx.y * 32;
    int tx = threadIdx.x, ty = threadIdx.y;
#pragma unroll
    for (int j = 0; j < 32; j += 8)
        t[ty + j][tx] = __half2float(ib[(size_t)(y0 + ty + j) * ldin + x0 + tx]);
    __syncthreads();
#pragma unroll
    for (int j = 0; j < 32; j += 8)
        ob[(size_t)(x0 + ty + j) * ldout + y0 + tx] = __float2half_rn(t[tx][ty + j]);
}

// ---------------- LayerNorm: f32 in -> f16 out ----------------
__global__ void ln_rows(const float* __restrict__ in, int ldin,
                        const float* __restrict__ w,
                        __half* __restrict__ out, int ldout, int dim)
{
    int r = blockIdx.x;
    const float* x = in + (size_t)r * ldin;
    __half* y = out + (size_t)r * ldout;
    __shared__ float red[256];
    int tid = threadIdx.x;

    float s = 0.f;
    for (int i = tid; i < dim; i += 256) s += x[i];
    red[tid] = s; __syncthreads();
    for (int o = 128; o > 0; o >>= 1) { if (tid < o) red[tid] += red[tid + o]; __syncthreads(); }
    float mean = red[0] / dim;
    __syncthreads();

    float v = 0.f;
    for (int i = tid; i < dim; i += 256) { float d = x[i] - mean; v += d * d; }
    red[tid] = v; __syncthreads();
    for (int o = 128; o > 0; o >>= 1) { if (tid < o) red[tid] += red[tid + o]; __syncthreads(); }
    float rstd = rsqrtf(red[0] / dim + 1e-5f);

    for (int i = tid; i < dim; i += 256)
        y[i] = __float2half_rn((x[i] - mean) * rstd * w[i]);
}

// ---------------- RoPE k_pe ----------------
__global__ void rope_k(const float* __restrict__ cosb, const float* __restrict__ sinb)
{
    int r = blockIdx.x;
    int i = threadIdx.x;
    const float* src = g_kva + (size_t)r * DATT + KVLR;
    float x = src[i];
    float other = src[(i < 32) ? (i + 32) : (i - 32)];
    float rot = (i < 32) ? -other : other;
    g_kattn[(size_t)r * DATT + KVLR + i] =
        __float2half_rn(x * cosb[r * ROPE + i] + rot * sinb[r * ROPE + i]);
}

// ---------------- RoPE q_pe (scale folded) ----------------
__global__ void rope_q(const float* __restrict__ cosb, const float* __restrict__ sinb)
{
    int bs = blockIdx.x >> 4;
    int h  = blockIdx.x & 15;
    int i  = threadIdx.x;
    const __half* src = g_q + (size_t)bs * (NH * QKD) + h * QKD + NOPE;
    float x = __half2float(src[i]);
    float other = __half2float(src[(i < 32) ? (i + 32) : (i - 32)]);
    float rot = (i < 32) ? -other : other;
    g_qattn[(size_t)bs * (NH * DATT) + h * DATT + KVLR + i] =
        __float2half_rn((x * cosb[bs * ROPE + i] + rot * sinb[bs * ROPE + i]) * SCALE);
}

// ---------------- one-pass causal softmax (row cached in smem) --------------
__global__ void softmax_causal()
{
    int r = blockIdx.x;
    int q = r & (Sb - 1);
    const float* row = g_scores + (size_t)r * Sb;
    __half* prow = g_p + (size_t)r * Sb;
    int n = q + 1;
    int nfill = ((q >> 7) + 1) << 7;
    __shared__ float buf[Sb];
    __shared__ float red[256];
    int tid = threadIdx.x;

    float mx = -3.4e38f;
    for (int i = tid; i < n; i += 256) {
        float v = row[i];
        buf[i] = v;
        mx = fmaxf(mx, v);
    }
    red[tid] = mx; __syncthreads();
    for (int o = 128; o > 0; o >>= 1) { if (tid < o) red[tid] = fmaxf(red[tid], red[tid + o]); __syncthreads(); }
    mx = red[0];
    __syncthreads();

    float s = 0.f;
    for (int i = tid; i < n; i += 256) {
        float e = __expf(buf[i] - mx);
        buf[i] = e;
        s += e;
    }
    red[tid] = s; __syncthreads();
    for (int o = 128; o > 0; o >>= 1) { if (tid < o) red[tid] += red[tid + o]; __syncthreads(); }
    float inv = 1.f / red[0];

    for (int i = tid; i < n; i += 256) prow[i] = __float2half_rn(buf[i] * inv);
    for (int i = n + tid; i < nfill; i += 256) prow[i] = __float2half_rn(0.f);
}

// ---------------- launch ----------------
extern "C" void kernel_launch(void* const* d_in, const int* in_sizes, int n_in,
                              void* d_out, int out_size)
{
    const float* hidden  = (const float*)d_in[0];
    const float* cosb    = (const float*)d_in[1];
    const float* sinb    = (const float*)d_in[2];
    const float* w_qa    = (const float*)d_in[3];
    const float* qalnw   = (const float*)d_in[4];
    const float* w_qb    = (const float*)d_in[5];
    const float* w_kva   = (const float*)d_in[6];
    const float* kvalnw  = (const float*)d_in[7];
    const float* W_UK_T  = (const float*)d_in[8];
    const float* W_UV    = (const float*)d_in[9];
    const float* w_o     = (const float*)d_in[10];
    float* out = (float*)d_out;

    float *p_qa, *p_kva, *p_sc;
    __half *p_hid, *p_wqa, *p_wqb, *p_wkva, *p_wo;
    __half *p_qaln, *p_q, *p_qattn, *p_kattn, *p_p, *p_ctx, *p_of, *p_wukT, *p_wuvT, *p_kcT;
    cudaGetSymbolAddress((void**)&p_qa,    g_qa);
    cudaGetSymbolAddress((void**)&p_kva,   g_kva);
    cudaGetSymbolAddress((void**)&p_sc,    g_scores);
    cudaGetSymbolAddress((void**)&p_hid,   g_hid);
    cudaGetSymbolAddress((void**)&p_wqa,   g_wqa);
    cudaGetSymbolAddress((void**)&p_wqb,   g_wqb);
    cudaGetSymbolAddress((void**)&p_wkva,  g_wkva);
    cudaGetSymbolAddress((void**)&p_wo,    g_wo);
    cudaGetSymbolAddress((void**)&p_qaln,  g_qaln);
    cudaGetSymbolAddress((void**)&p_q,     g_q);
    cudaGetSymbolAddress((void**)&p_qattn, g_qattn);
    cudaGetSymbolAddress((void**)&p_kattn, g_kattn);
    cudaGetSymbolAddress((void**)&p_p,     g_p);
    cudaGetSymbolAddress((void**)&p_ctx,   g_ctx);
    cudaGetSymbolAddress((void**)&p_of,    g_outfl);
    cudaGetSymbolAddress((void**)&p_wukT,  g_wukT);
    cudaGetSymbolAddress((void**)&p_wuvT,  g_wuvT);
    cudaGetSymbolAddress((void**)&p_kcT,   g_kcT);

    const int SMEM = 4 * TILE_W * 4;   // 73728 bytes
    cudaFuncSetAttribute(mma_gemm, cudaFuncAttributeMaxDynamicSharedMemorySize, SMEM);

    auto grid = [](int M, int N, int z) {
        return dim3((N + BN - 1) / BN, M / BM, z);
    };
    const int T = 256;

    // ---- convert external inputs to fp16 ----
    cvt_pass<<<592, 256>>>(hidden, p_hid,  MBS * Hd / 4);
    cvt_pass<<<592, 256>>>(w_qa,   p_wqa,  QLR * Hd / 4);
    cvt_pass<<<592, 256>>>(w_qb,   p_wqb,  NH * QKD * QLR / 4);
    cvt_pass<<<592, 256>>>(w_kva,  p_wkva, DATT * Hd / 4);
    cvt_pass<<<592, 256>>>(w_o,    p_wo,   Hd * NH * VD / 4);

    // 1) qa(f32) = hid @ wqa^T   [2048,1536] K=2048
    mma_gemm<<<grid(MBS, QLR, 1), T, SMEM>>>(
        p_hid, Hd, 0,1,0,1,  p_wqa, Hd, 0,1,0,1,  p_qa, QLR, 0,1,0,1,  MBS, QLR, Hd, 0, 0, 0, 1.f);

    // 2) kva(f32) = hid @ wkva^T [2048,576] K=2048
    mma_gemm<<<grid(MBS, DATT, 1), T, SMEM>>>(
        p_hid, Hd, 0,1,0,1,  p_wkva, Hd, 0,1,0,1,  p_kva, DATT, 0,1,0,1,  MBS, DATT, Hd, 0, 0, 0, 1.f);

    // 3) LN(qa) -> qaln(h)
    ln_rows<<<MBS, 256>>>(p_qa, QLR, qalnw, p_qaln, QLR, QLR);

    // 4) LN(kv_c) -> kattn(h)[:, :512]
    ln_rows<<<MBS, 256>>>(p_kva, DATT, kvalnw, p_kattn, DATT, KVLR);

    // 5) rope(k_pe) -> kattn(h)[:, 512:576]
    rope_k<<<MBS, 64>>>(cosb, sinb);

    // T1) W_UK_T(f32) -> wukT(h) [h][512][128]
    transpose_f32h<<<dim3(16, 4, NH), dim3(32, 8)>>>(
        W_UK_T, (long long)NOPE * KVLR, KVLR, p_wukT, (long long)KVLR * NOPE, NOPE);

    // T2) W_UV(f32) -> wuvT(h) [h][128][512]
    transpose_f32h<<<dim3(4, 16, NH), dim3(32, 8)>>>(
        W_UV, (long long)KVLR * VD, VD, p_wuvT, (long long)VD * KVLR, KVLR);

    // T3) kattn(h)[:, :512] -> kcT(h) [b][512][1024]
    transpose_hh<<<dim3(16, 32, Bb), dim3(32, 8)>>>(
        p_kattn, (long long)Sb * DATT, DATT, p_kcT, (long long)KVLR * Sb, Sb);

    // 6) q(h) = qaln @ wqb^T   [2048,3072] K=1536
    mma_gemm<<<grid(MBS, NH * QKD, 1), T, SMEM>>>(
        p_qaln, QLR, 0,1,0,1,  p_wqb, QLR, 0,1,0,1,  p_q, NH * QKD, 0,1,0,1,
        MBS, NH * QKD, QLR, 0, 0, 1, 1.f);

    // 7) rope(q_pe) -> qattn(h)[:,:,512:576] (scale folded)
    rope_q<<<MBS * NH, 64>>>(cosb, sinb);

    // 8) qattn(h)[:,:,h,0:512] = (q_nope @ wukT[h]^T) * SCALE
    mma_gemm<<<grid(MBS, KVLR, NH), T, SMEM>>>(
        p_q, NH * QKD, 0,1, QKD, NH,
        p_wukT, NOPE, 0,1, (long long)KVLR * NOPE, NH,
        p_qattn, NH * DATT, 0,1, DATT, NH,
        MBS, KVLR, NOPE, 0, 0, 1, SCALE);

    // 9) scores(f32) [1024,1024] K=576, causal skip (scale already in qattn)
    mma_gemm<<<grid(Sb, Sb, Bb * NH), T, SMEM>>>(
        p_qattn, NH * DATT, (long long)Sb * NH * DATT, NH, DATT, NH,
        p_kattn, DATT, (long long)Sb * DATT, NH, 0, 1,
        p_sc, Sb, (long long)Sb * Sb, 1, 0, 1,
        Sb, Sb, DATT, 1, 0, 0, 1.f);

    // 10) causal softmax -> p(h)
    softmax_causal<<<Bb * NH * Sb, 256>>>();

    // 11) ctx(h) = p @ kcT^T   [1024,512] K trunc
    mma_gemm<<<grid(Sb, KVLR, Bb * NH), T, SMEM>>>(
        p_p, Sb, (long long)Sb * Sb, 1, 0, 1,
        p_kcT, Sb, (long long)KVLR * Sb, NH, 0, 1,
        p_ctx, NH * KVLR, (long long)Sb * NH * KVLR, NH, KVLR, NH,
        Sb, KVLR, Sb, 0, 1, 1, 1.f);

    // 12) outfl(h) = ctx @ wuvT[h]^T  [1024,128] K=512
    mma_gemm<<<grid(Sb, VD, Bb * NH), T, SMEM>>>(
        p_ctx, NH * KVLR, (long long)Sb * NH * KVLR, NH, KVLR, NH,
        p_wuvT, KVLR, 0,1, (long long)VD * KVLR, NH,
        p_of, NH * VD, (long long)Sb * NH * VD, NH, VD, NH,
        Sb, VD, KVLR, 0, 0, 1, 1.f);

    // 13) out(f32) = outfl @ wo^T  [2048,2048] K=2048
    mma_gemm<<<grid(MBS, Hd, 1), T, SMEM>>>(
        p_of, NH * VD, 0,1,0,1,  p_wo, NH * VD, 0,1,0,1,  out, Hd, 0,1,0,1,
        MBS, Hd, NH * VD, 0, 0, 0, 1.f);
}

// round 10
// speedup vs baseline: 2.7865x; 1.0959x over previous
#include <cuda_runtime.h>
#include <cuda_fp16.h>
#include <math.h>
#include <stdint.h>

// ---------------- problem constants ----------------
#define Bb 2
#define Sb 1024
#define Hd 2048
#define NH 16
#define NOPE 128
#define ROPE 64
#define VD 128
#define QKD 192
#define QLR 1536
#define KVLR 512
#define DATT 576
#define MBS (Bb*Sb)
#define SCALE 0.07216878364870323f   // 1/sqrt(192)

// ---------------- scratch ----------------
__device__ float  g_qa    [MBS * QLR];
__device__ float  g_kva   [MBS * DATT];
__device__ float  g_scores[(size_t)Bb*NH*Sb*Sb];
__device__ __half g_hid   [MBS * Hd];
__device__ __half g_wqa   [QLR * Hd];
__device__ __half g_wqb   [NH * QKD * QLR];
__device__ __half g_wkva  [DATT * Hd];
__device__ __half g_wo    [Hd * NH * VD];
__device__ __half g_qaln  [MBS * QLR];
__device__ __half g_q     [MBS * NH * QKD];
__device__ __half g_qattn [MBS * NH * DATT];
__device__ __half g_kattn [MBS * DATT];
__device__ __half g_p     [(size_t)Bb*NH*Sb*Sb];
__device__ __half g_vT    [(size_t)Bb*NH*VD*Sb];   // V'^T per (b,h): [128][1024]
__device__ __half g_outfl [MBS * NH * VD];
__device__ __half g_wukT  [NH * KVLR * NOPE];
__device__ __half g_wuvT  [NH * VD * KVLR];

// ---------------- helpers ----------------
__device__ __forceinline__ uint32_t su32(const void* p) {
    uint32_t a;
    asm("{ .reg .u64 t; cvta.to.shared.u64 t, %1; cvt.u32.u64 %0, t; }" : "=r"(a) : "l"(p));
    return a;
}
__device__ __forceinline__ void mma_f16(float c[4], const uint32_t a[4], const uint32_t b[2]) {
    asm volatile(
        "mma.sync.aligned.m16n8k16.row.col.f32.f16.f16.f32 "
        "{%0,%1,%2,%3},{%4,%5,%6,%7},{%8,%9},{%0,%1,%2,%3};"
        : "+f"(c[0]), "+f"(c[1]), "+f"(c[2]), "+f"(c[3])
        : "r"(a[0]), "r"(a[1]), "r"(a[2]), "r"(a[3]), "r"(b[0]), "r"(b[1]));
}
#define LDSM_X4(r0, r1, r2, r3, addr) \
    asm volatile("ldmatrix.sync.aligned.m8n8.x4.shared.b16 {%0,%1,%2,%3}, [%4];" \
                 : "=r"(r0), "=r"(r1), "=r"(r2), "=r"(r3) : "r"(addr))
#define CP_ASYNC16(dst, src, sz) \
    asm volatile("cp.async.cg.shared.global [%0], [%1], 16, %2;" \
                 :: "r"(dst), "l"(src), "r"(sz) : "memory")
#define CP_COMMIT() asm volatile("cp.async.commit_group;" ::: "memory")
#define CP_WAIT(n)  asm volatile("cp.async.wait_group %0;" :: "n"(n) : "memory")

// ---------------- fp16 mma GEMM: 128x128 block, 8 warps (64x32 warp tile) ----
#define BM 128
#define BN 128
#define BKK 64
#define WSH 36
#define TILE_W (BM * WSH)

__global__ void __launch_bounds__(256, 2)
mma_gemm(const __half* __restrict__ A, int lda, long long sAd, int dA, long long sAm, int mA,
         const __half* __restrict__ B, int ldb, long long sBd, int dB, long long sBm, int mB,
         void*         __restrict__ Cv, int ldc, long long sCd, int dC, long long sCm, int mC,
         int M, int N, int K, int causal, int trunck, int outHalf, float cscale)
{
    const int mBase = blockIdx.y * BM;
    const int nBase = blockIdx.x * BN;
    if (causal && nBase > mBase + BM - 1) return;

    extern __shared__ uint32_t smw[];
    const uint32_t sAbase = su32(smw);
    const uint32_t sBbase = sAbase + 2u * TILE_W * 4u;

    const int z = blockIdx.z;
    const __half* Ab = A + (size_t)(z / dA) * sAd + (size_t)(z % mA) * sAm;
    const __half* Bp = B + (size_t)(z / dB) * sBd + (size_t)(z % mB) * sBm;
    const size_t  cOff = (size_t)(z / dC) * sCd + (size_t)(z % mC) * sCm;

    const int tid  = threadIdx.x;
    const int lane = tid & 31;
    const int warp = tid >> 5;
    const int wm   = warp & 1;
    const int wn   = warp >> 1;
    const int g    = lane >> 2;
    const int tig  = lane & 3;

    uint32_t aAddr[4];
#pragma unroll
    for (int ii = 0; ii < 4; ii++)
        aAddr[ii] = sAbase +
            (uint32_t)(((wm * 64 + ii * 16 + (lane & 15)) * WSH + ((lane >> 4) << 2)) * 4);
    uint32_t bAddr[2];
#pragma unroll
    for (int q = 0; q < 2; q++)
        bAddr[q] = sBbase +
            (uint32_t)(((wn * 32 + q * 16 + (lane & 7) + ((lane >> 4) << 3)) * WSH
                        + (((lane >> 3) & 1) << 2)) * 4);

    float acc[4][4][4];
#pragma unroll
    for (int i = 0; i < 4; i++)
#pragma unroll
        for (int j = 0; j < 4; j++)
#pragma unroll
            for (int r = 0; r < 4; r++) acc[i][j][r] = 0.f;

    int Ke = K;
    if (trunck) { int lim = mBase + BM; if (lim < Ke) Ke = lim; }
    const int nc = Ke / BKK;

    auto copy_chunk = [&](int ci, int p) {
        const int k0 = ci * BKK;
        const uint32_t aD = sAbase + (uint32_t)p * TILE_W * 4u;
        const uint32_t bD = sBbase + (uint32_t)p * TILE_W * 4u;
#pragma unroll
        for (int q = 0; q < 4; q++) {
            int slot = tid + q * 256;
            int row  = slot >> 3;
            int c8   = (slot & 7) << 3;
            uint32_t soff = (uint32_t)(row * (WSH * 4) + c8 * 2);
            int gm = mBase + row;
            const __half* asrc = (gm < M) ? (Ab + (size_t)gm * lda + k0 + c8) : Ab;
            CP_ASYNC16(aD + soff, asrc, (gm < M) ? 16 : 0);
            int gn = nBase + row;
            const __half* bsrc = (gn < N) ? (Bp + (size_t)gn * ldb + k0 + c8) : Bp;
            CP_ASYNC16(bD + soff, bsrc, (gn < N) ? 16 : 0);
        }
        CP_COMMIT();
    };

    copy_chunk(0, 0);

    for (int i = 0; i < nc; i++) {
        const int p = i & 1;
        if (i + 1 < nc) { copy_chunk(i + 1, p ^ 1); CP_WAIT(1); }
        else            { CP_WAIT(0); }
        __syncthreads();

        const uint32_t pOff = (uint32_t)p * TILE_W * 4u;
#pragma unroll
        for (int ks = 0; ks < 4; ks++) {
            const uint32_t kOff = pOff + (uint32_t)ks * 32u;
            uint32_t a[4][4], b[4][2];
#pragma unroll
            for (int ii = 0; ii < 4; ii++)
                LDSM_X4(a[ii][0], a[ii][1], a[ii][2], a[ii][3], aAddr[ii] + kOff);
            LDSM_X4(b[0][0], b[0][1], b[1][0], b[1][1], bAddr[0] + kOff);
            LDSM_X4(b[2][0], b[2][1], b[3][0], b[3][1], bAddr[1] + kOff);
#pragma unroll
            for (int ii = 0; ii < 4; ii++)
#pragma unroll
                for (int jj = 0; jj < 4; jj++)
                    mma_f16(acc[ii][jj], a[ii], b[jj]);
        }
        __syncthreads();
    }

    // ---- epilogue ----
    if (outHalf) {
        __half* Ch = (__half*)Cv + cOff;
#pragma unroll
        for (int i = 0; i < 4; i++) {
            int r0 = mBase + (wm << 6) + (i << 4) + g;
            if (r0 >= M) continue;
#pragma unroll
            for (int j = 0; j < 4; j++) {
                int col = nBase + (wn << 5) + (j << 3) + (tig << 1);
                if (col < N) {
                    *(__half2*)(Ch + (size_t)r0 * ldc + col) =
                        __floats2half2_rn(acc[i][j][0] * cscale, acc[i][j][1] * cscale);
                    *(__half2*)(Ch + (size_t)(r0 + 8) * ldc + col) =
                        __floats2half2_rn(acc[i][j][2] * cscale, acc[i][j][3] * cscale);
                }
            }
        }
    } else {
        float* Cf = (float*)Cv + cOff;
#pragma unroll
        for (int i = 0; i < 4; i++) {
            int r0 = mBase + (wm << 6) + (i << 4) + g;
            if (r0 >= M) continue;
#pragma unroll
            for (int j = 0; j < 4; j++) {
                int col = nBase + (wn << 5) + (j << 3) + (tig << 1);
                if (col < N) {
                    *(float2*)(Cf + (size_t)r0 * ldc + col)       = make_float2(acc[i][j][0], acc[i][j][1]);
                    *(float2*)(Cf + (size_t)(r0 + 8) * ldc + col) = make_float2(acc[i][j][2], acc[i][j][3]);
                }
            }
        }
    }
}

// ---------------- fused f32 -> f16 conversion for 5 tensors ----------------
#define CV0 (MBS * Hd / 4)
#define CV1 (CV0 + QLR * Hd / 4)
#define CV2 (CV1 + NH * QKD * QLR / 4)
#define CV3 (CV2 + DATT * Hd / 4)
#define CV4 (CV3 + Hd * NH * VD / 4)

__global__ void cvt_all(const float* __restrict__ s0, const float* __restrict__ s1,
                        const float* __restrict__ s2, const float* __restrict__ s3,
                        const float* __restrict__ s4)
{
    __half *d;
    const float *s;
    int stride = gridDim.x * blockDim.x;
    for (int i = blockIdx.x * blockDim.x + threadIdx.x; i < CV4; i += stride) {
        int off;
        if (i < CV0)      { s = s0; off = i;       d = g_hid; }
        else if (i < CV1) { s = s1; off = i - CV0; d = g_wqa; }
        else if (i < CV2) { s = s2; off = i - CV1; d = g_wqb; }
        else if (i < CV3) { s = s3; off = i - CV2; d = g_wkva; }
        else              { s = s4; off = i - CV3; d = g_wo; }
        float4 v = ((const float4*)s)[off];
        ((__half2*)d)[2 * off]     = __floats2half2_rn(v.x, v.y);
        ((__half2*)d)[2 * off + 1] = __floats2half2_rn(v.z, v.w);
    }
}

// ---------------- transpose f32 -> f16 ----------------
__global__ void transpose_f32h(const float* __restrict__ in, long long sIn, int ldin,
                               __half* __restrict__ out, long long sOut, int ldout)
{
    __shared__ float t[32][33];
    const float* ib = in + (size_t)blockIdx.z * sIn;
    __half* ob = out + (size_t)blockIdx.z * sOut;
    int x0 = blockIdx.x * 32, y0 = blockIdx.y * 32;
    int tx = threadIdx.x, ty = threadIdx.y;
#pragma unroll
    for (int j = 0; j < 32; j += 8)
        t[ty + j][tx] = ib[(size_t)(y0 + ty + j) * ldin + x0 + tx];
    __syncthreads();
#pragma unroll
    for (int j = 0; j < 32; j += 8)
        ob[(size_t)(x0 + ty + j) * ldout + y0 + tx] = __float2half_rn(t[tx][ty + j]);
}

// ---------------- LayerNorm: f32 in -> f16 out ----------------
__global__ void ln_rows(const float* __restrict__ in, int ldin,
                        const float* __restrict__ w,
                        __half* __restrict__ out, int ldout, int dim)
{
    int r = blockIdx.x;
    const float* x = in + (size_t)r * ldin;
    __half* y = out + (size_t)r * ldout;
    __shared__ float red[256];
    int tid = threadIdx.x;

    float s = 0.f;
    for (int i = tid; i < dim; i += 256) s += x[i];
    red[tid] = s; __syncthreads();
    for (int o = 128; o > 0; o >>= 1) { if (tid < o) red[tid] += red[tid + o]; __syncthreads(); }
    float mean = red[0] / dim;
    __syncthreads();

    float v = 0.f;
    for (int i = tid; i < dim; i += 256) { float d = x[i] - mean; v += d * d; }
    red[tid] = v; __syncthreads();
    for (int o = 128; o > 0; o >>= 1) { if (tid < o) red[tid] += red[tid + o]; __syncthreads(); }
    float rstd = rsqrtf(red[0] / dim + 1e-5f);

    for (int i = tid; i < dim; i += 256)
        y[i] = __float2half_rn((x[i] - mean) * rstd * w[i]);
}

// ---------------- RoPE k_pe ----------------
__global__ void rope_k(const float* __restrict__ cosb, const float* __restrict__ sinb)
{
    int r = blockIdx.x;
    int i = threadIdx.x;
    const float* src = g_kva + (size_t)r * DATT + KVLR;
    float x = src[i];
    float other = src[(i < 32) ? (i + 32) : (i - 32)];
    float rot = (i < 32) ? -other : other;
    g_kattn[(size_t)r * DATT + KVLR + i] =
        __float2half_rn(x * cosb[r * ROPE + i] + rot * sinb[r * ROPE + i]);
}

// ---------------- RoPE q_pe (scale folded) ----------------
__global__ void rope_q(const float* __restrict__ cosb, const float* __restrict__ sinb)
{
    int bs = blockIdx.x >> 4;
    int h  = blockIdx.x & 15;
    int i  = threadIdx.x;
    const __half* src = g_q + (size_t)bs * (NH * QKD) + h * QKD + NOPE;
    float x = __half2float(src[i]);
    float other = __half2float(src[(i < 32) ? (i + 32) : (i - 32)]);
    float rot = (i < 32) ? -other : other;
    g_qattn[(size_t)bs * (NH * DATT) + h * DATT + KVLR + i] =
        __float2half_rn((x * cosb[bs * ROPE + i] + rot * sinb[bs * ROPE + i]) * SCALE);
}

// ---------------- one-pass causal softmax (row cached in smem) --------------
__global__ void softmax_causal()
{
    int r = blockIdx.x;
    int q = r & (Sb - 1);
    const float* row = g_scores + (size_t)r * Sb;
    __half* prow = g_p + (size_t)r * Sb;
    int n = q + 1;
    int nfill = ((q >> 7) + 1) << 7;
    __shared__ float buf[Sb];
    __shared__ float red[256];
    int tid = threadIdx.x;

    float mx = -3.4e38f;
    for (int i = tid; i < n; i += 256) {
        float v = row[i];
        buf[i] = v;
        mx = fmaxf(mx, v);
    }
    red[tid] = mx; __syncthreads();
    for (int o = 128; o > 0; o >>= 1) { if (tid < o) red[tid] = fmaxf(red[tid], red[tid + o]); __syncthreads(); }
    mx = red[0];
    __syncthreads();

    float s = 0.f;
    for (int i = tid; i < n; i += 256) {
        float e = __expf(buf[i] - mx);
        buf[i] = e;
        s += e;
    }
    red[tid] = s; __syncthreads();
    for (int o = 128; o > 0; o >>= 1) { if (tid < o) red[tid] += red[tid + o]; __syncthreads(); }
    float inv = 1.f / red[0];

    for (int i = tid; i < n; i += 256) prow[i] = __float2half_rn(buf[i] * inv);
    for (int i = n + tid; i < nfill; i += 256) prow[i] = __float2half_rn(0.f);
}

// ---------------- launch ----------------
extern "C" void kernel_launch(void* const* d_in, const int* in_sizes, int n_in,
                              void* d_out, int out_size)
{
    const float* hidden  = (const float*)d_in[0];
    const float* cosb    = (const float*)d_in[1];
    const float* sinb    = (const float*)d_in[2];
    const float* w_qa    = (const float*)d_in[3];
    const float* qalnw   = (const float*)d_in[4];
    const float* w_qb    = (const float*)d_in[5];
    const float* w_kva   = (const float*)d_in[6];
    const float* kvalnw  = (const float*)d_in[7];
    const float* W_UK_T  = (const float*)d_in[8];
    const float* W_UV    = (const float*)d_in[9];
    const float* w_o     = (const float*)d_in[10];
    float* out = (float*)d_out;

    float *p_qa, *p_kva, *p_sc;
    __half *p_hid, *p_wqa, *p_wqb, *p_wkva, *p_wo;
    __half *p_qaln, *p_q, *p_qattn, *p_kattn, *p_p, *p_vT, *p_of, *p_wukT, *p_wuvT;
    cudaGetSymbolAddress((void**)&p_qa,    g_qa);
    cudaGetSymbolAddress((void**)&p_kva,   g_kva);
    cudaGetSymbolAddress((void**)&p_sc,    g_scores);
    cudaGetSymbolAddress((void**)&p_hid,   g_hid);
    cudaGetSymbolAddress((void**)&p_wqa,   g_wqa);
    cudaGetSymbolAddress((void**)&p_wqb,   g_wqb);
    cudaGetSymbolAddress((void**)&p_wkva,  g_wkva);
    cudaGetSymbolAddress((void**)&p_wo,    g_wo);
    cudaGetSymbolAddress((void**)&p_qaln,  g_qaln);
    cudaGetSymbolAddress((void**)&p_q,     g_q);
    cudaGetSymbolAddress((void**)&p_qattn, g_qattn);
    cudaGetSymbolAddress((void**)&p_kattn, g_kattn);
    cudaGetSymbolAddress((void**)&p_p,     g_p);
    cudaGetSymbolAddress((void**)&p_vT,    g_vT);
    cudaGetSymbolAddress((void**)&p_of,    g_outfl);
    cudaGetSymbolAddress((void**)&p_wukT,  g_wukT);
    cudaGetSymbolAddress((void**)&p_wuvT,  g_wuvT);

    const int SMEM = 4 * TILE_W * 4;   // 73728 bytes
    cudaFuncSetAttribute(mma_gemm, cudaFuncAttributeMaxDynamicSharedMemorySize, SMEM);

    auto grid = [](int M, int N, int z) {
        return dim3((N + BN - 1) / BN, (M + BM - 1) / BM, z);
    };
    const int T = 256;

    // ---- convert all external inputs to fp16 (one kernel) ----
    cvt_all<<<1184, 256>>>(hidden, w_qa, w_qb, w_kva, w_o);

    // 1) qa(f32) = hid @ wqa^T   [2048,1536] K=2048
    mma_gemm<<<grid(MBS, QLR, 1), T, SMEM>>>(
        p_hid, Hd, 0,1,0,1,  p_wqa, Hd, 0,1,0,1,  p_qa, QLR, 0,1,0,1,  MBS, QLR, Hd, 0, 0, 0, 1.f);

    // 2) kva(f32) = hid @ wkva^T [2048,576] K=2048
    mma_gemm<<<grid(MBS, DATT, 1), T, SMEM>>>(
        p_hid, Hd, 0,1,0,1,  p_wkva, Hd, 0,1,0,1,  p_kva, DATT, 0,1,0,1,  MBS, DATT, Hd, 0, 0, 0, 1.f);

    // 3) LN(qa) -> qaln(h)
    ln_rows<<<MBS, 256>>>(p_qa, QLR, qalnw, p_qaln, QLR, QLR);

    // 4) LN(kv_c) -> kattn(h)[:, :512]
    ln_rows<<<MBS, 256>>>(p_kva, DATT, kvalnw, p_kattn, DATT, KVLR);

    // 5) rope(k_pe) -> kattn(h)[:, 512:576]
    rope_k<<<MBS, 64>>>(cosb, sinb);

    // T1) W_UK_T(f32) -> wukT(h) [h][512][128]
    transpose_f32h<<<dim3(16, 4, NH), dim3(32, 8)>>>(
        W_UK_T, (long long)NOPE * KVLR, KVLR, p_wukT, (long long)KVLR * NOPE, NOPE);

    // T2) W_UV(f32) -> wuvT(h) [h][128][512]
    transpose_f32h<<<dim3(4, 16, NH), dim3(32, 8)>>>(
        W_UV, (long long)KVLR * VD, VD, p_wuvT, (long long)VD * KVLR, KVLR);

    // V) vT[b,h] = wuvT[h] @ kv_c[b]^T   M=128, N=1024, K=512
    mma_gemm<<<grid(VD, Sb, Bb * NH), T, SMEM>>>(
        p_wuvT, KVLR, 0,1, (long long)VD * KVLR, NH,
        p_kattn, DATT, (long long)Sb * DATT, NH, 0, 1,
        p_vT, Sb, (long long)VD * Sb, 1, 0, 1,
        VD, Sb, KVLR, 0, 0, 1, 1.f);

    // 6) q(h) = qaln @ wqb^T   [2048,3072] K=1536
    mma_gemm<<<grid(MBS, NH * QKD, 1), T, SMEM>>>(
        p_qaln, QLR, 0,1,0,1,  p_wqb, QLR, 0,1,0,1,  p_q, NH * QKD, 0,1,0,1,
        MBS, NH * QKD, QLR, 0, 0, 1, 1.f);

    // 7) rope(q_pe) -> qattn(h)[:,:,512:576] (scale folded)
    rope_q<<<MBS * NH, 64>>>(cosb, sinb);

    // 8) qattn(h)[:,:,h,0:512] = (q_nope @ wukT[h]^T) * SCALE
    mma_gemm<<<grid(MBS, KVLR, NH), T, SMEM>>>(
        p_q, NH * QKD, 0,1, QKD, NH,
        p_wukT, NOPE, 0,1, (long long)KVLR * NOPE, NH,
        p_qattn, NH * DATT, 0,1, DATT, NH,
        MBS, KVLR, NOPE, 0, 0, 1, SCALE);

    // 9) scores(f32) [1024,1024] K=576, causal skip
    mma_gemm<<<grid(Sb, Sb, Bb * NH), T, SMEM>>>(
        p_qattn, NH * DATT, (long long)Sb * NH * DATT, NH, DATT, NH,
        p_kattn, DATT, (long long)Sb * DATT, NH, 0, 1,
        p_sc, Sb, (long long)Sb * Sb, 1, 0, 1,
        Sb, Sb, DATT, 1, 0, 0, 1.f);

    // 10) causal softmax -> p(h)
    softmax_causal<<<Bb * NH * Sb, 256>>>();

    // 11) outfl(h)[:, h*128:+128] = p @ vT[b,h]^T   M=1024, N=128, K=1024 trunc
    mma_gemm<<<grid(Sb, VD, Bb * NH), T, SMEM>>>(
        p_p, Sb, (long long)Sb * Sb, 1, 0, 1,
        p_vT, Sb, (long long)VD * Sb, 1, 0, 1,
        p_of, NH * VD, (long long)Sb * NH * VD, NH, VD, NH,
        Sb, VD, Sb, 0, 1, 1, 1.f);

    // 13) out(f32) = outfl @ wo^T  [2048,2048] K=2048
    mma_gemm<<<grid(MBS, Hd, 1), T, SMEM>>>(
        p_of, NH * VD, 0,1,0,1,  p_wo, NH * VD, 0,1,0,1,  out, Hd, 0,1,0,1,
        MBS, Hd, NH * VD, 0, 0, 0, 1.f);
}

// round 11
// speedup vs baseline: 3.0675x; 1.1008x over previous
#include <cuda_runtime.h>
#include <cuda_fp16.h>
#include <math.h>
#include <stdint.h>

// ---------------- problem constants ----------------
#define Bb 2
#define Sb 1024
#define Hd 2048
#define NH 16
#define NOPE 128
#define ROPE 64
#define VD 128
#define QKD 192
#define QLR 1536
#define KVLR 512
#define DATT 576
#define MBS (Bb*Sb)
#define SCALE 0.07216878364870323f   // 1/sqrt(192)

// ---------------- scratch ----------------
__device__ float  g_qa    [MBS * QLR];
__device__ float  g_kva   [MBS * DATT];
__device__ float  g_scores[(size_t)Bb*NH*Sb*Sb];
__device__ __half g_hid   [MBS * Hd];
__device__ __half g_wqa   [QLR * Hd];
__device__ __half g_wqb   [NH * QKD * QLR];
__device__ __half g_wkva  [DATT * Hd];
__device__ __half g_wo    [Hd * NH * VD];
__device__ __half g_wuk   [NH * NOPE * KVLR];      // W_UK_T f16, native [h][128][512]
__device__ __half g_qaln  [MBS * QLR];
__device__ __half g_q     [MBS * NH * QKD];        // rope applied in place
__device__ __half g_kattn [MBS * DATT];            // LN(kv_c) ‖ rope(k_pe) (unscaled)
__device__ __half g_kb    [(size_t)Bb*NH*Sb*QKD];  // per (b,h): [1024][192] absorbed keys (scaled)
__device__ __half g_p     [(size_t)Bb*NH*Sb*Sb];
__device__ __half g_vT    [(size_t)Bb*NH*VD*Sb];   // V'^T per (b,h): [128][1024]
__device__ __half g_outfl [MBS * NH * VD];
__device__ __half g_wuvT  [NH * VD * KVLR];

// ---------------- helpers ----------------
__device__ __forceinline__ uint32_t su32(const void* p) {
    uint32_t a;
    asm("{ .reg .u64 t; cvta.to.shared.u64 t, %1; cvt.u32.u64 %0, t; }" : "=r"(a) : "l"(p));
    return a;
}
__device__ __forceinline__ void mma_f16(float c[4], const uint32_t a[4], const uint32_t b[2]) {
    asm volatile(
        "mma.sync.aligned.m16n8k16.row.col.f32.f16.f16.f32 "
        "{%0,%1,%2,%3},{%4,%5,%6,%7},{%8,%9},{%0,%1,%2,%3};"
        : "+f"(c[0]), "+f"(c[1]), "+f"(c[2]), "+f"(c[3])
        : "r"(a[0]), "r"(a[1]), "r"(a[2]), "r"(a[3]), "r"(b[0]), "r"(b[1]));
}
#define LDSM_X4(r0, r1, r2, r3, addr) \
    asm volatile("ldmatrix.sync.aligned.m8n8.x4.shared.b16 {%0,%1,%2,%3}, [%4];" \
                 : "=r"(r0), "=r"(r1), "=r"(r2), "=r"(r3) : "r"(addr))
#define CP_ASYNC16(dst, src, sz) \
    asm volatile("cp.async.cg.shared.global [%0], [%1], 16, %2;" \
                 :: "r"(dst), "l"(src), "r"(sz) : "memory")
#define CP_COMMIT() asm volatile("cp.async.commit_group;" ::: "memory")
#define CP_WAIT(n)  asm volatile("cp.async.wait_group %0;" :: "n"(n) : "memory")

// ---------------- fp16 mma GEMM: 128x128 block, 8 warps (64x32 warp tile) ----
#define BM 128
#define BN 128
#define BKK 64
#define WSH 36
#define TILE_W (BM * WSH)

__global__ void __launch_bounds__(256, 2)
mma_gemm(const __half* __restrict__ A, int lda, long long sAd, int dA, long long sAm, int mA,
         const __half* __restrict__ B, int ldb, long long sBd, int dB, long long sBm, int mB,
         void*         __restrict__ Cv, int ldc, long long sCd, int dC, long long sCm, int mC,
         int M, int N, int K, int causal, int trunck, int outHalf, float cscale)
{
    const int mBase = blockIdx.y * BM;
    const int nBase = blockIdx.x * BN;
    if (causal && nBase > mBase + BM - 1) return;

    extern __shared__ uint32_t smw[];
    const uint32_t sAbase = su32(smw);
    const uint32_t sBbase = sAbase + 2u * TILE_W * 4u;

    const int z = blockIdx.z;
    const __half* Ab = A + (size_t)(z / dA) * sAd + (size_t)(z % mA) * sAm;
    const __half* Bp = B + (size_t)(z / dB) * sBd + (size_t)(z % mB) * sBm;
    const size_t  cOff = (size_t)(z / dC) * sCd + (size_t)(z % mC) * sCm;

    const int tid  = threadIdx.x;
    const int lane = tid & 31;
    const int warp = tid >> 5;
    const int wm   = warp & 1;
    const int wn   = warp >> 1;
    const int g    = lane >> 2;
    const int tig  = lane & 3;

    uint32_t aAddr[4];
#pragma unroll
    for (int ii = 0; ii < 4; ii++)
        aAddr[ii] = sAbase +
            (uint32_t)(((wm * 64 + ii * 16 + (lane & 15)) * WSH + ((lane >> 4) << 2)) * 4);
    uint32_t bAddr[2];
#pragma unroll
    for (int q = 0; q < 2; q++)
        bAddr[q] = sBbase +
            (uint32_t)(((wn * 32 + q * 16 + (lane & 7) + ((lane >> 4) << 3)) * WSH
                        + (((lane >> 3) & 1) << 2)) * 4);

    float acc[4][4][4];
#pragma unroll
    for (int i = 0; i < 4; i++)
#pragma unroll
        for (int j = 0; j < 4; j++)
#pragma unroll
            for (int r = 0; r < 4; r++) acc[i][j][r] = 0.f;

    int Ke = K;
    if (trunck) { int lim = mBase + BM; if (lim < Ke) Ke = lim; }
    const int nc = Ke / BKK;

    auto copy_chunk = [&](int ci, int p) {
        const int k0 = ci * BKK;
        const uint32_t aD = sAbase + (uint32_t)p * TILE_W * 4u;
        const uint32_t bD = sBbase + (uint32_t)p * TILE_W * 4u;
#pragma unroll
        for (int q = 0; q < 4; q++) {
            int slot = tid + q * 256;
            int row  = slot >> 3;
            int c8   = (slot & 7) << 3;
            uint32_t soff = (uint32_t)(row * (WSH * 4) + c8 * 2);
            int gm = mBase + row;
            const __half* asrc = (gm < M) ? (Ab + (size_t)gm * lda + k0 + c8) : Ab;
            CP_ASYNC16(aD + soff, asrc, (gm < M) ? 16 : 0);
            int gn = nBase + row;
            const __half* bsrc = (gn < N) ? (Bp + (size_t)gn * ldb + k0 + c8) : Bp;
            CP_ASYNC16(bD + soff, bsrc, (gn < N) ? 16 : 0);
        }
        CP_COMMIT();
    };

    copy_chunk(0, 0);

    for (int i = 0; i < nc; i++) {
        const int p = i & 1;
        if (i + 1 < nc) { copy_chunk(i + 1, p ^ 1); CP_WAIT(1); }
        else            { CP_WAIT(0); }
        __syncthreads();

        const uint32_t pOff = (uint32_t)p * TILE_W * 4u;
#pragma unroll
        for (int ks = 0; ks < 4; ks++) {
            const uint32_t kOff = pOff + (uint32_t)ks * 32u;
            uint32_t a[4][4], b[4][2];
#pragma unroll
            for (int ii = 0; ii < 4; ii++)
                LDSM_X4(a[ii][0], a[ii][1], a[ii][2], a[ii][3], aAddr[ii] + kOff);
            LDSM_X4(b[0][0], b[0][1], b[1][0], b[1][1], bAddr[0] + kOff);
            LDSM_X4(b[2][0], b[2][1], b[3][0], b[3][1], bAddr[1] + kOff);
#pragma unroll
            for (int ii = 0; ii < 4; ii++)
#pragma unroll
                for (int jj = 0; jj < 4; jj++)
                    mma_f16(acc[ii][jj], a[ii], b[jj]);
        }
        __syncthreads();
    }

    // ---- epilogue ----
    if (outHalf) {
        __half* Ch = (__half*)Cv + cOff;
#pragma unroll
        for (int i = 0; i < 4; i++) {
            int r0 = mBase + (wm << 6) + (i << 4) + g;
            if (r0 >= M) continue;
#pragma unroll
            for (int j = 0; j < 4; j++) {
                int col = nBase + (wn << 5) + (j << 3) + (tig << 1);
                if (col < N) {
                    *(__half2*)(Ch + (size_t)r0 * ldc + col) =
                        __floats2half2_rn(acc[i][j][0] * cscale, acc[i][j][1] * cscale);
                    *(__half2*)(Ch + (size_t)(r0 + 8) * ldc + col) =
                        __floats2half2_rn(acc[i][j][2] * cscale, acc[i][j][3] * cscale);
                }
            }
        }
    } else {
        float* Cf = (float*)Cv + cOff;
#pragma unroll
        for (int i = 0; i < 4; i++) {
            int r0 = mBase + (wm << 6) + (i << 4) + g;
            if (r0 >= M) continue;
#pragma unroll
            for (int j = 0; j < 4; j++) {
                int col = nBase + (wn << 5) + (j << 3) + (tig << 1);
                if (col < N) {
                    *(float2*)(Cf + (size_t)r0 * ldc + col)       = make_float2(acc[i][j][0], acc[i][j][1]);
                    *(float2*)(Cf + (size_t)(r0 + 8) * ldc + col) = make_float2(acc[i][j][2], acc[i][j][3]);
                }
            }
        }
    }
}

// ---------------- fused f32 -> f16 conversion for 6 tensors ----------------
#define CV0 (MBS * Hd / 4)
#define CV1 (CV0 + QLR * Hd / 4)
#define CV2 (CV1 + NH * QKD * QLR / 4)
#define CV3 (CV2 + DATT * Hd / 4)
#define CV4 (CV3 + Hd * NH * VD / 4)
#define CV5 (CV4 + NH * NOPE * KVLR / 4)

__global__ void cvt_all(const float* __restrict__ s0, const float* __restrict__ s1,
                        const float* __restrict__ s2, const float* __restrict__ s3,
                        const float* __restrict__ s4, const float* __restrict__ s5)
{
    __half *d;
    const float *s;
    int stride = gridDim.x * blockDim.x;
    for (int i = blockIdx.x * blockDim.x + threadIdx.x; i < CV5; i += stride) {
        int off;
        if (i < CV0)      { s = s0; off = i;       d = g_hid; }
        else if (i < CV1) { s = s1; off = i - CV0; d = g_wqa; }
        else if (i < CV2) { s = s2; off = i - CV1; d = g_wqb; }
        else if (i < CV3) { s = s3; off = i - CV2; d = g_wkva; }
        else if (i < CV4) { s = s4; off = i - CV3; d = g_wo; }
        else              { s = s5; off = i - CV4; d = g_wuk; }
        float4 v = ((const float4*)s)[off];
        ((__half2*)d)[2 * off]     = __floats2half2_rn(v.x, v.y);
        ((__half2*)d)[2 * off + 1] = __floats2half2_rn(v.z, v.w);
    }
}

// ---------------- transpose f32 -> f16 ----------------
__global__ void transpose_f32h(const float* __restrict__ in, long long sIn, int ldin,
                               __half* __restrict__ out, long long sOut, int ldout)
{
    __shared__ float t[32][33];
    const float* ib = in + (size_t)blockIdx.z * sIn;
    __half* ob = out + (size_t)blockIdx.z * sOut;
    int x0 = blockIdx.x * 32, y0 = blockIdx.y * 32;
    int tx = threadIdx.x, ty = threadIdx.y;
#pragma unroll
    for (int j = 0; j < 32; j += 8)
        t[ty + j][tx] = ib[(size_t)(y0 + ty + j) * ldin + x0 + tx];
    __syncthreads();
#pragma unroll
    for (int j = 0; j < 32; j += 8)
        ob[(size_t)(x0 + ty + j) * ldout + y0 + tx] = __float2half_rn(t[tx][ty + j]);
}

// ---------------- LayerNorm: f32 in -> f16 out ----------------
__global__ void ln_rows(const float* __restrict__ in, int ldin,
                        const float* __restrict__ w,
                        __half* __restrict__ out, int ldout, int dim)
{
    int r = blockIdx.x;
    const float* x = in + (size_t)r * ldin;
    __half* y = out + (size_t)r * ldout;
    __shared__ float red[256];
    int tid = threadIdx.x;

    float s = 0.f;
    for (int i = tid; i < dim; i += 256) s += x[i];
    red[tid] = s; __syncthreads();
    for (int o = 128; o > 0; o >>= 1) { if (tid < o) red[tid] += red[tid + o]; __syncthreads(); }
    float mean = red[0] / dim;
    __syncthreads();

    float v = 0.f;
    for (int i = tid; i < dim; i += 256) { float d = x[i] - mean; v += d * d; }
    red[tid] = v; __syncthreads();
    for (int o = 128; o > 0; o >>= 1) { if (tid < o) red[tid] += red[tid + o]; __syncthreads(); }
    float rstd = rsqrtf(red[0] / dim + 1e-5f);

    for (int i = tid; i < dim; i += 256)
        y[i] = __float2half_rn((x[i] - mean) * rstd * w[i]);
}

// ---------------- RoPE k_pe: writes SCALE*rope(k_pe) into all 16 head slots of Kb
__global__ void rope_k(const float* __restrict__ cosb, const float* __restrict__ sinb)
{
    int r = blockIdx.x;          // b*Sb + s
    int i = threadIdx.x;         // 0..63
    int b = r >> 10;
    int s = r & (Sb - 1);
    const float* src = g_kva + (size_t)r * DATT + KVLR;
    float x = src[i];
    float other = src[(i < 32) ? (i + 32) : (i - 32)];
    float rot = (i < 32) ? -other : other;
    __half v = __float2half_rn((x * cosb[r * ROPE + i] + rot * sinb[r * ROPE + i]) * SCALE);
#pragma unroll
    for (int h = 0; h < NH; h++)
        g_kb[(((size_t)(b * NH + h) * Sb) + s) * QKD + NOPE + i] = v;
}

// ---------------- RoPE q_pe: in-place on g_q ----------------
__global__ void rope_q(const float* __restrict__ cosb, const float* __restrict__ sinb)
{
    int bs = blockIdx.x >> 4;
    int h  = blockIdx.x & 15;
    int i  = threadIdx.x;        // 0..63
    __half* base = g_q + (size_t)bs * (NH * QKD) + h * QKD + NOPE;
    float x = __half2float(base[i]);
    float other = __half2float(base[(i < 32) ? (i + 32) : (i - 32)]);
    __syncthreads();
    float rot = (i < 32) ? -other : other;
    base[i] = __float2half_rn(x * cosb[bs * ROPE + i] + rot * sinb[bs * ROPE + i]);
}

// ---------------- one-pass causal softmax (row cached in smem) --------------
__global__ void softmax_causal()
{
    int r = blockIdx.x;
    int q = r & (Sb - 1);
    const float* row = g_scores + (size_t)r * Sb;
    __half* prow = g_p + (size_t)r * Sb;
    int n = q + 1;
    int nfill = ((q >> 7) + 1) << 7;
    __shared__ float buf[Sb];
    __shared__ float red[256];
    int tid = threadIdx.x;

    float mx = -3.4e38f;
    for (int i = tid; i < n; i += 256) {
        float v = row[i];
        buf[i] = v;
        mx = fmaxf(mx, v);
    }
    red[tid] = mx; __syncthreads();
    for (int o = 128; o > 0; o >>= 1) { if (tid < o) red[tid] = fmaxf(red[tid], red[tid + o]); __syncthreads(); }
    mx = red[0];
    __syncthreads();

    float s = 0.f;
    for (int i = tid; i < n; i += 256) {
        float e = __expf(buf[i] - mx);
        buf[i] = e;
        s += e;
    }
    red[tid] = s; __syncthreads();
    for (int o = 128; o > 0; o >>= 1) { if (tid < o) red[tid] += red[tid + o]; __syncthreads(); }
    float inv = 1.f / red[0];

    for (int i = tid; i < n; i += 256) prow[i] = __float2half_rn(buf[i] * inv);
    for (int i = n + tid; i < nfill; i += 256) prow[i] = __float2half_rn(0.f);
}

// ---------------- launch ----------------
extern "C" void kernel_launch(void* const* d_in, const int* in_sizes, int n_in,
                              void* d_out, int out_size)
{
    const float* hidden  = (const float*)d_in[0];
    const float* cosb    = (const float*)d_in[1];
    const float* sinb    = (const float*)d_in[2];
    const float* w_qa    = (const float*)d_in[3];
    const float* qalnw   = (const float*)d_in[4];
    const float* w_qb    = (const float*)d_in[5];
    const float* w_kva   = (const float*)d_in[6];
    const float* kvalnw  = (const float*)d_in[7];
    const float* W_UK_T  = (const float*)d_in[8];
    const float* W_UV    = (const float*)d_in[9];
    const float* w_o     = (const float*)d_in[10];
    float* out = (float*)d_out;

    float *p_qa, *p_kva, *p_sc;
    __half *p_hid, *p_wqa, *p_wqb, *p_wkva, *p_wo, *p_wuk;
    __half *p_qaln, *p_q, *p_kattn, *p_kb, *p_p, *p_vT, *p_of, *p_wuvT;
    cudaGetSymbolAddress((void**)&p_qa,    g_qa);
    cudaGetSymbolAddress((void**)&p_kva,   g_kva);
    cudaGetSymbolAddress((void**)&p_sc,    g_scores);
    cudaGetSymbolAddress((void**)&p_hid,   g_hid);
    cudaGetSymbolAddress((void**)&p_wqa,   g_wqa);
    cudaGetSymbolAddress((void**)&p_wqb,   g_wqb);
    cudaGetSymbolAddress((void**)&p_wkva,  g_wkva);
    cudaGetSymbolAddress((void**)&p_wo,    g_wo);
    cudaGetSymbolAddress((void**)&p_wuk,   g_wuk);
    cudaGetSymbolAddress((void**)&p_qaln,  g_qaln);
    cudaGetSymbolAddress((void**)&p_q,     g_q);
    cudaGetSymbolAddress((void**)&p_kattn, g_kattn);
    cudaGetSymbolAddress((void**)&p_kb,    g_kb);
    cudaGetSymbolAddress((void**)&p_p,     g_p);
    cudaGetSymbolAddress((void**)&p_vT,    g_vT);
    cudaGetSymbolAddress((void**)&p_of,    g_outfl);
    cudaGetSymbolAddress((void**)&p_wuvT,  g_wuvT);

    const int SMEM = 4 * TILE_W * 4;   // 73728 bytes
    cudaFuncSetAttribute(mma_gemm, cudaFuncAttributeMaxDynamicSharedMemorySize, SMEM);

    auto grid = [](int M, int N, int z) {
        return dim3((N + BN - 1) / BN, (M + BM - 1) / BM, z);
    };
    const int T = 256;

    // ---- convert all external inputs to fp16 (one kernel) ----
    cvt_all<<<1184, 256>>>(hidden, w_qa, w_qb, w_kva, w_o, W_UK_T);

    // 1) qa(f32) = hid @ wqa^T   [2048,1536] K=2048
    mma_gemm<<<grid(MBS, QLR, 1), T, SMEM>>>(
        p_hid, Hd, 0,1,0,1,  p_wqa, Hd, 0,1,0,1,  p_qa, QLR, 0,1,0,1,  MBS, QLR, Hd, 0, 0, 0, 1.f);

    // 2) kva(f32) = hid @ wkva^T [2048,576] K=2048
    mma_gemm<<<grid(MBS, DATT, 1), T, SMEM>>>(
        p_hid, Hd, 0,1,0,1,  p_wkva, Hd, 0,1,0,1,  p_kva, DATT, 0,1,0,1,  MBS, DATT, Hd, 0, 0, 0, 1.f);

    // 3) LN(qa) -> qaln(h)
    ln_rows<<<MBS, 256>>>(p_qa, QLR, qalnw, p_qaln, QLR, QLR);

    // 4) LN(kv_c) -> kattn(h)[:, :512]
    ln_rows<<<MBS, 256>>>(p_kva, DATT, kvalnw, p_kattn, DATT, KVLR);

    // 5) rope(k_pe)*SCALE -> Kb[b,h][:,128:192] (all heads)
    rope_k<<<MBS, 64>>>(cosb, sinb);

    // T2) W_UV(f32) -> wuvT(h) [h][128][512]
    transpose_f32h<<<dim3(4, 16, NH), dim3(32, 8)>>>(
        W_UV, (long long)KVLR * VD, VD, p_wuvT, (long long)VD * KVLR, KVLR);

    // V') vT[b,h] = wuvT[h] @ kv_c[b]^T   M=128, N=1024, K=512
    mma_gemm<<<grid(VD, Sb, Bb * NH), T, SMEM>>>(
        p_wuvT, KVLR, 0,1, (long long)VD * KVLR, NH,
        p_kattn, DATT, (long long)Sb * DATT, NH, 0, 1,
        p_vT, Sb, (long long)VD * Sb, 1, 0, 1,
        VD, Sb, KVLR, 0, 0, 1, 1.f);

    // K') Kb[b,h][:,0:128] = (kv_c[b] @ wuk[h]^T) * SCALE   M=1024, N=128, K=512
    mma_gemm<<<grid(Sb, NOPE, Bb * NH), T, SMEM>>>(
        p_kattn, DATT, (long long)Sb * DATT, NH, 0, 1,
        p_wuk, KVLR, 0,1, (long long)NOPE * KVLR, NH,
        p_kb, QKD, (long long)Sb * QKD, 1, 0, 1,
        Sb, NOPE, KVLR, 0, 0, 1, SCALE);

    // 6) q(h) = qaln @ wqb^T   [2048,3072] K=1536
    mma_gemm<<<grid(MBS, NH * QKD, 1), T, SMEM>>>(
        p_qaln, QLR, 0,1,0,1,  p_wqb, QLR, 0,1,0,1,  p_q, NH * QKD, 0,1,0,1,
        MBS, NH * QKD, QLR, 0, 0, 1, 1.f);

    // 7) rope(q_pe) in place on g_q
    rope_q<<<MBS * NH, 64>>>(cosb, sinb);

    // 9) scores(f32) = q[b,:,h,:] @ Kb[b,h]^T  [1024,1024] K=192, causal
    mma_gemm<<<grid(Sb, Sb, Bb * NH), T, SMEM>>>(
        p_q, NH * QKD, (long long)Sb * NH * QKD, NH, QKD, NH,
        p_kb, QKD, (long long)Sb * QKD, 1, 0, 1,
        p_sc, Sb, (long long)Sb * Sb, 1, 0, 1,
        Sb, Sb, QKD, 1, 0, 0, 1.f);

    // 10) causal softmax -> p(h)
    softmax_causal<<<Bb * NH * Sb, 256>>>();

    // 11) outfl(h)[:, h*128:+128] = p @ vT[b,h]^T   M=1024, N=128, K trunc
    mma_gemm<<<grid(Sb, VD, Bb * NH), T, SMEM>>>(
        p_p, Sb, (long long)Sb * Sb, 1, 0, 1,
        p_vT, Sb, (long long)VD * Sb, 1, 0, 1,
        p_of, NH * VD, (long long)Sb * NH * VD, NH, VD, NH,
        Sb, VD, Sb, 0, 1, 1, 1.f);

    // 13) out(f32) = outfl @ wo^T  [2048,2048] K=2048
    mma_gemm<<<grid(MBS, Hd, 1), T, SMEM>>>(
        p_of, NH * VD, 0,1,0,1,  p_wo, NH * VD, 0,1,0,1,  out, Hd, 0,1,0,1,
        MBS, Hd, NH * VD, 0, 0, 0, 1.f);
}

// round 13
// speedup vs baseline: 3.8257x; 1.2472x over previous
#include <cuda_runtime.h>
#include <cuda_fp16.h>
#include <math.h>
#include <stdint.h>

// ---------------- problem constants ----------------
#define Bb 2
#define Sb 1024
#define Hd 2048
#define NH 16
#define NOPE 128
#define ROPE 64
#define VD 128
#define QKD 192
#define QLR 1536
#define KVLR 512
#define DATT 576
#define MBS (Bb*Sb)
#define SCALE 0.07216878364870323f   // 1/sqrt(192)

// ---------------- scratch ----------------
__device__ float  g_qa    [MBS * QLR];
__device__ float  g_kva   [MBS * DATT];
__device__ __half g_hid   [MBS * Hd];
__device__ __half g_wqa   [QLR * Hd];
__device__ __half g_wqb   [NH * QKD * QLR];
__device__ __half g_wkva  [DATT * Hd];
__device__ __half g_wo    [Hd * NH * VD];
__device__ __half g_wuk   [NH * NOPE * KVLR];      // W_UK_T f16 [h][128][512]
__device__ __half g_qaln  [MBS * QLR];
__device__ __half g_q     [MBS * NH * QKD];        // rope applied in place
__device__ __half g_kattn [MBS * DATT];            // LN(kv_c) (cols 0:512)
__device__ __half g_kb    [(size_t)Bb*NH*Sb*QKD];  // absorbed keys, scaled
__device__ __half g_vT    [(size_t)Bb*NH*VD*Sb];   // V'^T per (b,h): [128][1024]
__device__ __half g_outfl [MBS * NH * VD];
__device__ __half g_wuvT  [NH * VD * KVLR];

// ---------------- helpers ----------------
__device__ __forceinline__ uint32_t su32(const void* p) {
    uint32_t a;
    asm("{ .reg .u64 t; cvta.to.shared.u64 t, %1; cvt.u32.u64 %0, t; }" : "=r"(a) : "l"(p));
    return a;
}
__device__ __forceinline__ uint32_t h2u(__half2 h) {
    union { __half2 h; uint32_t u; } c;
    c.h = h;
    return c.u;
}
__device__ __forceinline__ void mma_f16(float c[4], const uint32_t a[4], const uint32_t b[2]) {
    asm volatile(
        "mma.sync.aligned.m16n8k16.row.col.f32.f16.f16.f32 "
        "{%0,%1,%2,%3},{%4,%5,%6,%7},{%8,%9},{%0,%1,%2,%3};"
        : "+f"(c[0]), "+f"(c[1]), "+f"(c[2]), "+f"(c[3])
        : "r"(a[0]), "r"(a[1]), "r"(a[2]), "r"(a[3]), "r"(b[0]), "r"(b[1]));
}
#define LDSM_X4(r0, r1, r2, r3, addr) \
    asm volatile("ldmatrix.sync.aligned.m8n8.x4.shared.b16 {%0,%1,%2,%3}, [%4];" \
                 : "=r"(r0), "=r"(r1), "=r"(r2), "=r"(r3) : "r"(addr))
#define CP_ASYNC16(dst, src, sz) \
    asm volatile("cp.async.cg.shared.global [%0], [%1], 16, %2;" \
                 :: "r"(dst), "l"(src), "r"(sz) : "memory")
#define CP_COMMIT() asm volatile("cp.async.commit_group;" ::: "memory")
#define CP_WAIT(n)  asm volatile("cp.async.wait_group %0;" :: "n"(n) : "memory")

// ---------------- fp16 mma GEMM: 128x128 block, 8 warps (64x32 warp tile) ----
#define BM 128
#define BN 128
#define BKK 64
#define WSH 36
#define TILE_W (BM * WSH)

__global__ void __launch_bounds__(256, 2)
mma_gemm(const __half* __restrict__ A, int lda, long long sAd, int dA, long long sAm, int mA,
         const __half* __restrict__ B, int ldb, long long sBd, int dB, long long sBm, int mB,
         void*         __restrict__ Cv, int ldc, long long sCd, int dC, long long sCm, int mC,
         int M, int N, int K, int outHalf, float cscale)
{
    const int mBase = blockIdx.y * BM;
    const int nBase = blockIdx.x * BN;

    extern __shared__ uint32_t smw[];
    const uint32_t sAbase = su32(smw);
    const uint32_t sBbase = sAbase + 2u * TILE_W * 4u;

    const int z = blockIdx.z;
    const __half* Ab = A + (size_t)(z / dA) * sAd + (size_t)(z % mA) * sAm;
    const __half* Bp = B + (size_t)(z / dB) * sBd + (size_t)(z % mB) * sBm;
    const size_t  cOff = (size_t)(z / dC) * sCd + (size_t)(z % mC) * sCm;

    const int tid  = threadIdx.x;
    const int lane = tid & 31;
    const int warp = tid >> 5;
    const int wm   = warp & 1;
    const int wn   = warp >> 1;
    const int g    = lane >> 2;
    const int tig  = lane & 3;

    uint32_t aAddr[4];
#pragma unroll
    for (int ii = 0; ii < 4; ii++)
        aAddr[ii] = sAbase +
            (uint32_t)(((wm * 64 + ii * 16 + (lane & 15)) * WSH + ((lane >> 4) << 2)) * 4);
    uint32_t bAddr[2];
#pragma unroll
    for (int q = 0; q < 2; q++)
        bAddr[q] = sBbase +
            (uint32_t)(((wn * 32 + q * 16 + (lane & 7) + ((lane >> 4) << 3)) * WSH
                        + (((lane >> 3) & 1) << 2)) * 4);

    float acc[4][4][4];
#pragma unroll
    for (int i = 0; i < 4; i++)
#pragma unroll
        for (int j = 0; j < 4; j++)
#pragma unroll
            for (int r = 0; r < 4; r++) acc[i][j][r] = 0.f;

    const int nc = K / BKK;

    auto copy_chunk = [&](int ci, int p) {
        const int k0 = ci * BKK;
        const uint32_t aD = sAbase + (uint32_t)p * TILE_W * 4u;
        const uint32_t bD = sBbase + (uint32_t)p * TILE_W * 4u;
#pragma unroll
        for (int q = 0; q < 4; q++) {
            int slot = tid + q * 256;
            int row  = slot >> 3;
            int c8   = (slot & 7) << 3;
            uint32_t soff = (uint32_t)(row * (WSH * 4) + c8 * 2);
            int gm = mBase + row;
            const __half* asrc = (gm < M) ? (Ab + (size_t)gm * lda + k0 + c8) : Ab;
            CP_ASYNC16(aD + soff, asrc, (gm < M) ? 16 : 0);
            int gn = nBase + row;
            const __half* bsrc = (gn < N) ? (Bp + (size_t)gn * ldb + k0 + c8) : Bp;
            CP_ASYNC16(bD + soff, bsrc, (gn < N) ? 16 : 0);
        }
        CP_COMMIT();
    };

    copy_chunk(0, 0);

    for (int i = 0; i < nc; i++) {
        const int p = i & 1;
        if (i + 1 < nc) { copy_chunk(i + 1, p ^ 1); CP_WAIT(1); }
        else            { CP_WAIT(0); }
        __syncthreads();

        const uint32_t pOff = (uint32_t)p * TILE_W * 4u;
#pragma unroll
        for (int ks = 0; ks < 4; ks++) {
            const uint32_t kOff = pOff + (uint32_t)ks * 32u;
            uint32_t a[4][4], b[4][2];
#pragma unroll
            for (int ii = 0; ii < 4; ii++)
                LDSM_X4(a[ii][0], a[ii][1], a[ii][2], a[ii][3], aAddr[ii] + kOff);
            LDSM_X4(b[0][0], b[0][1], b[1][0], b[1][1], bAddr[0] + kOff);
            LDSM_X4(b[2][0], b[2][1], b[3][0], b[3][1], bAddr[1] + kOff);
#pragma unroll
            for (int ii = 0; ii < 4; ii++)
#pragma unroll
                for (int jj = 0; jj < 4; jj++)
                    mma_f16(acc[ii][jj], a[ii], b[jj]);
        }
        __syncthreads();
    }

    if (outHalf) {
        __half* Ch = (__half*)Cv + cOff;
#pragma unroll
        for (int i = 0; i < 4; i++) {
            int r0 = mBase + (wm << 6) + (i << 4) + g;
            if (r0 >= M) continue;
#pragma unroll
            for (int j = 0; j < 4; j++) {
                int col = nBase + (wn << 5) + (j << 3) + (tig << 1);
                if (col < N) {
                    *(__half2*)(Ch + (size_t)r0 * ldc + col) =
                        __floats2half2_rn(acc[i][j][0] * cscale, acc[i][j][1] * cscale);
                    *(__half2*)(Ch + (size_t)(r0 + 8) * ldc + col) =
                        __floats2half2_rn(acc[i][j][2] * cscale, acc[i][j][3] * cscale);
                }
            }
        }
    } else {
        float* Cf = (float*)Cv + cOff;
#pragma unroll
        for (int i = 0; i < 4; i++) {
            int r0 = mBase + (wm << 6) + (i << 4) + g;
            if (r0 >= M) continue;
#pragma unroll
            for (int j = 0; j < 4; j++) {
                int col = nBase + (wn << 5) + (j << 3) + (tig << 1);
                if (col < N) {
                    *(float2*)(Cf + (size_t)r0 * ldc + col)       = make_float2(acc[i][j][0], acc[i][j][1]);
                    *(float2*)(Cf + (size_t)(r0 + 8) * ldc + col) = make_float2(acc[i][j][2], acc[i][j][3]);
                }
            }
        }
    }
}

// ---------------- flash attention: scores + softmax + p@V fused --------------
// grid: (8, 32). blockIdx.x -> q block i = 7 - bx (heavy first); blockIdx.y = b*NH+h.
// 256 threads, 8 warps; warp w owns q rows [128i + 16w, +16).
#define QS_STRIDE 100                      // words per 192-half row (96+4)
#define VS_STRIDE 68                       // words per 128-half row (64+4)
#define QS_B (128 * QS_STRIDE * 4)         // 51200
#define VS_B (128 * VS_STRIDE * 4)         // 34816
#define BUF_B (QS_B + VS_B)                // 86016 (K tile + V tile)
#define SMEM_FLASH (QS_B + 2 * BUF_B)      // 223232

__global__ void __launch_bounds__(256, 1)
flash_attn(const __half* __restrict__ Q, const __half* __restrict__ Kb,
           const __half* __restrict__ Vt, __half* __restrict__ Of)
{
    const int i = 7 - (int)blockIdx.x;
    const int z = blockIdx.y;
    const int b = z >> 4, h = z & 15;

    extern __shared__ uint32_t smw[];
    const uint32_t sQ  = su32(smw);
    const uint32_t sB0 = sQ + QS_B;

    const int tid = threadIdx.x, lane = tid & 31, w = tid >> 5;
    const int g = lane >> 2, tig = lane & 3;

    const __half* Qg = Q  + (size_t)(b * Sb + i * 128) * (NH * QKD) + h * QKD;
    const __half* Kg = Kb + (size_t)z * Sb * QKD;
    const __half* Vg = Vt + (size_t)z * VD * Sb;

    const uint32_t aQbase = sQ + (uint32_t)(((w * 16 + (lane & 15)) * QS_STRIDE
                                             + ((lane >> 4) << 2)) * 4);
    const uint32_t bKoff = (uint32_t)((((lane & 7) + ((lane >> 4) << 3)) * QS_STRIDE
                                       + (((lane >> 3) & 1) << 2)) * 4);
    const uint32_t bVoff = (uint32_t)((((lane & 7) + ((lane >> 4) << 3)) * VS_STRIDE
                                       + (((lane >> 3) & 1) << 2)) * 4);

    auto load_K = [&](int j, uint32_t dst) {
        const __half* src = Kg + (size_t)j * 128 * QKD;
        for (int t = tid; t < 128 * 24; t += 256) {
            int row = t / 24, cc = t % 24;
            CP_ASYNC16(dst + (uint32_t)(row * QS_STRIDE + cc * 4) * 4,
                       src + (size_t)row * QKD + cc * 8, 16);
        }
    };
    auto load_V = [&](int j, uint32_t dst) {
        for (int t = tid; t < 128 * 16; t += 256) {
            int row = t / 16, cc = t % 16;
            CP_ASYNC16(dst + (uint32_t)(row * VS_STRIDE + cc * 4) * 4,
                       Vg + (size_t)row * Sb + j * 128 + cc * 8, 16);
        }
    };

    // prologue: Q + (K0,V0) as group 0
    for (int t = tid; t < 128 * 24; t += 256) {
        int row = t / 24, cc = t % 24;
        CP_ASYNC16(sQ + (uint32_t)(row * QS_STRIDE + cc * 4) * 4,
                   Qg + (size_t)row * (NH * QKD) + cc * 8, 16);
    }
    load_K(0, sB0);
    load_V(0, sB0 + QS_B);
    CP_COMMIT();

    float m0 = -1e30f, m1 = -1e30f, l0 = 0.f, l1 = 0.f;
    float o[16][4];
#pragma unroll
    for (int nt = 0; nt < 16; nt++)
#pragma unroll
        for (int r = 0; r < 4; r++) o[nt][r] = 0.f;

    for (int j = 0; j <= i; j++) {
        const int p = j & 1;
        if (j < i) {
            const uint32_t nb = sB0 + (uint32_t)(p ^ 1) * BUF_B;
            load_K(j + 1, nb);
            load_V(j + 1, nb + QS_B);
            CP_COMMIT();
            CP_WAIT(1);
        } else {
            CP_WAIT(0);
        }
        __syncthreads();

        const uint32_t kbB = sB0 + (uint32_t)p * BUF_B;
        const uint32_t vbB = kbB + QS_B;

        // ---- S = q @ Kb_j^T ----
        float s[16][4];
#pragma unroll
        for (int nt = 0; nt < 16; nt++)
#pragma unroll
            for (int r = 0; r < 4; r++) s[nt][r] = 0.f;

#pragma unroll
        for (int ks = 0; ks < 12; ks++) {
            uint32_t a[4];
            LDSM_X4(a[0], a[1], a[2], a[3], aQbase + (uint32_t)ks * 32u);
#pragma unroll
            for (int t = 0; t < 8; t++) {
                uint32_t b0, b1, b2, b3;
                LDSM_X4(b0, b1, b2, b3,
                        kbB + (uint32_t)(t * 16 * QS_STRIDE * 4) + bKoff + (uint32_t)ks * 32u);
                uint32_t bb0[2] = {b0, b1}, bb1[2] = {b2, b3};
                mma_f16(s[2 * t],     a, bb0);
                mma_f16(s[2 * t + 1], a, bb1);
            }
        }

        // ---- causal mask on diagonal block ----
        if (j == i) {
            const int q0 = 16 * w + g, q1 = q0 + 8;
#pragma unroll
            for (int nt = 0; nt < 16; nt++) {
                int key = 8 * nt + 2 * tig;
                if (key     > q0) s[nt][0] = -1e30f;
                if (key + 1 > q0) s[nt][1] = -1e30f;
                if (key     > q1) s[nt][2] = -1e30f;
                if (key + 1 > q1) s[nt][3] = -1e30f;
            }
        }

        // ---- online softmax update ----
        float rm0 = -1e30f, rm1 = -1e30f;
#pragma unroll
        for (int nt = 0; nt < 16; nt++) {
            rm0 = fmaxf(rm0, fmaxf(s[nt][0], s[nt][1]));
            rm1 = fmaxf(rm1, fmaxf(s[nt][2], s[nt][3]));
        }
        rm0 = fmaxf(rm0, __shfl_xor_sync(0xffffffffu, rm0, 1));
        rm0 = fmaxf(rm0, __shfl_xor_sync(0xffffffffu, rm0, 2));
        rm1 = fmaxf(rm1, __shfl_xor_sync(0xffffffffu, rm1, 1));
        rm1 = fmaxf(rm1, __shfl_xor_sync(0xffffffffu, rm1, 2));

        const float mn0 = fmaxf(m0, rm0), mn1 = fmaxf(m1, rm1);
        const float sc0 = __expf(m0 - mn0), sc1 = __expf(m1 - mn1);
        m0 = mn0; m1 = mn1;

        float ps0 = 0.f, ps1 = 0.f;
#pragma unroll
        for (int nt = 0; nt < 16; nt++) {
            s[nt][0] = __expf(s[nt][0] - m0);
            s[nt][1] = __expf(s[nt][1] - m0);
            s[nt][2] = __expf(s[nt][2] - m1);
            s[nt][3] = __expf(s[nt][3] - m1);
            ps0 += s[nt][0] + s[nt][1];
            ps1 += s[nt][2] + s[nt][3];
            o[nt][0] *= sc0; o[nt][1] *= sc0;
            o[nt][2] *= sc1; o[nt][3] *= sc1;
        }
        ps0 += __shfl_xor_sync(0xffffffffu, ps0, 1);
        ps0 += __shfl_xor_sync(0xffffffffu, ps0, 2);
        ps1 += __shfl_xor_sync(0xffffffffu, ps1, 1);
        ps1 += __shfl_xor_sync(0xffffffffu, ps1, 2);
        l0 = l0 * sc0 + ps0;
        l1 = l1 * sc1 + ps1;

        // ---- O += p @ V (p from registers as A-fragments) ----
#pragma unroll
        for (int kt = 0; kt < 8; kt++) {
            uint32_t a[4];
            a[0] = h2u(__floats2half2_rn(s[2 * kt][0],     s[2 * kt][1]));
            a[1] = h2u(__floats2half2_rn(s[2 * kt][2],     s[2 * kt][3]));
            a[2] = h2u(__floats2half2_rn(s[2 * kt + 1][0], s[2 * kt + 1][1]));
            a[3] = h2u(__floats2half2_rn(s[2 * kt + 1][2], s[2 * kt + 1][3]));
#pragma unroll
            for (int t = 0; t < 8; t++) {
                uint32_t b0, b1, b2, b3;
                LDSM_X4(b0, b1, b2, b3,
                        vbB + (uint32_t)(t * 16 * VS_STRIDE * 4) + bVoff + (uint32_t)kt * 32u);
                uint32_t bb0[2] = {b0, b1}, bb1[2] = {b2, b3};
                mma_f16(o[2 * t],     a, bb0);
                mma_f16(o[2 * t + 1], a, bb1);
            }
        }
        __syncthreads();
    }

    // ---- normalize + write ----
    const float inv0 = 1.f / l0, inv1 = 1.f / l1;
    const size_t row0 = (size_t)(b * Sb + i * 128 + w * 16 + g);
    __half* out0 = Of + row0 * (NH * VD) + h * VD;
    __half* out1 = out0 + (size_t)8 * (NH * VD);
#pragma unroll
    for (int nt = 0; nt < 16; nt++) {
        int col = 8 * nt + 2 * tig;
        *(__half2*)(out0 + col) = __floats2half2_rn(o[nt][0] * inv0, o[nt][1] * inv0);
        *(__half2*)(out1 + col) = __floats2half2_rn(o[nt][2] * inv1, o[nt][3] * inv1);
    }
}

// ---------------- fused f32 -> f16 conversion for 6 tensors ----------------
#define CV0 (MBS * Hd / 4)
#define CV1 (CV0 + QLR * Hd / 4)
#define CV2 (CV1 + NH * QKD * QLR / 4)
#define CV3 (CV2 + DATT * Hd / 4)
#define CV4 (CV3 + Hd * NH * VD / 4)
#define CV5 (CV4 + NH * NOPE * KVLR / 4)

__global__ void cvt_all(const float* __restrict__ s0, const float* __restrict__ s1,
                        const float* __restrict__ s2, const float* __restrict__ s3,
                        const float* __restrict__ s4, const float* __restrict__ s5)
{
    __half *d;
    const float *s;
    int stride = gridDim.x * blockDim.x;
    for (int i = blockIdx.x * blockDim.x + threadIdx.x; i < CV5; i += stride) {
        int off;
        if (i < CV0)      { s = s0; off = i;       d = g_hid; }
        else if (i < CV1) { s = s1; off = i - CV0; d = g_wqa; }
        else if (i < CV2) { s = s2; off = i - CV1; d = g_wqb; }
        else if (i < CV3) { s = s3; off = i - CV2; d = g_wkva; }
        else if (i < CV4) { s = s4; off = i - CV3; d = g_wo; }
        else              { s = s5; off = i - CV4; d = g_wuk; }
        float4 v = ((const float4*)s)[off];
        ((__half2*)d)[2 * off]     = __floats2half2_rn(v.x, v.y);
        ((__half2*)d)[2 * off + 1] = __floats2half2_rn(v.z, v.w);
    }
}

// ---------------- transpose f32 -> f16 ----------------
__global__ void transpose_f32h(const float* __restrict__ in, long long sIn, int ldin,
                               __half* __restrict__ out, long long sOut, int ldout)
{
    __shared__ float t[32][33];
    const float* ib = in + (size_t)blockIdx.z * sIn;
    __half* ob = out + (size_t)blockIdx.z * sOut;
    int x0 = blockIdx.x * 32, y0 = blockIdx.y * 32;
    int tx = threadIdx.x, ty = threadIdx.y;
#pragma unroll
    for (int j = 0; j < 32; j += 8)
        t[ty + j][tx] = ib[(size_t)(y0 + ty + j) * ldin + x0 + tx];
    __syncthreads();
#pragma unroll
    for (int j = 0; j < 32; j += 8)
        ob[(size_t)(x0 + ty + j) * ldout + y0 + tx] = __float2half_rn(t[tx][ty + j]);
}

// ---------------- LayerNorm: register-cached, 128 threads, NV float4/thread ----
template<int NV>
__global__ void __launch_bounds__(128)
ln_rows_v(const float* __restrict__ in, int ldin,
          const float* __restrict__ w,
          __half* __restrict__ out, int ldout)
{
    const int dim = NV * 512;
    const int r = blockIdx.x, tid = threadIdx.x;
    const int lane = tid & 31, warp = tid >> 5;
    const float4* x = (const float4*)(in + (size_t)r * ldin);
    __shared__ float sm4[4];
    __shared__ float stats[2];

    float4 v[NV];
    float s = 0.f;
#pragma unroll
    for (int q = 0; q < NV; q++) {
        v[q] = x[tid + q * 128];
        s += v[q].x + v[q].y + v[q].z + v[q].w;
    }
#pragma unroll
    for (int o = 16; o > 0; o >>= 1) s += __shfl_xor_sync(0xffffffffu, s, o);
    if (lane == 0) sm4[warp] = s;
    __syncthreads();
    if (tid == 0) stats[0] = (sm4[0] + sm4[1] + sm4[2] + sm4[3]) / dim;
    __syncthreads();
    const float mean = stats[0];

    float vv = 0.f;
#pragma unroll
    for (int q = 0; q < NV; q++) {
        float dx = v[q].x - mean, dy = v[q].y - mean;
        float dz = v[q].z - mean, dw = v[q].w - mean;
        vv += dx * dx + dy * dy + dz * dz + dw * dw;
    }
#pragma unroll
    for (int o = 16; o > 0; o >>= 1) vv += __shfl_xor_sync(0xffffffffu, vv, o);
    if (lane == 0) sm4[warp] = vv;
    __syncthreads();
    if (tid == 0) stats[1] = rsqrtf((sm4[0] + sm4[1] + sm4[2] + sm4[3]) / dim + 1e-5f);
    __syncthreads();
    const float rstd = stats[1];

    __half2* yo = (__half2*)(out + (size_t)r * ldout);
#pragma unroll
    for (int q = 0; q < NV; q++) {
        float4 ww = ((const float4*)w)[tid + q * 128];
        int c = tid + q * 128;
        yo[2 * c]     = __floats2half2_rn((v[q].x - mean) * rstd * ww.x,
                                          (v[q].y - mean) * rstd * ww.y);
        yo[2 * c + 1] = __floats2half2_rn((v[q].z - mean) * rstd * ww.z,
                                          (v[q].w - mean) * rstd * ww.w);
    }
}

// ---------------- RoPE k_pe: writes SCALE*rope(k_pe) into all head slots of Kb
__global__ void rope_k(const float* __restrict__ cosb, const float* __restrict__ sinb)
{
    int r = blockIdx.x;
    int i = threadIdx.x;
    int b = r >> 10;
    int s = r & (Sb - 1);
    const float* src = g_kva + (size_t)r * DATT + KVLR;
    float x = src[i];
    float other = src[(i < 32) ? (i + 32) : (i - 32)];
    float rot = (i < 32) ? -other : other;
    __half v = __float2half_rn((x * cosb[r * ROPE + i] + rot * sinb[r * ROPE + i]) * SCALE);
#pragma unroll
    for (int h = 0; h < NH; h++)
        g_kb[(((size_t)(b * NH + h) * Sb) + s) * QKD + NOPE + i] = v;
}

// ---------------- RoPE q_pe: in-place on g_q ----------------
__global__ void rope_q(const float* __restrict__ cosb, const float* __restrict__ sinb)
{
    int bs = blockIdx.x >> 4;
    int h  = blockIdx.x & 15;
    int i  = threadIdx.x;
    __half* base = g_q + (size_t)bs * (NH * QKD) + h * QKD + NOPE;
    float x = __half2float(base[i]);
    float other = __half2float(base[(i < 32) ? (i + 32) : (i - 32)]);
    __syncthreads();
    float rot = (i < 32) ? -other : other;
    base[i] = __float2half_rn(x * cosb[bs * ROPE + i] + rot * sinb[bs * ROPE + i]);
}

// ---------------- launch ----------------
extern "C" void kernel_launch(void* const* d_in, const int* in_sizes, int n_in,
                              void* d_out, int out_size)
{
    const float* hidden  = (const float*)d_in[0];
    const float* cosb    = (const float*)d_in[1];
    const float* sinb    = (const float*)d_in[2];
    const float* w_qa    = (const float*)d_in[3];
    const float* qalnw   = (const float*)d_in[4];
    const float* w_qb    = (const float*)d_in[5];
    const float* w_kva   = (const float*)d_in[6];
    const float* kvalnw  = (const float*)d_in[7];
    const float* W_UK_T  = (const float*)d_in[8];
    const float* W_UV    = (const float*)d_in[9];
    const float* w_o     = (const float*)d_in[10];
    float* out = (float*)d_out;

    float *p_qa, *p_kva;
    __half *p_hid, *p_wqa, *p_wqb, *p_wkva, *p_wo, *p_wuk;
    __half *p_qaln, *p_q, *p_kattn, *p_kb, *p_vT, *p_of, *p_wuvT;
    cudaGetSymbolAddress((void**)&p_qa,    g_qa);
    cudaGetSymbolAddress((void**)&p_kva,   g_kva);
    cudaGetSymbolAddress((void**)&p_hid,   g_hid);
    cudaGetSymbolAddress((void**)&p_wqa,   g_wqa);
    cudaGetSymbolAddress((void**)&p_wqb,   g_wqb);
    cudaGetSymbolAddress((void**)&p_wkva,  g_wkva);
    cudaGetSymbolAddress((void**)&p_wo,    g_wo);
    cudaGetSymbolAddress((void**)&p_wuk,   g_wuk);
    cudaGetSymbolAddress((void**)&p_qaln,  g_qaln);
    cudaGetSymbolAddress((void**)&p_q,     g_q);
    cudaGetSymbolAddress((void**)&p_kattn, g_kattn);
    cudaGetSymbolAddress((void**)&p_kb,    g_kb);
    cudaGetSymbolAddress((void**)&p_vT,    g_vT);
    cudaGetSymbolAddress((void**)&p_of,    g_outfl);
    cudaGetSymbolAddress((void**)&p_wuvT,  g_wuvT);

    const int SMEM = 4 * TILE_W * 4;   // 73728 bytes
    cudaFuncSetAttribute(mma_gemm, cudaFuncAttributeMaxDynamicSharedMemorySize, SMEM);
    cudaFuncSetAttribute(flash_attn, cudaFuncAttributeMaxDynamicSharedMemorySize, SMEM_FLASH);

    auto grid = [](int M, int N, int z) {
        return dim3((N + BN - 1) / BN, (M + BM - 1) / BM, z);
    };
    const int T = 256;

    // ---- convert all external inputs to fp16 ----
    cvt_all<<<1184, 256>>>(hidden, w_qa, w_qb, w_kva, w_o, W_UK_T);

    // 1) qa(f32) = hid @ wqa^T   [2048,1536] K=2048
    mma_gemm<<<grid(MBS, QLR, 1), T, SMEM>>>(
        p_hid, Hd, 0,1,0,1,  p_wqa, Hd, 0,1,0,1,  p_qa, QLR, 0,1,0,1,  MBS, QLR, Hd, 0, 1.f);

    // 2) kva(f32) = hid @ wkva^T [2048,576] K=2048
    mma_gemm<<<grid(MBS, DATT, 1), T, SMEM>>>(
        p_hid, Hd, 0,1,0,1,  p_wkva, Hd, 0,1,0,1,  p_kva, DATT, 0,1,0,1,  MBS, DATT, Hd, 0, 1.f);

    // 3) LN(qa) -> qaln(h)
    ln_rows_v<3><<<MBS, 128>>>(p_qa, QLR, qalnw, p_qaln, QLR);

    // 4) LN(kv_c) -> kattn(h)[:, :512]
    ln_rows_v<1><<<MBS, 128>>>(p_kva, DATT, kvalnw, p_kattn, DATT);

    // 5) rope(k_pe)*SCALE -> Kb[b,h][:,128:192]
    rope_k<<<MBS, 64>>>(cosb, sinb);

    // T2) W_UV(f32) -> wuvT(h) [h][128][512]
    transpose_f32h<<<dim3(4, 16, NH), dim3(32, 8)>>>(
        W_UV, (long long)KVLR * VD, VD, p_wuvT, (long long)VD * KVLR, KVLR);

    // V') vT[b,h] = wuvT[h] @ kv_c[b]^T   M=128, N=1024, K=512
    mma_gemm<<<grid(VD, Sb, Bb * NH), T, SMEM>>>(
        p_wuvT, KVLR, 0,1, (long long)VD * KVLR, NH,
        p_kattn, DATT, (long long)Sb * DATT, NH, 0, 1,
        p_vT, Sb, (long long)VD * Sb, 1, 0, 1,
        VD, Sb, KVLR, 1, 1.f);

    // K') Kb[b,h][:,0:128] = (kv_c[b] @ wuk[h]^T) * SCALE   M=1024, N=128, K=512
    mma_gemm<<<grid(Sb, NOPE, Bb * NH), T, SMEM>>>(
        p_kattn, DATT, (long long)Sb * DATT, NH, 0, 1,
        p_wuk, KVLR, 0,1, (long long)NOPE * KVLR, NH,
        p_kb, QKD, (long long)Sb * QKD, 1, 0, 1,
        Sb, NOPE, KVLR, 1, SCALE);

    // 6) q(h) = qaln @ wqb^T   [2048,3072] K=1536
    mma_gemm<<<grid(MBS, NH * QKD, 1), T, SMEM>>>(
        p_qaln, QLR, 0,1,0,1,  p_wqb, QLR, 0,1,0,1,  p_q, NH * QKD, 0,1,0,1,
        MBS, NH * QKD, QLR, 1, 1.f);

    // 7) rope(q_pe) in place
    rope_q<<<MBS * NH, 64>>>(cosb, sinb);

    // 9-11) fused flash attention -> outfl(h)
    flash_attn<<<dim3(8, Bb * NH), 256, SMEM_FLASH>>>(p_q, p_kb, p_vT, p_of);

    // 13) out(f32) = outfl @ wo^T  [2048,2048] K=2048
    mma_gemm<<<grid(MBS, Hd, 1), T, SMEM>>>(
        p_of, NH * VD, 0,1,0,1,  p_wo, NH * VD, 0,1,0,1,  out, Hd, 0,1,0,1,
        MBS, Hd, NH * VD, 0, 1.f);
}

// round 14
// speedup vs baseline: 4.4126x; 1.1534x over previous
#include <cuda_runtime.h>
#include <cuda_fp16.h>
#include <math.h>
#include <stdint.h>

// ---------------- problem constants ----------------
#define Bb 2
#define Sb 1024
#define Hd 2048
#define NH 16
#define NOPE 128
#define ROPE 64
#define VD 128
#define QKD 192
#define QLR 1536
#define KVLR 512
#define DATT 576
#define MBS (Bb*Sb)
#define NQK (QLR + DATT)               // 2112 combined qa|kva width
#define SCALE 0.07216878364870323f    // 1/sqrt(192)

// ---------------- scratch ----------------
__device__ float  g_qakva [MBS * NQK];             // [2048][2112] = qa | kva
__device__ __half g_hid   [MBS * Hd];
__device__ __half g_wqkv  [NQK * Hd];              // wqa rows 0:1536 | wkva rows 1536:2112
__device__ __half g_wqb   [NH * QKD * QLR];
__device__ __half g_wo    [Hd * NH * VD];
__device__ __half g_wuk   [NH * NOPE * KVLR];      // W_UK_T f16 [h][128][512]
__device__ __half g_qaln  [MBS * QLR];
__device__ __half g_q     [MBS * NH * QKD];        // rope applied in place
__device__ __half g_kattn [MBS * DATT];            // LN(kv_c) (cols 0:512)
__device__ __half g_kb    [(size_t)Bb*NH*Sb*QKD];  // absorbed keys, scaled
__device__ __half g_vT    [(size_t)Bb*NH*VD*Sb];   // V'^T per (b,h): [128][1024]
__device__ __half g_outfl [MBS * NH * VD];
__device__ __half g_wuvT  [NH * VD * KVLR];

// ---------------- helpers ----------------
__device__ __forceinline__ uint32_t su32(const void* p) {
    uint32_t a;
    asm("{ .reg .u64 t; cvta.to.shared.u64 t, %1; cvt.u32.u64 %0, t; }" : "=r"(a) : "l"(p));
    return a;
}
__device__ __forceinline__ uint32_t h2u(__half2 h) {
    union { __half2 h; uint32_t u; } c;
    c.h = h;
    return c.u;
}
__device__ __forceinline__ void mma_f16(float c[4], const uint32_t a[4], const uint32_t b[2]) {
    asm volatile(
        "mma.sync.aligned.m16n8k16.row.col.f32.f16.f16.f32 "
        "{%0,%1,%2,%3},{%4,%5,%6,%7},{%8,%9},{%0,%1,%2,%3};"
        : "+f"(c[0]), "+f"(c[1]), "+f"(c[2]), "+f"(c[3])
        : "r"(a[0]), "r"(a[1]), "r"(a[2]), "r"(a[3]), "r"(b[0]), "r"(b[1]));
}
#define LDSM_X4(r0, r1, r2, r3, addr) \
    asm volatile("ldmatrix.sync.aligned.m8n8.x4.shared.b16 {%0,%1,%2,%3}, [%4];" \
                 : "=r"(r0), "=r"(r1), "=r"(r2), "=r"(r3) : "r"(addr))
#define CP_ASYNC16(dst, src, sz) \
    asm volatile("cp.async.cg.shared.global [%0], [%1], 16, %2;" \
                 :: "r"(dst), "l"(src), "r"(sz) : "memory")
#define CP_COMMIT() asm volatile("cp.async.commit_group;" ::: "memory")
#define CP_WAIT(n)  asm volatile("cp.async.wait_group %0;" :: "n"(n) : "memory")

// ---------------- fp16 mma GEMM: 128x128 block, 8 warps (64x32 warp tile) ----
#define BM 128
#define BN 128
#define BKK 64
#define WSH 36
#define TILE_W (BM * WSH)

__global__ void __launch_bounds__(256, 2)
mma_gemm(const __half* __restrict__ A, int lda, long long sAd, int dA, long long sAm, int mA,
         const __half* __restrict__ B, int ldb, long long sBd, int dB, long long sBm, int mB,
         void*         __restrict__ Cv, int ldc, long long sCd, int dC, long long sCm, int mC,
         int M, int N, int K, int outHalf, float cscale)
{
    const int mBase = blockIdx.y * BM;
    const int nBase = blockIdx.x * BN;

    extern __shared__ uint32_t smw[];
    const uint32_t sAbase = su32(smw);
    const uint32_t sBbase = sAbase + 2u * TILE_W * 4u;

    const int z = blockIdx.z;
    const __half* Ab = A + (size_t)(z / dA) * sAd + (size_t)(z % mA) * sAm;
    const __half* Bp = B + (size_t)(z / dB) * sBd + (size_t)(z % mB) * sBm;
    const size_t  cOff = (size_t)(z / dC) * sCd + (size_t)(z % mC) * sCm;

    const int tid  = threadIdx.x;
    const int lane = tid & 31;
    const int warp = tid >> 5;
    const int wm   = warp & 1;
    const int wn   = warp >> 1;
    const int g    = lane >> 2;
    const int tig  = lane & 3;

    uint32_t aAddr[4];
#pragma unroll
    for (int ii = 0; ii < 4; ii++)
        aAddr[ii] = sAbase +
            (uint32_t)(((wm * 64 + ii * 16 + (lane & 15)) * WSH + ((lane >> 4) << 2)) * 4);
    uint32_t bAddr[2];
#pragma unroll
    for (int q = 0; q < 2; q++)
        bAddr[q] = sBbase +
            (uint32_t)(((wn * 32 + q * 16 + (lane & 7) + ((lane >> 4) << 3)) * WSH
                        + (((lane >> 3) & 1) << 2)) * 4);

    float acc[4][4][4];
#pragma unroll
    for (int i = 0; i < 4; i++)
#pragma unroll
        for (int j = 0; j < 4; j++)
#pragma unroll
            for (int r = 0; r < 4; r++) acc[i][j][r] = 0.f;

    const int nc = K / BKK;

    auto copy_chunk = [&](int ci, int p) {
        const int k0 = ci * BKK;
        const uint32_t aD = sAbase + (uint32_t)p * TILE_W * 4u;
        const uint32_t bD = sBbase + (uint32_t)p * TILE_W * 4u;
#pragma unroll
        for (int q = 0; q < 4; q++) {
            int slot = tid + q * 256;
            int row  = slot >> 3;
            int c8   = (slot & 7) << 3;
            uint32_t soff = (uint32_t)(row * (WSH * 4) + c8 * 2);
            int gm = mBase + row;
            const __half* asrc = (gm < M) ? (Ab + (size_t)gm * lda + k0 + c8) : Ab;
            CP_ASYNC16(aD + soff, asrc, (gm < M) ? 16 : 0);
            int gn = nBase + row;
            const __half* bsrc = (gn < N) ? (Bp + (size_t)gn * ldb + k0 + c8) : Bp;
            CP_ASYNC16(bD + soff, bsrc, (gn < N) ? 16 : 0);
        }
        CP_COMMIT();
    };

    copy_chunk(0, 0);

    for (int i = 0; i < nc; i++) {
        const int p = i & 1;
        if (i + 1 < nc) { copy_chunk(i + 1, p ^ 1); CP_WAIT(1); }
        else            { CP_WAIT(0); }
        __syncthreads();

        const uint32_t pOff = (uint32_t)p * TILE_W * 4u;
#pragma unroll
        for (int ks = 0; ks < 4; ks++) {
            const uint32_t kOff = pOff + (uint32_t)ks * 32u;
            uint32_t a[4][4], b[4][2];
#pragma unroll
            for (int ii = 0; ii < 4; ii++)
                LDSM_X4(a[ii][0], a[ii][1], a[ii][2], a[ii][3], aAddr[ii] + kOff);
            LDSM_X4(b[0][0], b[0][1], b[1][0], b[1][1], bAddr[0] + kOff);
            LDSM_X4(b[2][0], b[2][1], b[3][0], b[3][1], bAddr[1] + kOff);
#pragma unroll
            for (int ii = 0; ii < 4; ii++)
#pragma unroll
                for (int jj = 0; jj < 4; jj++)
                    mma_f16(acc[ii][jj], a[ii], b[jj]);
        }
        __syncthreads();
    }

    if (outHalf) {
        __half* Ch = (__half*)Cv + cOff;
#pragma unroll
        for (int i = 0; i < 4; i++) {
            int r0 = mBase + (wm << 6) + (i << 4) + g;
            if (r0 >= M) continue;
#pragma unroll
            for (int j = 0; j < 4; j++) {
                int col = nBase + (wn << 5) + (j << 3) + (tig << 1);
                if (col < N) {
                    *(__half2*)(Ch + (size_t)r0 * ldc + col) =
                        __floats2half2_rn(acc[i][j][0] * cscale, acc[i][j][1] * cscale);
                    *(__half2*)(Ch + (size_t)(r0 + 8) * ldc + col) =
                        __floats2half2_rn(acc[i][j][2] * cscale, acc[i][j][3] * cscale);
                }
            }
        }
    } else {
        float* Cf = (float*)Cv + cOff;
#pragma unroll
        for (int i = 0; i < 4; i++) {
            int r0 = mBase + (wm << 6) + (i << 4) + g;
            if (r0 >= M) continue;
#pragma unroll
            for (int j = 0; j < 4; j++) {
                int col = nBase + (wn << 5) + (j << 3) + (tig << 1);
                if (col < N) {
                    *(float2*)(Cf + (size_t)r0 * ldc + col)       = make_float2(acc[i][j][0], acc[i][j][1]);
                    *(float2*)(Cf + (size_t)(r0 + 8) * ldc + col) = make_float2(acc[i][j][2], acc[i][j][3]);
                }
            }
        }
    }
}

// ---------------- flash attention (unchanged from round 13) ----------------
#define QS_STRIDE 100
#define VS_STRIDE 68
#define QS_B (128 * QS_STRIDE * 4)
#define VS_B (128 * VS_STRIDE * 4)
#define BUF_B (QS_B + VS_B)
#define SMEM_FLASH (QS_B + 2 * BUF_B)

__global__ void __launch_bounds__(256, 1)
flash_attn(const __half* __restrict__ Q, const __half* __restrict__ Kb,
           const __half* __restrict__ Vt, __half* __restrict__ Of)
{
    const int i = 7 - (int)blockIdx.x;
    const int z = blockIdx.y;
    const int b = z >> 4, h = z & 15;

    extern __shared__ uint32_t smw[];
    const uint32_t sQ  = su32(smw);
    const uint32_t sB0 = sQ + QS_B;

    const int tid = threadIdx.x, lane = tid & 31, w = tid >> 5;
    const int g = lane >> 2, tig = lane & 3;

    const __half* Qg = Q  + (size_t)(b * Sb + i * 128) * (NH * QKD) + h * QKD;
    const __half* Kg = Kb + (size_t)z * Sb * QKD;
    const __half* Vg = Vt + (size_t)z * VD * Sb;

    const uint32_t aQbase = sQ + (uint32_t)(((w * 16 + (lane & 15)) * QS_STRIDE
                                             + ((lane >> 4) << 2)) * 4);
    const uint32_t bKoff = (uint32_t)((((lane & 7) + ((lane >> 4) << 3)) * QS_STRIDE
                                       + (((lane >> 3) & 1) << 2)) * 4);
    const uint32_t bVoff = (uint32_t)((((lane & 7) + ((lane >> 4) << 3)) * VS_STRIDE
                                       + (((lane >> 3) & 1) << 2)) * 4);

    auto load_K = [&](int j, uint32_t dst) {
        const __half* src = Kg + (size_t)j * 128 * QKD;
        for (int t = tid; t < 128 * 24; t += 256) {
            int row = t / 24, cc = t % 24;
            CP_ASYNC16(dst + (uint32_t)(row * QS_STRIDE + cc * 4) * 4,
                       src + (size_t)row * QKD + cc * 8, 16);
        }
    };
    auto load_V = [&](int j, uint32_t dst) {
        for (int t = tid; t < 128 * 16; t += 256) {
            int row = t / 16, cc = t % 16;
            CP_ASYNC16(dst + (uint32_t)(row * VS_STRIDE + cc * 4) * 4,
                       Vg + (size_t)row * Sb + j * 128 + cc * 8, 16);
        }
    };

    for (int t = tid; t < 128 * 24; t += 256) {
        int row = t / 24, cc = t % 24;
        CP_ASYNC16(sQ + (uint32_t)(row * QS_STRIDE + cc * 4) * 4,
                   Qg + (size_t)row * (NH * QKD) + cc * 8, 16);
    }
    load_K(0, sB0);
    load_V(0, sB0 + QS_B);
    CP_COMMIT();

    float m0 = -1e30f, m1 = -1e30f, l0 = 0.f, l1 = 0.f;
    float o[16][4];
#pragma unroll
    for (int nt = 0; nt < 16; nt++)
#pragma unroll
        for (int r = 0; r < 4; r++) o[nt][r] = 0.f;

    for (int j = 0; j <= i; j++) {
        const int p = j & 1;
        if (j < i) {
            const uint32_t nb = sB0 + (uint32_t)(p ^ 1) * BUF_B;
            load_K(j + 1, nb);
            load_V(j + 1, nb + QS_B);
            CP_COMMIT();
            CP_WAIT(1);
        } else {
            CP_WAIT(0);
        }
        __syncthreads();

        const uint32_t kbB = sB0 + (uint32_t)p * BUF_B;
        const uint32_t vbB = kbB + QS_B;

        float s[16][4];
#pragma unroll
        for (int nt = 0; nt < 16; nt++)
#pragma unroll
            for (int r = 0; r < 4; r++) s[nt][r] = 0.f;

#pragma unroll
        for (int ks = 0; ks < 12; ks++) {
            uint32_t a[4];
            LDSM_X4(a[0], a[1], a[2], a[3], aQbase + (uint32_t)ks * 32u);
#pragma unroll
            for (int t = 0; t < 8; t++) {
                uint32_t b0, b1, b2, b3;
                LDSM_X4(b0, b1, b2, b3,
                        kbB + (uint32_t)(t * 16 * QS_STRIDE * 4) + bKoff + (uint32_t)ks * 32u);
                uint32_t bb0[2] = {b0, b1}, bb1[2] = {b2, b3};
                mma_f16(s[2 * t],     a, bb0);
                mma_f16(s[2 * t + 1], a, bb1);
            }
        }

        if (j == i) {
            const int q0 = 16 * w + g, q1 = q0 + 8;
#pragma unroll
            for (int nt = 0; nt < 16; nt++) {
                int key = 8 * nt + 2 * tig;
                if (key     > q0) s[nt][0] = -1e30f;
                if (key + 1 > q0) s[nt][1] = -1e30f;
                if (key     > q1) s[nt][2] = -1e30f;
                if (key + 1 > q1) s[nt][3] = -1e30f;
            }
        }

        float rm0 = -1e30f, rm1 = -1e30f;
#pragma unroll
        for (int nt = 0; nt < 16; nt++) {
            rm0 = fmaxf(rm0, fmaxf(s[nt][0], s[nt][1]));
            rm1 = fmaxf(rm1, fmaxf(s[nt][2], s[nt][3]));
        }
        rm0 = fmaxf(rm0, __shfl_xor_sync(0xffffffffu, rm0, 1));
        rm0 = fmaxf(rm0, __shfl_xor_sync(0xffffffffu, rm0, 2));
        rm1 = fmaxf(rm1, __shfl_xor_sync(0xffffffffu, rm1, 1));
        rm1 = fmaxf(rm1, __shfl_xor_sync(0xffffffffu, rm1, 2));

        const float mn0 = fmaxf(m0, rm0), mn1 = fmaxf(m1, rm1);
        const float sc0 = __expf(m0 - mn0), sc1 = __expf(m1 - mn1);
        m0 = mn0; m1 = mn1;

        float ps0 = 0.f, ps1 = 0.f;
#pragma unroll
        for (int nt = 0; nt < 16; nt++) {
            s[nt][0] = __expf(s[nt][0] - m0);
            s[nt][1] = __expf(s[nt][1] - m0);
            s[nt][2] = __expf(s[nt][2] - m1);
            s[nt][3] = __expf(s[nt][3] - m1);
            ps0 += s[nt][0] + s[nt][1];
            ps1 += s[nt][2] + s[nt][3];
            o[nt][0] *= sc0; o[nt][1] *= sc0;
            o[nt][2] *= sc1; o[nt][3] *= sc1;
        }
        ps0 += __shfl_xor_sync(0xffffffffu, ps0, 1);
        ps0 += __shfl_xor_sync(0xffffffffu, ps0, 2);
        ps1 += __shfl_xor_sync(0xffffffffu, ps1, 1);
        ps1 += __shfl_xor_sync(0xffffffffu, ps1, 2);
        l0 = l0 * sc0 + ps0;
        l1 = l1 * sc1 + ps1;

#pragma unroll
        for (int kt = 0; kt < 8; kt++) {
            uint32_t a[4];
            a[0] = h2u(__floats2half2_rn(s[2 * kt][0],     s[2 * kt][1]));
            a[1] = h2u(__floats2half2_rn(s[2 * kt][2],     s[2 * kt][3]));
            a[2] = h2u(__floats2half2_rn(s[2 * kt + 1][0], s[2 * kt + 1][1]));
            a[3] = h2u(__floats2half2_rn(s[2 * kt + 1][2], s[2 * kt + 1][3]));
#pragma unroll
            for (int t = 0; t < 8; t++) {
                uint32_t b0, b1, b2, b3;
                LDSM_X4(b0, b1, b2, b3,
                        vbB + (uint32_t)(t * 16 * VS_STRIDE * 4) + bVoff + (uint32_t)kt * 32u);
                uint32_t bb0[2] = {b0, b1}, bb1[2] = {b2, b3};
                mma_f16(o[2 * t],     a, bb0);
                mma_f16(o[2 * t + 1], a, bb1);
            }
        }
        __syncthreads();
    }

    const float inv0 = 1.f / l0, inv1 = 1.f / l1;
    const size_t row0 = (size_t)(b * Sb + i * 128 + w * 16 + g);
    __half* out0 = Of + row0 * (NH * VD) + h * VD;
    __half* out1 = out0 + (size_t)8 * (NH * VD);
#pragma unroll
    for (int nt = 0; nt < 16; nt++) {
        int col = 8 * nt + 2 * tig;
        *(__half2*)(out0 + col) = __floats2half2_rn(o[nt][0] * inv0, o[nt][1] * inv0);
        *(__half2*)(out1 + col) = __floats2half2_rn(o[nt][2] * inv1, o[nt][3] * inv1);
    }
}

// ---------------- fused f32 -> f16 conversion (hid, wqa|wkva -> wqkv, wqb, wo, wuk)
#define CV0 (MBS * Hd / 4)
#define CV1 (CV0 + QLR * Hd / 4)
#define CV2 (CV1 + DATT * Hd / 4)
#define CV3 (CV2 + NH * QKD * QLR / 4)
#define CV4 (CV3 + Hd * NH * VD / 4)
#define CV5 (CV4 + NH * NOPE * KVLR / 4)

__global__ void cvt_all(const float* __restrict__ s0, const float* __restrict__ s1,
                        const float* __restrict__ s2, const float* __restrict__ s3,
                        const float* __restrict__ s4, const float* __restrict__ s5)
{
    __half *d;
    const float *s;
    int stride = gridDim.x * blockDim.x;
    for (int i = blockIdx.x * blockDim.x + threadIdx.x; i < CV5; i += stride) {
        int off;
        if (i < CV0)      { s = s0; off = i;       d = g_hid; }
        else if (i < CV1) { s = s1; off = i - CV0; d = g_wqkv; }                    // wqa
        else if (i < CV2) { s = s2; off = i - CV1; d = g_wqkv + QLR * Hd / 4 * 4; } // wkva
        else if (i < CV3) { s = s3; off = i - CV2; d = g_wqb; }
        else if (i < CV4) { s = s4; off = i - CV3; d = g_wo; }
        else              { s = s5; off = i - CV4; d = g_wuk; }
        float4 v = ((const float4*)s)[off];
        ((__half2*)d)[2 * off]     = __floats2half2_rn(v.x, v.y);
        ((__half2*)d)[2 * off + 1] = __floats2half2_rn(v.z, v.w);
    }
}

// ---------------- transpose f32 -> f16 ----------------
__global__ void transpose_f32h(const float* __restrict__ in, long long sIn, int ldin,
                               __half* __restrict__ out, long long sOut, int ldout)
{
    __shared__ float t[32][33];
    const float* ib = in + (size_t)blockIdx.z * sIn;
    __half* ob = out + (size_t)blockIdx.z * sOut;
    int x0 = blockIdx.x * 32, y0 = blockIdx.y * 32;
    int tx = threadIdx.x, ty = threadIdx.y;
#pragma unroll
    for (int j = 0; j < 32; j += 8)
        t[ty + j][tx] = ib[(size_t)(y0 + ty + j) * ldin + x0 + tx];
    __syncthreads();
#pragma unroll
    for (int j = 0; j < 32; j += 8)
        ob[(size_t)(x0 + ty + j) * ldout + y0 + tx] = __float2half_rn(t[tx][ty + j]);
}

// ---------------- LayerNorm (q path): register-cached, 128 threads -----------
template<int NV>
__global__ void __launch_bounds__(128)
ln_rows_v(const float* __restrict__ in, int ldin,
          const float* __restrict__ w,
          __half* __restrict__ out, int ldout)
{
    const int dim = NV * 512;
    const int r = blockIdx.x, tid = threadIdx.x;
    const int lane = tid & 31, warp = tid >> 5;
    const float4* x = (const float4*)(in + (size_t)r * ldin);
    __shared__ float sm4[4];
    __shared__ float stats[2];

    float4 v[NV];
    float s = 0.f;
#pragma unroll
    for (int q = 0; q < NV; q++) {
        v[q] = x[tid + q * 128];
        s += v[q].x + v[q].y + v[q].z + v[q].w;
    }
#pragma unroll
    for (int o = 16; o > 0; o >>= 1) s += __shfl_xor_sync(0xffffffffu, s, o);
    if (lane == 0) sm4[warp] = s;
    __syncthreads();
    if (tid == 0) stats[0] = (sm4[0] + sm4[1] + sm4[2] + sm4[3]) / dim;
    __syncthreads();
    const float mean = stats[0];

    float vv = 0.f;
#pragma unroll
    for (int q = 0; q < NV; q++) {
        float dx = v[q].x - mean, dy = v[q].y - mean;
        float dz = v[q].z - mean, dw = v[q].w - mean;
        vv += dx * dx + dy * dy + dz * dz + dw * dw;
    }
#pragma unroll
    for (int o = 16; o > 0; o >>= 1) vv += __shfl_xor_sync(0xffffffffu, vv, o);
    if (lane == 0) sm4[warp] = vv;
    __syncthreads();
    if (tid == 0) stats[1] = rsqrtf((sm4[0] + sm4[1] + sm4[2] + sm4[3]) / dim + 1e-5f);
    __syncthreads();
    const float rstd = stats[1];

    __half2* yo = (__half2*)(out + (size_t)r * ldout);
#pragma unroll
    for (int q = 0; q < NV; q++) {
        float4 ww = ((const float4*)w)[tid + q * 128];
        int c = tid + q * 128;
        yo[2 * c]     = __floats2half2_rn((v[q].x - mean) * rstd * ww.x,
                                          (v[q].y - mean) * rstd * ww.y);
        yo[2 * c + 1] = __floats2half2_rn((v[q].z - mean) * rstd * ww.z,
                                          (v[q].w - mean) * rstd * ww.w);
    }
}

// ---------------- kv path: LN(512) -> kattn, plus rope(k_pe)*SCALE -> Kb -----
__global__ void __launch_bounds__(128)
ln_kv_rope(const float* __restrict__ in /* g_qakva */, const float* __restrict__ w,
           const float* __restrict__ cosb, const float* __restrict__ sinb)
{
    const int r = blockIdx.x, tid = threadIdx.x;
    const int lane = tid & 31, warp = tid >> 5;
    const float4* x = (const float4*)(in + (size_t)r * NQK + QLR);
    __shared__ float sm4[4];
    __shared__ float stats[2];

    float4 v = x[tid];
    float s = v.x + v.y + v.z + v.w;
#pragma unroll
    for (int o = 16; o > 0; o >>= 1) s += __shfl_xor_sync(0xffffffffu, s, o);
    if (lane == 0) sm4[warp] = s;
    __syncthreads();
    if (tid == 0) stats[0] = (sm4[0] + sm4[1] + sm4[2] + sm4[3]) / KVLR;
    __syncthreads();
    const float mean = stats[0];

    float dx = v.x - mean, dy = v.y - mean, dz = v.z - mean, dw = v.w - mean;
    float vv = dx * dx + dy * dy + dz * dz + dw * dw;
#pragma unroll
    for (int o = 16; o > 0; o >>= 1) vv += __shfl_xor_sync(0xffffffffu, vv, o);
    if (lane == 0) sm4[warp] = vv;
    __syncthreads();
    if (tid == 0) stats[1] = rsqrtf((sm4[0] + sm4[1] + sm4[2] + sm4[3]) / KVLR + 1e-5f);
    __syncthreads();
    const float rstd = stats[1];

    __half2* yo = (__half2*)(g_kattn + (size_t)r * DATT);
    float4 ww = ((const float4*)w)[tid];
    yo[2 * tid]     = __floats2half2_rn((v.x - mean) * rstd * ww.x, (v.y - mean) * rstd * ww.y);
    yo[2 * tid + 1] = __floats2half2_rn((v.z - mean) * rstd * ww.z, (v.w - mean) * rstd * ww.w);

    // rope(k_pe)*SCALE -> all 16 head slots of Kb (threads 0..63)
    if (tid < ROPE) {
        const int i = tid;
        const int b = r >> 10, srow = r & (Sb - 1);
        const float* pe = in + (size_t)r * NQK + QLR + KVLR;
        float xx = pe[i];
        float other = pe[(i < 32) ? (i + 32) : (i - 32)];
        float rot = (i < 32) ? -other : other;
        __half hv = __float2half_rn((xx * cosb[r * ROPE + i] + rot * sinb[r * ROPE + i]) * SCALE);
#pragma unroll
        for (int h = 0; h < NH; h++)
            g_kb[(((size_t)(b * NH + h) * Sb) + srow) * QKD + NOPE + i] = hv;
    }
}

// ---------------- RoPE q_pe: in-place on g_q ----------------
__global__ void rope_q(const float* __restrict__ cosb, const float* __restrict__ sinb)
{
    int bs = blockIdx.x >> 4;
    int h  = blockIdx.x & 15;
    int i  = threadIdx.x;
    __half* base = g_q + (size_t)bs * (NH * QKD) + h * QKD + NOPE;
    float x = __half2float(base[i]);
    float other = __half2float(base[(i < 32) ? (i + 32) : (i - 32)]);
    __syncthreads();
    float rot = (i < 32) ? -other : other;
    base[i] = __float2half_rn(x * cosb[bs * ROPE + i] + rot * sinb[bs * ROPE + i]);
}

// ---------------- launch ----------------
extern "C" void kernel_launch(void* const* d_in, const int* in_sizes, int n_in,
                              void* d_out, int out_size)
{
    const float* hidden  = (const float*)d_in[0];
    const float* cosb    = (const float*)d_in[1];
    const float* sinb    = (const float*)d_in[2];
    const float* w_qa    = (const float*)d_in[3];
    const float* qalnw   = (const float*)d_in[4];
    const float* w_qb    = (const float*)d_in[5];
    const float* w_kva   = (const float*)d_in[6];
    const float* kvalnw  = (const float*)d_in[7];
    const float* W_UK_T  = (const float*)d_in[8];
    const float* W_UV    = (const float*)d_in[9];
    const float* w_o     = (const float*)d_in[10];
    float* out = (float*)d_out;

    float *p_qakva;
    __half *p_hid, *p_wqkv, *p_wqb, *p_wo, *p_wuk;
    __half *p_qaln, *p_q, *p_kattn, *p_kb, *p_vT, *p_of, *p_wuvT;
    cudaGetSymbolAddress((void**)&p_qakva, g_qakva);
    cudaGetSymbolAddress((void**)&p_hid,   g_hid);
    cudaGetSymbolAddress((void**)&p_wqkv,  g_wqkv);
    cudaGetSymbolAddress((void**)&p_wqb,   g_wqb);
    cudaGetSymbolAddress((void**)&p_wo,    g_wo);
    cudaGetSymbolAddress((void**)&p_wuk,   g_wuk);
    cudaGetSymbolAddress((void**)&p_qaln,  g_qaln);
    cudaGetSymbolAddress((void**)&p_q,     g_q);
    cudaGetSymbolAddress((void**)&p_kattn, g_kattn);
    cudaGetSymbolAddress((void**)&p_kb,    g_kb);
    cudaGetSymbolAddress((void**)&p_vT,    g_vT);
    cudaGetSymbolAddress((void**)&p_of,    g_outfl);
    cudaGetSymbolAddress((void**)&p_wuvT,  g_wuvT);

    const int SMEM = 4 * TILE_W * 4;
    cudaFuncSetAttribute(mma_gemm, cudaFuncAttributeMaxDynamicSharedMemorySize, SMEM);
    cudaFuncSetAttribute(flash_attn, cudaFuncAttributeMaxDynamicSharedMemorySize, SMEM_FLASH);

    auto grid = [](int M, int N, int z) {
        return dim3((N + BN - 1) / BN, (M + BM - 1) / BM, z);
    };
    const int T = 256;

    // side stream + fork/join events (created per call; capturable pattern)
    cudaStream_t sB;
    cudaStreamCreateWithFlags(&sB, cudaStreamNonBlocking);
    cudaEvent_t evFork, evJoin;
    cudaEventCreateWithFlags(&evFork, cudaEventDisableTiming);
    cudaEventCreateWithFlags(&evJoin, cudaEventDisableTiming);

    // ---- convert external inputs to fp16 ----
    cvt_all<<<1184, 256>>>(hidden, w_qa, w_kva, w_qb, w_o, W_UK_T);

    // T2) W_UV(f32) -> wuvT(h) [h][128][512]
    transpose_f32h<<<dim3(4, 16, NH), dim3(32, 8)>>>(
        W_UV, (long long)KVLR * VD, VD, p_wuvT, (long long)VD * KVLR, KVLR);

    // 1+2) qakva(f32) = hid @ [wqa|wkva]^T   [2048,2112] K=2048  (one wave)
    mma_gemm<<<grid(MBS, NQK, 1), T, SMEM>>>(
        p_hid, Hd, 0,1,0,1,  p_wqkv, Hd, 0,1,0,1,  p_qakva, NQK, 0,1,0,1,
        MBS, NQK, Hd, 0, 1.f);

    // 3) LN(qa) -> qaln(h)
    ln_rows_v<3><<<MBS, 128>>>(p_qakva, NQK, qalnw, p_qaln, QLR);

    // 4+5) LN(kv_c) -> kattn ; rope(k_pe)*SCALE -> Kb pe slots
    ln_kv_rope<<<MBS, 128>>>(p_qakva, kvalnw, cosb, sinb);

    // ---- fork: V' and K' on side stream, q-path on main ----
    cudaEventRecord(evFork, 0);
    cudaStreamWaitEvent(sB, evFork, 0);

    // V') vT[b,h] = wuvT[h] @ kv_c[b]^T   M=128, N=1024, K=512
    mma_gemm<<<grid(VD, Sb, Bb * NH), T, SMEM, sB>>>(
        p_wuvT, KVLR, 0,1, (long long)VD * KVLR, NH,
        p_kattn, DATT, (long long)Sb * DATT, NH, 0, 1,
        p_vT, Sb, (long long)VD * Sb, 1, 0, 1,
        VD, Sb, KVLR, 1, 1.f);

    // K') Kb[b,h][:,0:128] = (kv_c[b] @ wuk[h]^T) * SCALE   M=1024, N=128, K=512
    mma_gemm<<<grid(Sb, NOPE, Bb * NH), T, SMEM, sB>>>(
        p_kattn, DATT, (long long)Sb * DATT, NH, 0, 1,
        p_wuk, KVLR, 0,1, (long long)NOPE * KVLR, NH,
        p_kb, QKD, (long long)Sb * QKD, 1, 0, 1,
        Sb, NOPE, KVLR, 1, SCALE);

    cudaEventRecord(evJoin, sB);

    // 6) q(h) = qaln @ wqb^T   [2048,3072] K=1536   (main stream, overlaps V'/K')
    mma_gemm<<<grid(MBS, NH * QKD, 1), T, SMEM>>>(
        p_qaln, QLR, 0,1,0,1,  p_wqb, QLR, 0,1,0,1,  p_q, NH * QKD, 0,1,0,1,
        MBS, NH * QKD, QLR, 1, 1.f);

    // 7) rope(q_pe) in place
    rope_q<<<MBS * NH, 64>>>(cosb, sinb);

    // ---- join ----
    cudaStreamWaitEvent(0, evJoin, 0);

    // 9-11) fused flash attention -> outfl(h)
    flash_attn<<<dim3(8, Bb * NH), 256, SMEM_FLASH>>>(p_q, p_kb, p_vT, p_of);

    // 13) out(f32) = outfl @ wo^T  [2048,2048] K=2048
    mma_gemm<<<grid(MBS, Hd, 1), T, SMEM>>>(
        p_of, NH * VD, 0,1,0,1,  p_wo, NH * VD, 0,1,0,1,  out, Hd, 0,1,0,1,
        MBS, Hd, NH * VD, 0, 1.f);
}

// round 15
// speedup vs baseline: 4.6946x; 1.0639x over previous
#include <cuda_runtime.h>
#include <cuda_fp16.h>
#include <math.h>
#include <stdint.h>

// ---------------- problem constants ----------------
#define Bb 2
#define Sb 1024
#define Hd 2048
#define NH 16
#define NOPE 128
#define ROPE 64
#define VD 128
#define QKD 192
#define QLR 1536
#define KVLR 512
#define DATT 576
#define MBS (Bb*Sb)
#define NQK (QLR + DATT)               // 2112 combined qa|kva width
#define SCALE 0.07216878364870323f    // 1/sqrt(192)

// ---------------- scratch ----------------
__device__ float  g_qakva [MBS * NQK];             // [2048][2112] = qa | kva
__device__ __half g_hid   [MBS * Hd];
__device__ __half g_wqkv  [NQK * Hd];              // wqa rows 0:1536 | wkva rows 1536:2112
__device__ __half g_wqb   [NH * QKD * QLR];
__device__ __half g_wo    [Hd * NH * VD];
__device__ __half g_wuk   [NH * NOPE * KVLR];      // W_UK_T f16 [h][128][512]
__device__ __half g_qaln  [MBS * QLR];
__device__ __half g_q     [MBS * NH * QKD];        // rope applied in place
__device__ __half g_kattn [MBS * DATT];            // LN(kv_c) (cols 0:512)
__device__ __half g_kb    [(size_t)Bb*NH*Sb*QKD];  // absorbed keys, scaled
__device__ __half g_vT    [(size_t)Bb*NH*VD*Sb];   // V'^T per (b,h): [128][1024]
__device__ __half g_outfl [MBS * NH * VD];
__device__ __half g_wuvT  [NH * VD * KVLR];

// ---------------- helpers ----------------
__device__ __forceinline__ uint32_t su32(const void* p) {
    uint32_t a;
    asm("{ .reg .u64 t; cvta.to.shared.u64 t, %1; cvt.u32.u64 %0, t; }" : "=r"(a) : "l"(p));
    return a;
}
__device__ __forceinline__ uint32_t h2u(__half2 h) {
    union { __half2 h; uint32_t u; } c;
    c.h = h;
    return c.u;
}
__device__ __forceinline__ void mma_f16(float c[4], const uint32_t a[4], const uint32_t b[2]) {
    asm volatile(
        "mma.sync.aligned.m16n8k16.row.col.f32.f16.f16.f32 "
        "{%0,%1,%2,%3},{%4,%5,%6,%7},{%8,%9},{%0,%1,%2,%3};"
        : "+f"(c[0]), "+f"(c[1]), "+f"(c[2]), "+f"(c[3])
        : "r"(a[0]), "r"(a[1]), "r"(a[2]), "r"(a[3]), "r"(b[0]), "r"(b[1]));
}
#define LDSM_X4(r0, r1, r2, r3, addr) \
    asm volatile("ldmatrix.sync.aligned.m8n8.x4.shared.b16 {%0,%1,%2,%3}, [%4];" \
                 : "=r"(r0), "=r"(r1), "=r"(r2), "=r"(r3) : "r"(addr))
#define CP_ASYNC16(dst, src, sz) \
    asm volatile("cp.async.cg.shared.global [%0], [%1], 16, %2;" \
                 :: "r"(dst), "l"(src), "r"(sz) : "memory")
#define CP_COMMIT() asm volatile("cp.async.commit_group;" ::: "memory")
#define CP_WAIT(n)  asm volatile("cp.async.wait_group %0;" :: "n"(n) : "memory")

// ---------------- fp16 mma GEMM: 128x128 block, 8 warps (64x32 warp tile) ----
#define BM 128
#define BN 128
#define BKK 64
#define WSH 36
#define TILE_W (BM * WSH)

__global__ void __launch_bounds__(256, 2)
mma_gemm(const __half* __restrict__ A, int lda, long long sAd, int dA, long long sAm, int mA,
         const __half* __restrict__ B, int ldb, long long sBd, int dB, long long sBm, int mB,
         void*         __restrict__ Cv, int ldc, long long sCd, int dC, long long sCm, int mC,
         int M, int N, int K, int outHalf, float cscale)
{
    const int mBase = blockIdx.y * BM;
    const int nBase = blockIdx.x * BN;

    extern __shared__ uint32_t smw[];
    const uint32_t sAbase = su32(smw);
    const uint32_t sBbase = sAbase + 2u * TILE_W * 4u;

    const int z = blockIdx.z;
    const __half* Ab = A + (size_t)(z / dA) * sAd + (size_t)(z % mA) * sAm;
    const __half* Bp = B + (size_t)(z / dB) * sBd + (size_t)(z % mB) * sBm;
    const size_t  cOff = (size_t)(z / dC) * sCd + (size_t)(z % mC) * sCm;

    const int tid  = threadIdx.x;
    const int lane = tid & 31;
    const int warp = tid >> 5;
    const int wm   = warp & 1;
    const int wn   = warp >> 1;
    const int g    = lane >> 2;
    const int tig  = lane & 3;

    uint32_t aAddr[4];
#pragma unroll
    for (int ii = 0; ii < 4; ii++)
        aAddr[ii] = sAbase +
            (uint32_t)(((wm * 64 + ii * 16 + (lane & 15)) * WSH + ((lane >> 4) << 2)) * 4);
    uint32_t bAddr[2];
#pragma unroll
    for (int q = 0; q < 2; q++)
        bAddr[q] = sBbase +
            (uint32_t)(((wn * 32 + q * 16 + (lane & 7) + ((lane >> 4) << 3)) * WSH
                        + (((lane >> 3) & 1) << 2)) * 4);

    float acc[4][4][4];
#pragma unroll
    for (int i = 0; i < 4; i++)
#pragma unroll
        for (int j = 0; j < 4; j++)
#pragma unroll
            for (int r = 0; r < 4; r++) acc[i][j][r] = 0.f;

    const int nc = K / BKK;

    auto copy_chunk = [&](int ci, int p) {
        const int k0 = ci * BKK;
        const uint32_t aD = sAbase + (uint32_t)p * TILE_W * 4u;
        const uint32_t bD = sBbase + (uint32_t)p * TILE_W * 4u;
#pragma unroll
        for (int q = 0; q < 4; q++) {
            int slot = tid + q * 256;
            int row  = slot >> 3;
            int c8   = (slot & 7) << 3;
            uint32_t soff = (uint32_t)(row * (WSH * 4) + c8 * 2);
            int gm = mBase + row;
            const __half* asrc = (gm < M) ? (Ab + (size_t)gm * lda + k0 + c8) : Ab;
            CP_ASYNC16(aD + soff, asrc, (gm < M) ? 16 : 0);
            int gn = nBase + row;
            const __half* bsrc = (gn < N) ? (Bp + (size_t)gn * ldb + k0 + c8) : Bp;
            CP_ASYNC16(bD + soff, bsrc, (gn < N) ? 16 : 0);
        }
        CP_COMMIT();
    };

    copy_chunk(0, 0);

    for (int i = 0; i < nc; i++) {
        const int p = i & 1;
        if (i + 1 < nc) { copy_chunk(i + 1, p ^ 1); CP_WAIT(1); }
        else            { CP_WAIT(0); }
        __syncthreads();

        const uint32_t pOff = (uint32_t)p * TILE_W * 4u;
#pragma unroll
        for (int ks = 0; ks < 4; ks++) {
            const uint32_t kOff = pOff + (uint32_t)ks * 32u;
            uint32_t a[4][4], b[4][2];
#pragma unroll
            for (int ii = 0; ii < 4; ii++)
                LDSM_X4(a[ii][0], a[ii][1], a[ii][2], a[ii][3], aAddr[ii] + kOff);
            LDSM_X4(b[0][0], b[0][1], b[1][0], b[1][1], bAddr[0] + kOff);
            LDSM_X4(b[2][0], b[2][1], b[3][0], b[3][1], bAddr[1] + kOff);
#pragma unroll
            for (int ii = 0; ii < 4; ii++)
#pragma unroll
                for (int jj = 0; jj < 4; jj++)
                    mma_f16(acc[ii][jj], a[ii], b[jj]);
        }
        __syncthreads();
    }

    if (outHalf) {
        __half* Ch = (__half*)Cv + cOff;
#pragma unroll
        for (int i = 0; i < 4; i++) {
            int r0 = mBase + (wm << 6) + (i << 4) + g;
            if (r0 >= M) continue;
#pragma unroll
            for (int j = 0; j < 4; j++) {
                int col = nBase + (wn << 5) + (j << 3) + (tig << 1);
                if (col < N) {
                    *(__half2*)(Ch + (size_t)r0 * ldc + col) =
                        __floats2half2_rn(acc[i][j][0] * cscale, acc[i][j][1] * cscale);
                    *(__half2*)(Ch + (size_t)(r0 + 8) * ldc + col) =
                        __floats2half2_rn(acc[i][j][2] * cscale, acc[i][j][3] * cscale);
                }
            }
        }
    } else {
        float* Cf = (float*)Cv + cOff;
#pragma unroll
        for (int i = 0; i < 4; i++) {
            int r0 = mBase + (wm << 6) + (i << 4) + g;
            if (r0 >= M) continue;
#pragma unroll
            for (int j = 0; j < 4; j++) {
                int col = nBase + (wn << 5) + (j << 3) + (tig << 1);
                if (col < N) {
                    *(float2*)(Cf + (size_t)r0 * ldc + col)       = make_float2(acc[i][j][0], acc[i][j][1]);
                    *(float2*)(Cf + (size_t)(r0 + 8) * ldc + col) = make_float2(acc[i][j][2], acc[i][j][3]);
                }
            }
        }
    }
}

// ---------------- flash attention (1D grid, global LPT order) ----------------
#define QS_STRIDE 100
#define VS_STRIDE 68
#define QS_B (128 * QS_STRIDE * 4)
#define VS_B (128 * VS_STRIDE * 4)
#define BUF_B (QS_B + VS_B)
#define SMEM_FLASH (QS_B + 2 * BUF_B)

__global__ void __launch_bounds__(256, 1)
flash_attn(const __half* __restrict__ Q, const __half* __restrict__ Kb,
           const __half* __restrict__ Vt, __half* __restrict__ Of)
{
    // global LPT: first 32 blocks are i=7 (heaviest), next 32 i=6, ...
    const int i = 7 - ((int)blockIdx.x >> 5);
    const int z = (int)blockIdx.x & 31;
    const int b = z >> 4, h = z & 15;

    extern __shared__ uint32_t smw[];
    const uint32_t sQ  = su32(smw);
    const uint32_t sB0 = sQ + QS_B;

    const int tid = threadIdx.x, lane = tid & 31, w = tid >> 5;
    const int g = lane >> 2, tig = lane & 3;

    const __half* Qg = Q  + (size_t)(b * Sb + i * 128) * (NH * QKD) + h * QKD;
    const __half* Kg = Kb + (size_t)z * Sb * QKD;
    const __half* Vg = Vt + (size_t)z * VD * Sb;

    const uint32_t aQbase = sQ + (uint32_t)(((w * 16 + (lane & 15)) * QS_STRIDE
                                             + ((lane >> 4) << 2)) * 4);
    const uint32_t bKoff = (uint32_t)((((lane & 7) + ((lane >> 4) << 3)) * QS_STRIDE
                                       + (((lane >> 3) & 1) << 2)) * 4);
    const uint32_t bVoff = (uint32_t)((((lane & 7) + ((lane >> 4) << 3)) * VS_STRIDE
                                       + (((lane >> 3) & 1) << 2)) * 4);

    auto load_K = [&](int j, uint32_t dst) {
        const __half* src = Kg + (size_t)j * 128 * QKD;
        for (int t = tid; t < 128 * 24; t += 256) {
            int row = t / 24, cc = t % 24;
            CP_ASYNC16(dst + (uint32_t)(row * QS_STRIDE + cc * 4) * 4,
                       src + (size_t)row * QKD + cc * 8, 16);
        }
    };
    auto load_V = [&](int j, uint32_t dst) {
        for (int t = tid; t < 128 * 16; t += 256) {
            int row = t / 16, cc = t % 16;
            CP_ASYNC16(dst + (uint32_t)(row * VS_STRIDE + cc * 4) * 4,
                       Vg + (size_t)row * Sb + j * 128 + cc * 8, 16);
        }
    };

    for (int t = tid; t < 128 * 24; t += 256) {
        int row = t / 24, cc = t % 24;
        CP_ASYNC16(sQ + (uint32_t)(row * QS_STRIDE + cc * 4) * 4,
                   Qg + (size_t)row * (NH * QKD) + cc * 8, 16);
    }
    load_K(0, sB0);
    load_V(0, sB0 + QS_B);
    CP_COMMIT();

    float m0 = -1e30f, m1 = -1e30f, l0 = 0.f, l1 = 0.f;
    float o[16][4];
#pragma unroll
    for (int nt = 0; nt < 16; nt++)
#pragma unroll
        for (int r = 0; r < 4; r++) o[nt][r] = 0.f;

    for (int j = 0; j <= i; j++) {
        const int p = j & 1;
        if (j < i) {
            const uint32_t nb = sB0 + (uint32_t)(p ^ 1) * BUF_B;
            load_K(j + 1, nb);
            load_V(j + 1, nb + QS_B);
            CP_COMMIT();
            CP_WAIT(1);
        } else {
            CP_WAIT(0);
        }
        __syncthreads();

        const uint32_t kbB = sB0 + (uint32_t)p * BUF_B;
        const uint32_t vbB = kbB + QS_B;

        float s[16][4];
#pragma unroll
        for (int nt = 0; nt < 16; nt++)
#pragma unroll
            for (int r = 0; r < 4; r++) s[nt][r] = 0.f;

#pragma unroll
        for (int ks = 0; ks < 12; ks++) {
            uint32_t a[4];
            LDSM_X4(a[0], a[1], a[2], a[3], aQbase + (uint32_t)ks * 32u);
#pragma unroll
            for (int t = 0; t < 8; t++) {
                uint32_t b0, b1, b2, b3;
                LDSM_X4(b0, b1, b2, b3,
                        kbB + (uint32_t)(t * 16 * QS_STRIDE * 4) + bKoff + (uint32_t)ks * 32u);
                uint32_t bb0[2] = {b0, b1}, bb1[2] = {b2, b3};
                mma_f16(s[2 * t],     a, bb0);
                mma_f16(s[2 * t + 1], a, bb1);
            }
        }

        if (j == i) {
            const int q0 = 16 * w + g, q1 = q0 + 8;
#pragma unroll
            for (int nt = 0; nt < 16; nt++) {
                int key = 8 * nt + 2 * tig;
                if (key     > q0) s[nt][0] = -1e30f;
                if (key + 1 > q0) s[nt][1] = -1e30f;
                if (key     > q1) s[nt][2] = -1e30f;
                if (key + 1 > q1) s[nt][3] = -1e30f;
            }
        }

        float rm0 = -1e30f, rm1 = -1e30f;
#pragma unroll
        for (int nt = 0; nt < 16; nt++) {
            rm0 = fmaxf(rm0, fmaxf(s[nt][0], s[nt][1]));
            rm1 = fmaxf(rm1, fmaxf(s[nt][2], s[nt][3]));
        }
        rm0 = fmaxf(rm0, __shfl_xor_sync(0xffffffffu, rm0, 1));
        rm0 = fmaxf(rm0, __shfl_xor_sync(0xffffffffu, rm0, 2));
        rm1 = fmaxf(rm1, __shfl_xor_sync(0xffffffffu, rm1, 1));
        rm1 = fmaxf(rm1, __shfl_xor_sync(0xffffffffu, rm1, 2));

        const float mn0 = fmaxf(m0, rm0), mn1 = fmaxf(m1, rm1);
        const float sc0 = __expf(m0 - mn0), sc1 = __expf(m1 - mn1);
        m0 = mn0; m1 = mn1;

        float ps0 = 0.f, ps1 = 0.f;
#pragma unroll
        for (int nt = 0; nt < 16; nt++) {
            s[nt][0] = __expf(s[nt][0] - m0);
            s[nt][1] = __expf(s[nt][1] - m0);
            s[nt][2] = __expf(s[nt][2] - m1);
            s[nt][3] = __expf(s[nt][3] - m1);
            ps0 += s[nt][0] + s[nt][1];
            ps1 += s[nt][2] + s[nt][3];
            o[nt][0] *= sc0; o[nt][1] *= sc0;
            o[nt][2] *= sc1; o[nt][3] *= sc1;
        }
        ps0 += __shfl_xor_sync(0xffffffffu, ps0, 1);
        ps0 += __shfl_xor_sync(0xffffffffu, ps0, 2);
        ps1 += __shfl_xor_sync(0xffffffffu, ps1, 1);
        ps1 += __shfl_xor_sync(0xffffffffu, ps1, 2);
        l0 = l0 * sc0 + ps0;
        l1 = l1 * sc1 + ps1;

#pragma unroll
        for (int kt = 0; kt < 8; kt++) {
            uint32_t a[4];
            a[0] = h2u(__floats2half2_rn(s[2 * kt][0],     s[2 * kt][1]));
            a[1] = h2u(__floats2half2_rn(s[2 * kt][2],     s[2 * kt][3]));
            a[2] = h2u(__floats2half2_rn(s[2 * kt + 1][0], s[2 * kt + 1][1]));
            a[3] = h2u(__floats2half2_rn(s[2 * kt + 1][2], s[2 * kt + 1][3]));
#pragma unroll
            for (int t = 0; t < 8; t++) {
                uint32_t b0, b1, b2, b3;
                LDSM_X4(b0, b1, b2, b3,
                        vbB + (uint32_t)(t * 16 * VS_STRIDE * 4) + bVoff + (uint32_t)kt * 32u);
                uint32_t bb0[2] = {b0, b1}, bb1[2] = {b2, b3};
                mma_f16(o[2 * t],     a, bb0);
                mma_f16(o[2 * t + 1], a, bb1);
            }
        }
        __syncthreads();
    }

    const float inv0 = 1.f / l0, inv1 = 1.f / l1;
    const size_t row0 = (size_t)(b * Sb + i * 128 + w * 16 + g);
    __half* out0 = Of + row0 * (NH * VD) + h * VD;
    __half* out1 = out0 + (size_t)8 * (NH * VD);
#pragma unroll
    for (int nt = 0; nt < 16; nt++) {
        int col = 8 * nt + 2 * tig;
        *(__half2*)(out0 + col) = __floats2half2_rn(o[nt][0] * inv0, o[nt][1] * inv0);
        *(__half2*)(out1 + col) = __floats2half2_rn(o[nt][2] * inv1, o[nt][3] * inv1);
    }
}

// ---------------- cvt main (hid, wqa, wkva -> g_hid, g_wqkv) -----------------
#define CM0 (MBS * Hd / 4)
#define CM1 (CM0 + QLR * Hd / 4)
#define CM2 (CM1 + DATT * Hd / 4)

__global__ void cvt_main(const float* __restrict__ s0, const float* __restrict__ s1,
                         const float* __restrict__ s2)
{
    __half *d;
    const float *s;
    int stride = gridDim.x * blockDim.x;
    for (int i = blockIdx.x * blockDim.x + threadIdx.x; i < CM2; i += stride) {
        int off;
        if (i < CM0)      { s = s0; off = i;       d = g_hid; }
        else if (i < CM1) { s = s1; off = i - CM0; d = g_wqkv; }
        else              { s = s2; off = i - CM1; d = g_wqkv + QLR * Hd; }
        float4 v = ((const float4*)s)[off];
        ((__half2*)d)[2 * off]     = __floats2half2_rn(v.x, v.y);
        ((__half2*)d)[2 * off + 1] = __floats2half2_rn(v.z, v.w);
    }
}

// ---------------- cvt rest (wqb, wo, wuk) -----------------
#define CR0 (NH * QKD * QLR / 4)
#define CR1 (CR0 + Hd * NH * VD / 4)
#define CR2 (CR1 + NH * NOPE * KVLR / 4)

__global__ void cvt_rest(const float* __restrict__ s0, const float* __restrict__ s1,
                         const float* __restrict__ s2)
{
    __half *d;
    const float *s;
    int stride = gridDim.x * blockDim.x;
    for (int i = blockIdx.x * blockDim.x + threadIdx.x; i < CR2; i += stride) {
        int off;
        if (i < CR0)      { s = s0; off = i;       d = g_wqb; }
        else if (i < CR1) { s = s1; off = i - CR0; d = g_wo; }
        else              { s = s2; off = i - CR1; d = g_wuk; }
        float4 v = ((const float4*)s)[off];
        ((__half2*)d)[2 * off]     = __floats2half2_rn(v.x, v.y);
        ((__half2*)d)[2 * off + 1] = __floats2half2_rn(v.z, v.w);
    }
}

// ---------------- transpose f32 -> f16 ----------------
__global__ void transpose_f32h(const float* __restrict__ in, long long sIn, int ldin,
                               __half* __restrict__ out, long long sOut, int ldout)
{
    __shared__ float t[32][33];
    const float* ib = in + (size_t)blockIdx.z * sIn;
    __half* ob = out + (size_t)blockIdx.z * sOut;
    int x0 = blockIdx.x * 32, y0 = blockIdx.y * 32;
    int tx = threadIdx.x, ty = threadIdx.y;
#pragma unroll
    for (int j = 0; j < 32; j += 8)
        t[ty + j][tx] = ib[(size_t)(y0 + ty + j) * ldin + x0 + tx];
    __syncthreads();
#pragma unroll
    for (int j = 0; j < 32; j += 8)
        ob[(size_t)(x0 + ty + j) * ldout + y0 + tx] = __float2half_rn(t[tx][ty + j]);
}

// ---------------- fused: LN(qa) + LN(kv_c) + rope(k_pe)*SCALE ----------------
__global__ void __launch_bounds__(128)
ln_all(const float* __restrict__ in /* g_qakva */,
       const float* __restrict__ wq, const float* __restrict__ wkv,
       const float* __restrict__ cosb, const float* __restrict__ sinb)
{
    const int r = blockIdx.x, tid = threadIdx.x;
    const int lane = tid & 31, warp = tid >> 5;
    __shared__ float sm4[4];
    __shared__ float stats[2];

    // ----- q-path LN over cols [0,1536) -----
    const float4* xq = (const float4*)(in + (size_t)r * NQK);
    float4 v[3];
    float s = 0.f;
#pragma unroll
    for (int q = 0; q < 3; q++) {
        v[q] = xq[tid + q * 128];
        s += v[q].x + v[q].y + v[q].z + v[q].w;
    }
#pragma unroll
    for (int o = 16; o > 0; o >>= 1) s += __shfl_xor_sync(0xffffffffu, s, o);
    if (lane == 0) sm4[warp] = s;
    __syncthreads();
    if (tid == 0) stats[0] = (sm4[0] + sm4[1] + sm4[2] + sm4[3]) / QLR;
    __syncthreads();
    float mean = stats[0];

    float vv = 0.f;
#pragma unroll
    for (int q = 0; q < 3; q++) {
        float dx = v[q].x - mean, dy = v[q].y - mean;
        float dz = v[q].z - mean, dw = v[q].w - mean;
        vv += dx * dx + dy * dy + dz * dz + dw * dw;
    }
#pragma unroll
    for (int o = 16; o > 0; o >>= 1) vv += __shfl_xor_sync(0xffffffffu, vv, o);
    if (lane == 0) sm4[warp] = vv;
    __syncthreads();
    if (tid == 0) stats[1] = rsqrtf((sm4[0] + sm4[1] + sm4[2] + sm4[3]) / QLR + 1e-5f);
    __syncthreads();
    float rstd = stats[1];

    __half2* yq = (__half2*)(g_qaln + (size_t)r * QLR);
#pragma unroll
    for (int q = 0; q < 3; q++) {
        float4 ww = ((const float4*)wq)[tid + q * 128];
        int c = tid + q * 128;
        yq[2 * c]     = __floats2half2_rn((v[q].x - mean) * rstd * ww.x,
                                          (v[q].y - mean) * rstd * ww.y);
        yq[2 * c + 1] = __floats2half2_rn((v[q].z - mean) * rstd * ww.z,
                                          (v[q].w - mean) * rstd * ww.w);
    }
    __syncthreads();

    // ----- kv-path LN over cols [1536,2048) -----
    float4 vk = ((const float4*)(in + (size_t)r * NQK + QLR))[tid];
    s = vk.x + vk.y + vk.z + vk.w;
#pragma unroll
    for (int o = 16; o > 0; o >>= 1) s += __shfl_xor_sync(0xffffffffu, s, o);
    if (lane == 0) sm4[warp] = s;
    __syncthreads();
    if (tid == 0) stats[0] = (sm4[0] + sm4[1] + sm4[2] + sm4[3]) / KVLR;
    __syncthreads();
    mean = stats[0];

    float dx = vk.x - mean, dy = vk.y - mean, dz = vk.z - mean, dw = vk.w - mean;
    vv = dx * dx + dy * dy + dz * dz + dw * dw;
#pragma unroll
    for (int o = 16; o > 0; o >>= 1) vv += __shfl_xor_sync(0xffffffffu, vv, o);
    if (lane == 0) sm4[warp] = vv;
    __syncthreads();
    if (tid == 0) stats[1] = rsqrtf((sm4[0] + sm4[1] + sm4[2] + sm4[3]) / KVLR + 1e-5f);
    __syncthreads();
    rstd = stats[1];

    __half2* yk = (__half2*)(g_kattn + (size_t)r * DATT);
    float4 wwk = ((const float4*)wkv)[tid];
    yk[2 * tid]     = __floats2half2_rn((vk.x - mean) * rstd * wwk.x,
                                        (vk.y - mean) * rstd * wwk.y);
    yk[2 * tid + 1] = __floats2half2_rn((vk.z - mean) * rstd * wwk.z,
                                        (vk.w - mean) * rstd * wwk.w);

    // ----- rope(k_pe)*SCALE -> all 16 head slots of Kb (threads 0..63) -----
    if (tid < ROPE) {
        const int i = tid;
        const int b = r >> 10, srow = r & (Sb - 1);
        const float* pe = in + (size_t)r * NQK + QLR + KVLR;
        float xx = pe[i];
        float other = pe[(i < 32) ? (i + 32) : (i - 32)];
        float rot = (i < 32) ? -other : other;
        __half hv = __float2half_rn((xx * cosb[r * ROPE + i] + rot * sinb[r * ROPE + i]) * SCALE);
#pragma unroll
        for (int h = 0; h < NH; h++)
            g_kb[(((size_t)(b * NH + h) * Sb) + srow) * QKD + NOPE + i] = hv;
    }
}

// ---------------- RoPE q_pe: in-place on g_q ----------------
__global__ void rope_q(const float* __restrict__ cosb, const float* __restrict__ sinb)
{
    int bs = blockIdx.x >> 4;
    int h  = blockIdx.x & 15;
    int i  = threadIdx.x;
    __half* base = g_q + (size_t)bs * (NH * QKD) + h * QKD + NOPE;
    float x = __half2float(base[i]);
    float other = __half2float(base[(i < 32) ? (i + 32) : (i - 32)]);
    __syncthreads();
    float rot = (i < 32) ? -other : other;
    base[i] = __float2half_rn(x * cosb[bs * ROPE + i] + rot * sinb[bs * ROPE + i]);
}

// ---------------- launch ----------------
extern "C" void kernel_launch(void* const* d_in, const int* in_sizes, int n_in,
                              void* d_out, int out_size)
{
    const float* hidden  = (const float*)d_in[0];
    const float* cosb    = (const float*)d_in[1];
    const float* sinb    = (const float*)d_in[2];
    const float* w_qa    = (const float*)d_in[3];
    const float* qalnw   = (const float*)d_in[4];
    const float* w_qb    = (const float*)d_in[5];
    const float* w_kva   = (const float*)d_in[6];
    const float* kvalnw  = (const float*)d_in[7];
    const float* W_UK_T  = (const float*)d_in[8];
    const float* W_UV    = (const float*)d_in[9];
    const float* w_o     = (const float*)d_in[10];
    float* out = (float*)d_out;

    float *p_qakva;
    __half *p_hid, *p_wqkv, *p_wqb, *p_wo, *p_wuk;
    __half *p_qaln, *p_q, *p_kattn, *p_kb, *p_vT, *p_of, *p_wuvT;
    cudaGetSymbolAddress((void**)&p_qakva, g_qakva);
    cudaGetSymbolAddress((void**)&p_hid,   g_hid);
    cudaGetSymbolAddress((void**)&p_wqkv,  g_wqkv);
    cudaGetSymbolAddress((void**)&p_wqb,   g_wqb);
    cudaGetSymbolAddress((void**)&p_wo,    g_wo);
    cudaGetSymbolAddress((void**)&p_wuk,   g_wuk);
    cudaGetSymbolAddress((void**)&p_qaln,  g_qaln);
    cudaGetSymbolAddress((void**)&p_q,     g_q);
    cudaGetSymbolAddress((void**)&p_kattn, g_kattn);
    cudaGetSymbolAddress((void**)&p_kb,    g_kb);
    cudaGetSymbolAddress((void**)&p_vT,    g_vT);
    cudaGetSymbolAddress((void**)&p_of,    g_outfl);
    cudaGetSymbolAddress((void**)&p_wuvT,  g_wuvT);

    const int SMEM = 4 * TILE_W * 4;
    cudaFuncSetAttribute(mma_gemm, cudaFuncAttributeMaxDynamicSharedMemorySize, SMEM);
    cudaFuncSetAttribute(flash_attn, cudaFuncAttributeMaxDynamicSharedMemorySize, SMEM_FLASH);

    auto grid = [](int M, int N, int z) {
        return dim3((N + BN - 1) / BN, (M + BM - 1) / BM, z);
    };
    const int T = 256;

    cudaStream_t sB;
    cudaStreamCreateWithFlags(&sB, cudaStreamNonBlocking);
    cudaEvent_t evFork, evSideReady, evKV, evJoin;
    cudaEventCreateWithFlags(&evFork, cudaEventDisableTiming);
    cudaEventCreateWithFlags(&evSideReady, cudaEventDisableTiming);
    cudaEventCreateWithFlags(&evKV, cudaEventDisableTiming);
    cudaEventCreateWithFlags(&evJoin, cudaEventDisableTiming);

    // fork side stream at entry (keeps capture graph connected from stream 0)
    cudaEventRecord(evFork, 0);
    cudaStreamWaitEvent(sB, evFork, 0);

    // ---- side: convert wqb/wo/wuk + transpose W_UV (overlaps GEMM1) ----
    cvt_rest<<<1024, 256, 0, sB>>>(w_qb, w_o, W_UK_T);
    transpose_f32h<<<dim3(4, 16, NH), dim3(32, 8), 0, sB>>>(
        W_UV, (long long)KVLR * VD, VD, p_wuvT, (long long)VD * KVLR, KVLR);
    cudaEventRecord(evSideReady, sB);

    // ---- main: convert hid + wqa|wkva ----
    cvt_main<<<1024, 256>>>(hidden, w_qa, w_kva);

    // 1+2) qakva(f32) = hid @ [wqa|wkva]^T   [2048,2112] K=2048 (one wave)
    mma_gemm<<<grid(MBS, NQK, 1), T, SMEM>>>(
        p_hid, Hd, 0,1,0,1,  p_wqkv, Hd, 0,1,0,1,  p_qakva, NQK, 0,1,0,1,
        MBS, NQK, Hd, 0, 1.f);

    // 3+4+5) LN(qa), LN(kv_c), rope(k_pe) in one kernel
    ln_all<<<MBS, 128>>>(p_qakva, qalnw, kvalnw, cosb, sinb);
    cudaEventRecord(evKV, 0);

    // ---- side: V' and K' (need kv_c + side weights) ----
    cudaStreamWaitEvent(sB, evKV, 0);
    mma_gemm<<<grid(VD, Sb, Bb * NH), T, SMEM, sB>>>(
        p_wuvT, KVLR, 0,1, (long long)VD * KVLR, NH,
        p_kattn, DATT, (long long)Sb * DATT, NH, 0, 1,
        p_vT, Sb, (long long)VD * Sb, 1, 0, 1,
        VD, Sb, KVLR, 1, 1.f);
    mma_gemm<<<grid(Sb, NOPE, Bb * NH), T, SMEM, sB>>>(
        p_kattn, DATT, (long long)Sb * DATT, NH, 0, 1,
        p_wuk, KVLR, 0,1, (long long)NOPE * KVLR, NH,
        p_kb, QKD, (long long)Sb * QKD, 1, 0, 1,
        Sb, NOPE, KVLR, 1, SCALE);
    cudaEventRecord(evJoin, sB);

    // ---- main: q projection (needs wqb from side cvt_rest) ----
    cudaStreamWaitEvent(0, evSideReady, 0);
    mma_gemm<<<grid(MBS, NH * QKD, 1), T, SMEM>>>(
        p_qaln, QLR, 0,1,0,1,  p_wqb, QLR, 0,1,0,1,  p_q, NH * QKD, 0,1,0,1,
        MBS, NH * QKD, QLR, 1, 1.f);
    rope_q<<<MBS * NH, 64>>>(cosb, sinb);

    // ---- join ----
    cudaStreamWaitEvent(0, evJoin, 0);

    // 9-11) fused flash attention -> outfl(h), global LPT order
    flash_attn<<<256, 256, SMEM_FLASH>>>(p_q, p_kb, p_vT, p_of);

    // 13) out(f32) = outfl @ wo^T  [2048,2048] K=2048
    mma_gemm<<<grid(MBS, Hd, 1), T, SMEM>>>(
        p_of, NH * VD, 0,1,0,1,  p_wo, NH * VD, 0,1,0,1,  out, Hd, 0,1,0,1,
        MBS, Hd, NH * VD, 0, 1.f);
}

// round 16
// speedup vs baseline: 4.7336x; 1.0083x over previous
#include <cuda_runtime.h>
#include <cuda_fp16.h>
#include <math.h>
#include <stdint.h>

// ---------------- problem constants ----------------
#define Bb 2
#define Sb 1024
#define Hd 2048
#define NH 16
#define NOPE 128
#define ROPE 64
#define VD 128
#define QKD 192
#define QLR 1536
#define KVLR 512
#define DATT 576
#define MBS (Bb*Sb)
#define NQK (QLR + DATT)               // 2112 combined qa|kva width
#define SCALE 0.07216878364870323f    // 1/sqrt(192)

// ---------------- scratch ----------------
__device__ float  g_qakva [MBS * NQK];             // [2048][2112] = qa | kva
__device__ __half g_hid   [MBS * Hd];
__device__ __half g_wqkv  [NQK * Hd];              // wqa rows 0:1536 | wkva rows 1536:2112
__device__ __half g_wqb   [NH * QKD * QLR];
__device__ __half g_wo    [Hd * NH * VD];
__device__ __half g_wuk   [NH * NOPE * KVLR];      // W_UK_T f16 [h][128][512]
__device__ __half g_qaln  [MBS * QLR];
__device__ __half g_q     [MBS * NH * QKD];        // rope applied in place
__device__ __half g_kattn [MBS * DATT];            // LN(kv_c) (cols 0:512)
__device__ __half g_kb    [(size_t)Bb*NH*Sb*QKD];  // absorbed keys, scaled
__device__ __half g_vT    [(size_t)Bb*NH*VD*Sb];   // V'^T per (b,h): [128][1024]
__device__ __half g_outfl [MBS * NH * VD];
__device__ __half g_wuvT  [NH * VD * KVLR];

// ---------------- helpers ----------------
__device__ __forceinline__ uint32_t su32(const void* p) {
    uint32_t a;
    asm("{ .reg .u64 t; cvta.to.shared.u64 t, %1; cvt.u32.u64 %0, t; }" : "=r"(a) : "l"(p));
    return a;
}
__device__ __forceinline__ uint32_t h2u(__half2 h) {
    union { __half2 h; uint32_t u; } c;
    c.h = h;
    return c.u;
}
__device__ __forceinline__ void mma_f16(float c[4], const uint32_t a[4], const uint32_t b[2]) {
    asm volatile(
        "mma.sync.aligned.m16n8k16.row.col.f32.f16.f16.f32 "
        "{%0,%1,%2,%3},{%4,%5,%6,%7},{%8,%9},{%0,%1,%2,%3};"
        : "+f"(c[0]), "+f"(c[1]), "+f"(c[2]), "+f"(c[3])
        : "r"(a[0]), "r"(a[1]), "r"(a[2]), "r"(a[3]), "r"(b[0]), "r"(b[1]));
}
#define LDSM_X4(r0, r1, r2, r3, addr) \
    asm volatile("ldmatrix.sync.aligned.m8n8.x4.shared.b16 {%0,%1,%2,%3}, [%4];" \
                 : "=r"(r0), "=r"(r1), "=r"(r2), "=r"(r3) : "r"(addr))
#define CP_ASYNC16(dst, src, sz) \
    asm volatile("cp.async.cg.shared.global [%0], [%1], 16, %2;" \
                 :: "r"(dst), "l"(src), "r"(sz) : "memory")
#define CP_COMMIT() asm volatile("cp.async.commit_group;" ::: "memory")
#define CP_WAIT(n)  asm volatile("cp.async.wait_group %0;" :: "n"(n) : "memory")

// ---------------- fp16 mma GEMM: 128x128 block, 3-stage pipeline ------------
#define BM 128
#define BN 128
#define BKK 64
#define WSH 36
#define TILE_W (BM * WSH)
#define SSTRIDE (2u * TILE_W * 4u)      // bytes per stage (A tile + B tile)
#define NST 3
#define SMEM_GEMM (NST * 2 * TILE_W * 4)  // 110592

__global__ void __launch_bounds__(256, 2)
mma_gemm(const __half* __restrict__ A, int lda, long long sAd, int dA, long long sAm, int mA,
         const __half* __restrict__ B, int ldb, long long sBd, int dB, long long sBm, int mB,
         void*         __restrict__ Cv, int ldc, long long sCd, int dC, long long sCm, int mC,
         int M, int N, int K, int outHalf, float cscale)
{
    const int mBase = blockIdx.y * BM;
    const int nBase = blockIdx.x * BN;

    extern __shared__ uint32_t smw[];
    const uint32_t sBase = su32(smw);

    const int z = blockIdx.z;
    const __half* Ab = A + (size_t)(z / dA) * sAd + (size_t)(z % mA) * sAm;
    const __half* Bp = B + (size_t)(z / dB) * sBd + (size_t)(z % mB) * sBm;
    const size_t  cOff = (size_t)(z / dC) * sCd + (size_t)(z % mC) * sCm;

    const int tid  = threadIdx.x;
    const int lane = tid & 31;
    const int warp = tid >> 5;
    const int wm   = warp & 1;
    const int wn   = warp >> 1;
    const int g    = lane >> 2;
    const int tig  = lane & 3;

    // stage-relative ldmatrix base offsets (bytes): A at 0, B at TILE_W*4
    uint32_t aAddr[4];
#pragma unroll
    for (int ii = 0; ii < 4; ii++)
        aAddr[ii] = sBase +
            (uint32_t)(((wm * 64 + ii * 16 + (lane & 15)) * WSH + ((lane >> 4) << 2)) * 4);
    uint32_t bAddr[2];
#pragma unroll
    for (int q = 0; q < 2; q++)
        bAddr[q] = sBase + TILE_W * 4u +
            (uint32_t)(((wn * 32 + q * 16 + (lane & 7) + ((lane >> 4) << 3)) * WSH
                        + (((lane >> 3) & 1) << 2)) * 4);

    float acc[4][4][4];
#pragma unroll
    for (int i = 0; i < 4; i++)
#pragma unroll
        for (int j = 0; j < 4; j++)
#pragma unroll
            for (int r = 0; r < 4; r++) acc[i][j][r] = 0.f;

    const int nc = K / BKK;

    auto copy_chunk = [&](int ci, int st) {
        const int k0 = ci * BKK;
        const uint32_t aD = sBase + (uint32_t)st * SSTRIDE;
        const uint32_t bD = aD + TILE_W * 4u;
#pragma unroll
        for (int q = 0; q < 4; q++) {
            int slot = tid + q * 256;
            int row  = slot >> 3;
            int c8   = (slot & 7) << 3;
            uint32_t soff = (uint32_t)(row * (WSH * 4) + c8 * 2);
            int gm = mBase + row;
            const __half* asrc = (gm < M) ? (Ab + (size_t)gm * lda + k0 + c8) : Ab;
            CP_ASYNC16(aD + soff, asrc, (gm < M) ? 16 : 0);
            int gn = nBase + row;
            const __half* bsrc = (gn < N) ? (Bp + (size_t)gn * ldb + k0 + c8) : Bp;
            CP_ASYNC16(bD + soff, bsrc, (gn < N) ? 16 : 0);
        }
        CP_COMMIT();
    };

    // prologue: stages 0 and 1
    copy_chunk(0, 0);
    if (nc > 1) copy_chunk(1, 1); else CP_COMMIT();

    int st = 0;
    for (int i = 0; i < nc; i++) {
        CP_WAIT(1);              // chunk i complete (only chunk i+1 may be pending)
        __syncthreads();         // visibility of chunk i + WAR barrier for prefetch below

        if (i + 2 < nc) copy_chunk(i + 2, (st + 2 >= NST) ? st + 2 - NST : st + 2);
        else            CP_COMMIT();

        const uint32_t stOff = (uint32_t)st * SSTRIDE;
#pragma unroll
        for (int ks = 0; ks < 4; ks++) {
            const uint32_t kOff = stOff + (uint32_t)ks * 32u;
            uint32_t a[4][4], b[4][2];
#pragma unroll
            for (int ii = 0; ii < 4; ii++)
                LDSM_X4(a[ii][0], a[ii][1], a[ii][2], a[ii][3], aAddr[ii] + kOff);
            LDSM_X4(b[0][0], b[0][1], b[1][0], b[1][1], bAddr[0] + kOff);
            LDSM_X4(b[2][0], b[2][1], b[3][0], b[3][1], bAddr[1] + kOff);
#pragma unroll
            for (int ii = 0; ii < 4; ii++)
#pragma unroll
                for (int jj = 0; jj < 4; jj++)
                    mma_f16(acc[ii][jj], a[ii], b[jj]);
        }
        st = (st + 1 >= NST) ? 0 : st + 1;
    }

    if (outHalf) {
        __half* Ch = (__half*)Cv + cOff;
#pragma unroll
        for (int i = 0; i < 4; i++) {
            int r0 = mBase + (wm << 6) + (i << 4) + g;
            if (r0 >= M) continue;
#pragma unroll
            for (int j = 0; j < 4; j++) {
                int col = nBase + (wn << 5) + (j << 3) + (tig << 1);
                if (col < N) {
                    *(__half2*)(Ch + (size_t)r0 * ldc + col) =
                        __floats2half2_rn(acc[i][j][0] * cscale, acc[i][j][1] * cscale);
                    *(__half2*)(Ch + (size_t)(r0 + 8) * ldc + col) =
                        __floats2half2_rn(acc[i][j][2] * cscale, acc[i][j][3] * cscale);
                }
            }
        }
    } else {
        float* Cf = (float*)Cv + cOff;
#pragma unroll
        for (int i = 0; i < 4; i++) {
            int r0 = mBase + (wm << 6) + (i << 4) + g;
            if (r0 >= M) continue;
#pragma unroll
            for (int j = 0; j < 4; j++) {
                int col = nBase + (wn << 5) + (j << 3) + (tig << 1);
                if (col < N) {
                    *(float2*)(Cf + (size_t)r0 * ldc + col)       = make_float2(acc[i][j][0], acc[i][j][1]);
                    *(float2*)(Cf + (size_t)(r0 + 8) * ldc + col) = make_float2(acc[i][j][2], acc[i][j][3]);
                }
            }
        }
    }
}

// ---------------- flash attention (1D grid, global LPT order) ----------------
#define QS_STRIDE 100
#define VS_STRIDE 68
#define QS_B (128 * QS_STRIDE * 4)
#define VS_B (128 * VS_STRIDE * 4)
#define BUF_B (QS_B + VS_B)
#define SMEM_FLASH (QS_B + 2 * BUF_B)

__global__ void __launch_bounds__(256, 1)
flash_attn(const __half* __restrict__ Q, const __half* __restrict__ Kb,
           const __half* __restrict__ Vt, __half* __restrict__ Of)
{
    const int i = 7 - ((int)blockIdx.x >> 5);
    const int z = (int)blockIdx.x & 31;
    const int b = z >> 4, h = z & 15;

    extern __shared__ uint32_t smw[];
    const uint32_t sQ  = su32(smw);
    const uint32_t sB0 = sQ + QS_B;

    const int tid = threadIdx.x, lane = tid & 31, w = tid >> 5;
    const int g = lane >> 2, tig = lane & 3;

    const __half* Qg = Q  + (size_t)(b * Sb + i * 128) * (NH * QKD) + h * QKD;
    const __half* Kg = Kb + (size_t)z * Sb * QKD;
    const __half* Vg = Vt + (size_t)z * VD * Sb;

    const uint32_t aQbase = sQ + (uint32_t)(((w * 16 + (lane & 15)) * QS_STRIDE
                                             + ((lane >> 4) << 2)) * 4);
    const uint32_t bKoff = (uint32_t)((((lane & 7) + ((lane >> 4) << 3)) * QS_STRIDE
                                       + (((lane >> 3) & 1) << 2)) * 4);
    const uint32_t bVoff = (uint32_t)((((lane & 7) + ((lane >> 4) << 3)) * VS_STRIDE
                                       + (((lane >> 3) & 1) << 2)) * 4);

    auto load_K = [&](int j, uint32_t dst) {
        const __half* src = Kg + (size_t)j * 128 * QKD;
        for (int t = tid; t < 128 * 24; t += 256) {
            int row = t / 24, cc = t % 24;
            CP_ASYNC16(dst + (uint32_t)(row * QS_STRIDE + cc * 4) * 4,
                       src + (size_t)row * QKD + cc * 8, 16);
        }
    };
    auto load_V = [&](int j, uint32_t dst) {
        for (int t = tid; t < 128 * 16; t += 256) {
            int row = t / 16, cc = t % 16;
            CP_ASYNC16(dst + (uint32_t)(row * VS_STRIDE + cc * 4) * 4,
                       Vg + (size_t)row * Sb + j * 128 + cc * 8, 16);
        }
    };

    for (int t = tid; t < 128 * 24; t += 256) {
        int row = t / 24, cc = t % 24;
        CP_ASYNC16(sQ + (uint32_t)(row * QS_STRIDE + cc * 4) * 4,
                   Qg + (size_t)row * (NH * QKD) + cc * 8, 16);
    }
    load_K(0, sB0);
    load_V(0, sB0 + QS_B);
    CP_COMMIT();

    float m0 = -1e30f, m1 = -1e30f, l0 = 0.f, l1 = 0.f;
    float o[16][4];
#pragma unroll
    for (int nt = 0; nt < 16; nt++)
#pragma unroll
        for (int r = 0; r < 4; r++) o[nt][r] = 0.f;

    for (int j = 0; j <= i; j++) {
        const int p = j & 1;
        if (j < i) {
            const uint32_t nb = sB0 + (uint32_t)(p ^ 1) * BUF_B;
            load_K(j + 1, nb);
            load_V(j + 1, nb + QS_B);
            CP_COMMIT();
            CP_WAIT(1);
        } else {
            CP_WAIT(0);
        }
        __syncthreads();

        const uint32_t kbB = sB0 + (uint32_t)p * BUF_B;
        const uint32_t vbB = kbB + QS_B;

        float s[16][4];
#pragma unroll
        for (int nt = 0; nt < 16; nt++)
#pragma unroll
            for (int r = 0; r < 4; r++) s[nt][r] = 0.f;

#pragma unroll
        for (int ks = 0; ks < 12; ks++) {
            uint32_t a[4];
            LDSM_X4(a[0], a[1], a[2], a[3], aQbase + (uint32_t)ks * 32u);
#pragma unroll
            for (int t = 0; t < 8; t++) {
                uint32_t b0, b1, b2, b3;
                LDSM_X4(b0, b1, b2, b3,
                        kbB + (uint32_t)(t * 16 * QS_STRIDE * 4) + bKoff + (uint32_t)ks * 32u);
                uint32_t bb0[2] = {b0, b1}, bb1[2] = {b2, b3};
                mma_f16(s[2 * t],     a, bb0);
                mma_f16(s[2 * t + 1], a, bb1);
            }
        }

        if (j == i) {
            const int q0 = 16 * w + g, q1 = q0 + 8;
#pragma unroll
            for (int nt = 0; nt < 16; nt++) {
                int key = 8 * nt + 2 * tig;
                if (key     > q0) s[nt][0] = -1e30f;
                if (key + 1 > q0) s[nt][1] = -1e30f;
                if (key     > q1) s[nt][2] = -1e30f;
                if (key + 1 > q1) s[nt][3] = -1e30f;
            }
        }

        float rm0 = -1e30f, rm1 = -1e30f;
#pragma unroll
        for (int nt = 0; nt < 16; nt++) {
            rm0 = fmaxf(rm0, fmaxf(s[nt][0], s[nt][1]));
            rm1 = fmaxf(rm1, fmaxf(s[nt][2], s[nt][3]));
        }
        rm0 = fmaxf(rm0, __shfl_xor_sync(0xffffffffu, rm0, 1));
        rm0 = fmaxf(rm0, __shfl_xor_sync(0xffffffffu, rm0, 2));
        rm1 = fmaxf(rm1, __shfl_xor_sync(0xffffffffu, rm1, 1));
        rm1 = fmaxf(rm1, __shfl_xor_sync(0xffffffffu, rm1, 2));

        const float mn0 = fmaxf(m0, rm0), mn1 = fmaxf(m1, rm1);
        const float sc0 = __expf(m0 - mn0), sc1 = __expf(m1 - mn1);
        m0 = mn0; m1 = mn1;

        float ps0 = 0.f, ps1 = 0.f;
#pragma unroll
        for (int nt = 0; nt < 16; nt++) {
            s[nt][0] = __expf(s[nt][0] - m0);
            s[nt][1] = __expf(s[nt][1] - m0);
            s[nt][2] = __expf(s[nt][2] - m1);
            s[nt][3] = __expf(s[nt][3] - m1);
            ps0 += s[nt][0] + s[nt][1];
            ps1 += s[nt][2] + s[nt][3];
            o[nt][0] *= sc0; o[nt][1] *= sc0;
            o[nt][2] *= sc1; o[nt][3] *= sc1;
        }
        ps0 += __shfl_xor_sync(0xffffffffu, ps0, 1);
        ps0 += __shfl_xor_sync(0xffffffffu, ps0, 2);
        ps1 += __shfl_xor_sync(0xffffffffu, ps1, 1);
        ps1 += __shfl_xor_sync(0xffffffffu, ps1, 2);
        l0 = l0 * sc0 + ps0;
        l1 = l1 * sc1 + ps1;

#pragma unroll
        for (int kt = 0; kt < 8; kt++) {
            uint32_t a[4];
            a[0] = h2u(__floats2half2_rn(s[2 * kt][0],     s[2 * kt][1]));
            a[1] = h2u(__floats2half2_rn(s[2 * kt][2],     s[2 * kt][3]));
            a[2] = h2u(__floats2half2_rn(s[2 * kt + 1][0], s[2 * kt + 1][1]));
            a[3] = h2u(__floats2half2_rn(s[2 * kt + 1][2], s[2 * kt + 1][3]));
#pragma unroll
            for (int t = 0; t < 8; t++) {
                uint32_t b0, b1, b2, b3;
                LDSM_X4(b0, b1, b2, b3,
                        vbB + (uint32_t)(t * 16 * VS_STRIDE * 4) + bVoff + (uint32_t)kt * 32u);
                uint32_t bb0[2] = {b0, b1}, bb1[2] = {b2, b3};
                mma_f16(o[2 * t],     a, bb0);
                mma_f16(o[2 * t + 1], a, bb1);
            }
        }
        __syncthreads();
    }

    const float inv0 = 1.f / l0, inv1 = 1.f / l1;
    const size_t row0 = (size_t)(b * Sb + i * 128 + w * 16 + g);
    __half* out0 = Of + row0 * (NH * VD) + h * VD;
    __half* out1 = out0 + (size_t)8 * (NH * VD);
#pragma unroll
    for (int nt = 0; nt < 16; nt++) {
        int col = 8 * nt + 2 * tig;
        *(__half2*)(out0 + col) = __floats2half2_rn(o[nt][0] * inv0, o[nt][1] * inv0);
        *(__half2*)(out1 + col) = __floats2half2_rn(o[nt][2] * inv1, o[nt][3] * inv1);
    }
}

// ---------------- cvt main (hid, wqa, wkva -> g_hid, g_wqkv) -----------------
#define CM0 (MBS * Hd / 4)
#define CM1 (CM0 + QLR * Hd / 4)
#define CM2 (CM1 + DATT * Hd / 4)

__global__ void cvt_main(const float* __restrict__ s0, const float* __restrict__ s1,
                         const float* __restrict__ s2)
{
    __half *d;
    const float *s;
    int stride = gridDim.x * blockDim.x;
    for (int i = blockIdx.x * blockDim.x + threadIdx.x; i < CM2; i += stride) {
        int off;
        if (i < CM0)      { s = s0; off = i;       d = g_hid; }
        else if (i < CM1) { s = s1; off = i - CM0; d = g_wqkv; }
        else              { s = s2; off = i - CM1; d = g_wqkv + QLR * Hd; }
        float4 v = ((const float4*)s)[off];
        ((__half2*)d)[2 * off]     = __floats2half2_rn(v.x, v.y);
        ((__half2*)d)[2 * off + 1] = __floats2half2_rn(v.z, v.w);
    }
}

// ---------------- cvt rest (wqb, wo, wuk) -----------------
#define CR0 (NH * QKD * QLR / 4)
#define CR1 (CR0 + Hd * NH * VD / 4)
#define CR2 (CR1 + NH * NOPE * KVLR / 4)

__global__ void cvt_rest(const float* __restrict__ s0, const float* __restrict__ s1,
                         const float* __restrict__ s2)
{
    __half *d;
    const float *s;
    int stride = gridDim.x * blockDim.x;
    for (int i = blockIdx.x * blockDim.x + threadIdx.x; i < CR2; i += stride) {
        int off;
        if (i < CR0)      { s = s0; off = i;       d = g_wqb; }
        else if (i < CR1) { s = s1; off = i - CR0; d = g_wo; }
        else              { s = s2; off = i - CR1; d = g_wuk; }
        float4 v = ((const float4*)s)[off];
        ((__half2*)d)[2 * off]     = __floats2half2_rn(v.x, v.y);
        ((__half2*)d)[2 * off + 1] = __floats2half2_rn(v.z, v.w);
    }
}

// ---------------- transpose f32 -> f16 ----------------
__global__ void transpose_f32h(const float* __restrict__ in, long long sIn, int ldin,
                               __half* __restrict__ out, long long sOut, int ldout)
{
    __shared__ float t[32][33];
    const float* ib = in + (size_t)blockIdx.z * sIn;
    __half* ob = out + (size_t)blockIdx.z * sOut;
    int x0 = blockIdx.x * 32, y0 = blockIdx.y * 32;
    int tx = threadIdx.x, ty = threadIdx.y;
#pragma unroll
    for (int j = 0; j < 32; j += 8)
        t[ty + j][tx] = ib[(size_t)(y0 + ty + j) * ldin + x0 + tx];
    __syncthreads();
#pragma unroll
    for (int j = 0; j < 32; j += 8)
        ob[(size_t)(x0 + ty + j) * ldout + y0 + tx] = __float2half_rn(t[tx][ty + j]);
}

// ---------------- fused: LN(qa) + LN(kv_c) + rope(k_pe)*SCALE ----------------
__global__ void __launch_bounds__(128)
ln_all(const float* __restrict__ in /* g_qakva */,
       const float* __restrict__ wq, const float* __restrict__ wkv,
       const float* __restrict__ cosb, const float* __restrict__ sinb)
{
    const int r = blockIdx.x, tid = threadIdx.x;
    const int lane = tid & 31, warp = tid >> 5;
    __shared__ float sm4[4];
    __shared__ float stats[2];

    const float4* xq = (const float4*)(in + (size_t)r * NQK);
    float4 v[3];
    float s = 0.f;
#pragma unroll
    for (int q = 0; q < 3; q++) {
        v[q] = xq[tid + q * 128];
        s += v[q].x + v[q].y + v[q].z + v[q].w;
    }
#pragma unroll
    for (int o = 16; o > 0; o >>= 1) s += __shfl_xor_sync(0xffffffffu, s, o);
    if (lane == 0) sm4[warp] = s;
    __syncthreads();
    if (tid == 0) stats[0] = (sm4[0] + sm4[1] + sm4[2] + sm4[3]) / QLR;
    __syncthreads();
    float mean = stats[0];

    float vv = 0.f;
#pragma unroll
    for (int q = 0; q < 3; q++) {
        float dx = v[q].x - mean, dy = v[q].y - mean;
        float dz = v[q].z - mean, dw = v[q].w - mean;
        vv += dx * dx + dy * dy + dz * dz + dw * dw;
    }
#pragma unroll
    for (int o = 16; o > 0; o >>= 1) vv += __shfl_xor_sync(0xffffffffu, vv, o);
    if (lane == 0) sm4[warp] = vv;
    __syncthreads();
    if (tid == 0) stats[1] = rsqrtf((sm4[0] + sm4[1] + sm4[2] + sm4[3]) / QLR + 1e-5f);
    __syncthreads();
    float rstd = stats[1];

    __half2* yq = (__half2*)(g_qaln + (size_t)r * QLR);
#pragma unroll
    for (int q = 0; q < 3; q++) {
        float4 ww = ((const float4*)wq)[tid + q * 128];
        int c = tid + q * 128;
        yq[2 * c]     = __floats2half2_rn((v[q].x - mean) * rstd * ww.x,
                                          (v[q].y - mean) * rstd * ww.y);
        yq[2 * c + 1] = __floats2half2_rn((v[q].z - mean) * rstd * ww.z,
                                          (v[q].w - mean) * rstd * ww.w);
    }
    __syncthreads();

    float4 vk = ((const float4*)(in + (size_t)r * NQK + QLR))[tid];
    s = vk.x + vk.y + vk.z + vk.w;
#pragma unroll
    for (int o = 16; o > 0; o >>= 1) s += __shfl_xor_sync(0xffffffffu, s, o);
    if (lane == 0) sm4[warp] = s;
    __syncthreads();
    if (tid == 0) stats[0] = (sm4[0] + sm4[1] + sm4[2] + sm4[3]) / KVLR;
    __syncthreads();
    mean = stats[0];

    float dx = vk.x - mean, dy = vk.y - mean, dz = vk.z - mean, dw = vk.w - mean;
    vv = dx * dx + dy * dy + dz * dz + dw * dw;
#pragma unroll
    for (int o = 16; o > 0; o >>= 1) vv += __shfl_xor_sync(0xffffffffu, vv, o);
    if (lane == 0) sm4[warp] = vv;
    __syncthreads();
    if (tid == 0) stats[1] = rsqrtf((sm4[0] + sm4[1] + sm4[2] + sm4[3]) / KVLR + 1e-5f);
    __syncthreads();
    rstd = stats[1];

    __half2* yk = (__half2*)(g_kattn + (size_t)r * DATT);
    float4 wwk = ((const float4*)wkv)[tid];
    yk[2 * tid]     = __floats2half2_rn((vk.x - mean) * rstd * wwk.x,
                                        (vk.y - mean) * rstd * wwk.y);
    yk[2 * tid + 1] = __floats2half2_rn((vk.z - mean) * rstd * wwk.z,
                                        (vk.w - mean) * rstd * wwk.w);

    if (tid < ROPE) {
        const int i = tid;
        const int b = r >> 10, srow = r & (Sb - 1);
        const float* pe = in + (size_t)r * NQK + QLR + KVLR;
        float xx = pe[i];
        float other = pe[(i < 32) ? (i + 32) : (i - 32)];
        float rot = (i < 32) ? -other : other;
        __half hv = __float2half_rn((xx * cosb[r * ROPE + i] + rot * sinb[r * ROPE + i]) * SCALE);
#pragma unroll
        for (int h = 0; h < NH; h++)
            g_kb[(((size_t)(b * NH + h) * Sb) + srow) * QKD + NOPE + i] = hv;
    }
}

// ---------------- RoPE q_pe: in-place on g_q ----------------
__global__ void rope_q(const float* __restrict__ cosb, const float* __restrict__ sinb)
{
    int bs = blockIdx.x >> 4;
    int h  = blockIdx.x & 15;
    int i  = threadIdx.x;
    __half* base = g_q + (size_t)bs * (NH * QKD) + h * QKD + NOPE;
    float x = __half2float(base[i]);
    float other = __half2float(base[(i < 32) ? (i + 32) : (i - 32)]);
    __syncthreads();
    float rot = (i < 32) ? -other : other;
    base[i] = __float2half_rn(x * cosb[bs * ROPE + i] + rot * sinb[bs * ROPE + i]);
}

// ---------------- launch ----------------
extern "C" void kernel_launch(void* const* d_in, const int* in_sizes, int n_in,
                              void* d_out, int out_size)
{
    const float* hidden  = (const float*)d_in[0];
    const float* cosb    = (const float*)d_in[1];
    const float* sinb    = (const float*)d_in[2];
    const float* w_qa    = (const float*)d_in[3];
    const float* qalnw   = (const float*)d_in[4];
    const float* w_qb    = (const float*)d_in[5];
    const float* w_kva   = (const float*)d_in[6];
    const float* kvalnw  = (const float*)d_in[7];
    const float* W_UK_T  = (const float*)d_in[8];
    const float* W_UV    = (const float*)d_in[9];
    const float* w_o     = (const float*)d_in[10];
    float* out = (float*)d_out;

    float *p_qakva;
    __half *p_hid, *p_wqkv, *p_wqb, *p_wo, *p_wuk;
    __half *p_qaln, *p_q, *p_kattn, *p_kb, *p_vT, *p_of, *p_wuvT;
    cudaGetSymbolAddress((void**)&p_qakva, g_qakva);
    cudaGetSymbolAddress((void**)&p_hid,   g_hid);
    cudaGetSymbolAddress((void**)&p_wqkv,  g_wqkv);
    cudaGetSymbolAddress((void**)&p_wqb,   g_wqb);
    cudaGetSymbolAddress((void**)&p_wo,    g_wo);
    cudaGetSymbolAddress((void**)&p_wuk,   g_wuk);
    cudaGetSymbolAddress((void**)&p_qaln,  g_qaln);
    cudaGetSymbolAddress((void**)&p_q,     g_q);
    cudaGetSymbolAddress((void**)&p_kattn, g_kattn);
    cudaGetSymbolAddress((void**)&p_kb,    g_kb);
    cudaGetSymbolAddress((void**)&p_vT,    g_vT);
    cudaGetSymbolAddress((void**)&p_of,    g_outfl);
    cudaGetSymbolAddress((void**)&p_wuvT,  g_wuvT);

    cudaFuncSetAttribute(mma_gemm, cudaFuncAttributeMaxDynamicSharedMemorySize, SMEM_GEMM);
    cudaFuncSetAttribute(flash_attn, cudaFuncAttributeMaxDynamicSharedMemorySize, SMEM_FLASH);

    auto grid = [](int M, int N, int z) {
        return dim3((N + BN - 1) / BN, (M + BM - 1) / BM, z);
    };
    const int T = 256;

    cudaStream_t sB;
    cudaStreamCreateWithFlags(&sB, cudaStreamNonBlocking);
    cudaEvent_t evFork, evSideReady, evKV, evJoin;
    cudaEventCreateWithFlags(&evFork, cudaEventDisableTiming);
    cudaEventCreateWithFlags(&evSideReady, cudaEventDisableTiming);
    cudaEventCreateWithFlags(&evKV, cudaEventDisableTiming);
    cudaEventCreateWithFlags(&evJoin, cudaEventDisableTiming);

    cudaEventRecord(evFork, 0);
    cudaStreamWaitEvent(sB, evFork, 0);

    // side: convert wqb/wo/wuk + transpose W_UV (overlaps GEMM1)
    cvt_rest<<<1024, 256, 0, sB>>>(w_qb, w_o, W_UK_T);
    transpose_f32h<<<dim3(4, 16, NH), dim3(32, 8), 0, sB>>>(
        W_UV, (long long)KVLR * VD, VD, p_wuvT, (long long)VD * KVLR, KVLR);
    cudaEventRecord(evSideReady, sB);

    // main: convert hid + wqa|wkva
    cvt_main<<<1024, 256>>>(hidden, w_qa, w_kva);

    // 1+2) qakva(f32) = hid @ [wqa|wkva]^T   [2048,2112] K=2048 (one wave)
    mma_gemm<<<grid(MBS, NQK, 1), T, SMEM_GEMM>>>(
        p_hid, Hd, 0,1,0,1,  p_wqkv, Hd, 0,1,0,1,  p_qakva, NQK, 0,1,0,1,
        MBS, NQK, Hd, 0, 1.f);

    // 3+4+5) LN(qa), LN(kv_c), rope(k_pe)
    ln_all<<<MBS, 128>>>(p_qakva, qalnw, kvalnw, cosb, sinb);
    cudaEventRecord(evKV, 0);

    // side: V' and K'
    cudaStreamWaitEvent(sB, evKV, 0);
    mma_gemm<<<grid(VD, Sb, Bb * NH), T, SMEM_GEMM, sB>>>(
        p_wuvT, KVLR, 0,1, (long long)VD * KVLR, NH,
        p_kattn, DATT, (long long)Sb * DATT, NH, 0, 1,
        p_vT, Sb, (long long)VD * Sb, 1, 0, 1,
        VD, Sb, KVLR, 1, 1.f);
    mma_gemm<<<grid(Sb, NOPE, Bb * NH), T, SMEM_GEMM, sB>>>(
        p_kattn, DATT, (long long)Sb * DATT, NH, 0, 1,
        p_wuk, KVLR, 0,1, (long long)NOPE * KVLR, NH,
        p_kb, QKD, (long long)Sb * QKD, 1, 0, 1,
        Sb, NOPE, KVLR, 1, SCALE);
    cudaEventRecord(evJoin, sB);

    // main: q projection + rope
    cudaStreamWaitEvent(0, evSideReady, 0);
    mma_gemm<<<grid(MBS, NH * QKD, 1), T, SMEM_GEMM>>>(
        p_qaln, QLR, 0,1,0,1,  p_wqb, QLR, 0,1,0,1,  p_q, NH * QKD, 0,1,0,1,
        MBS, NH * QKD, QLR, 1, 1.f);
    rope_q<<<MBS * NH, 64>>>(cosb, sinb);

    cudaStreamWaitEvent(0, evJoin, 0);

    // 9-11) fused flash attention
    flash_attn<<<256, 256, SMEM_FLASH>>>(p_q, p_kb, p_vT, p_of);

    // 13) out(f32) = outfl @ wo^T  [2048,2048] K=2048
    mma_gemm<<<grid(MBS, Hd, 1), T, SMEM_GEMM>>>(
        p_of, NH * VD, 0,1,0,1,  p_wo, NH * VD, 0,1,0,1,  out, Hd, 0,1,0,1,
        MBS, Hd, NH * VD, 0, 1.f);
}

// round 17
// speedup vs baseline: 4.9842x; 1.0529x over previous
#include <cuda_runtime.h>
#include <cuda_fp16.h>
#include <math.h>
#include <stdint.h>

// ---------------- problem constants ----------------
#define Bb 2
#define Sb 1024
#define Hd 2048
#define NH 16
#define NOPE 128
#define ROPE 64
#define VD 128
#define QKD 192
#define QLR 1536
#define KVLR 512
#define DATT 576
#define MBS (Bb*Sb)
#define NQK (QLR + DATT)               // 2112 combined qa|kva width
#define SCALE 0.07216878364870323f    // 1/sqrt(192)

// ---------------- scratch ----------------
__device__ float  g_qakva [MBS * NQK];             // [2048][2112] = qa | kva
__device__ __half g_hid   [MBS * Hd];
__device__ __half g_wqkv  [NQK * Hd];              // wqa rows 0:1536 | wkva rows 1536:2112
__device__ __half g_wqb   [NH * QKD * QLR];
__device__ __half g_wo    [Hd * NH * VD];
__device__ __half g_wuk   [NH * NOPE * KVLR];      // W_UK_T f16 [h][128][512]
__device__ __half g_qaln  [MBS * QLR];
__device__ __half g_q     [MBS * NH * QKD];        // rope applied in place
__device__ __half g_kattn [MBS * DATT];            // LN(kv_c) (cols 0:512)
__device__ __half g_kb    [(size_t)Bb*NH*Sb*QKD];  // absorbed keys, scaled
__device__ __half g_vT    [(size_t)Bb*NH*VD*Sb];   // V'^T per (b,h): [128][1024]
__device__ __half g_outfl [MBS * NH * VD];
__device__ __half g_wuvT  [NH * VD * KVLR];

// ---------------- helpers ----------------
__device__ __forceinline__ uint32_t su32(const void* p) {
    uint32_t a;
    asm("{ .reg .u64 t; cvta.to.shared.u64 t, %1; cvt.u32.u64 %0, t; }" : "=r"(a) : "l"(p));
    return a;
}
__device__ __forceinline__ uint32_t h2u(__half2 h) {
    union { __half2 h; uint32_t u; } c;
    c.h = h;
    return c.u;
}
__device__ __forceinline__ void mma_f16(float c[4], const uint32_t a[4], const uint32_t b[2]) {
    asm volatile(
        "mma.sync.aligned.m16n8k16.row.col.f32.f16.f16.f32 "
        "{%0,%1,%2,%3},{%4,%5,%6,%7},{%8,%9},{%0,%1,%2,%3};"
        : "+f"(c[0]), "+f"(c[1]), "+f"(c[2]), "+f"(c[3])
        : "r"(a[0]), "r"(a[1]), "r"(a[2]), "r"(a[3]), "r"(b[0]), "r"(b[1]));
}
#define LDSM_X4(r0, r1, r2, r3, addr) \
    asm volatile("ldmatrix.sync.aligned.m8n8.x4.shared.b16 {%0,%1,%2,%3}, [%4];" \
                 : "=r"(r0), "=r"(r1), "=r"(r2), "=r"(r3) : "r"(addr))
#define CP_ASYNC16(dst, src, sz) \
    asm volatile("cp.async.cg.shared.global [%0], [%1], 16, %2;" \
                 :: "r"(dst), "l"(src), "r"(sz) : "memory")
#define CP_COMMIT() asm volatile("cp.async.commit_group;" ::: "memory")
#define CP_WAIT(n)  asm volatile("cp.async.wait_group %0;" :: "n"(n) : "memory")

// ------ fp16 mma GEMM: 128x128 block, 4 warps (64x64 warp tile), 3 stages ---
#define BM 128
#define BN 128
#define BKK 64
#define WSH 36
#define TILE_W (BM * WSH)
#define SSTRIDE (2u * TILE_W * 4u)        // bytes per stage (A tile + B tile)
#define NST 3
#define SMEM_GEMM (NST * 2 * TILE_W * 4)  // 110592

__global__ void __launch_bounds__(128, 2)
mma_gemm(const __half* __restrict__ A, int lda, long long sAd, int dA, long long sAm, int mA,
         const __half* __restrict__ B, int ldb, long long sBd, int dB, long long sBm, int mB,
         void*         __restrict__ Cv, int ldc, long long sCd, int dC, long long sCm, int mC,
         int M, int N, int K, int outHalf, float cscale)
{
    const int mBase = blockIdx.y * BM;
    const int nBase = blockIdx.x * BN;

    extern __shared__ uint32_t smw[];
    const uint32_t sBase = su32(smw);

    const int z = blockIdx.z;
    const __half* Ab = A + (size_t)(z / dA) * sAd + (size_t)(z % mA) * sAm;
    const __half* Bp = B + (size_t)(z / dB) * sBd + (size_t)(z % mB) * sBm;
    const size_t  cOff = (size_t)(z / dC) * sCd + (size_t)(z % mC) * sCm;

    const int tid  = threadIdx.x;       // 0..127
    const int lane = tid & 31;
    const int warp = tid >> 5;          // 0..3
    const int wm   = warp & 1;          // 2 warps in M (64 rows)
    const int wn   = warp >> 1;         // 2 warps in N (64 cols)
    const int g    = lane >> 2;
    const int tig  = lane & 3;

    // stage-relative ldmatrix base offsets: A at 0, B at TILE_W*4
    uint32_t aAddr[4];
#pragma unroll
    for (int ii = 0; ii < 4; ii++)
        aAddr[ii] = sBase +
            (uint32_t)(((wm * 64 + ii * 16 + (lane & 15)) * WSH + ((lane >> 4) << 2)) * 4);
    uint32_t bAddr[4];
#pragma unroll
    for (int q = 0; q < 4; q++)
        bAddr[q] = sBase + TILE_W * 4u +
            (uint32_t)(((wn * 64 + q * 16 + (lane & 7) + ((lane >> 4) << 3)) * WSH
                        + (((lane >> 3) & 1) << 2)) * 4);

    float acc[4][8][4];
#pragma unroll
    for (int i = 0; i < 4; i++)
#pragma unroll
        for (int j = 0; j < 8; j++)
#pragma unroll
            for (int r = 0; r < 4; r++) acc[i][j][r] = 0.f;

    const int nc = K / BKK;

    auto copy_chunk = [&](int ci, int st) {
        const int k0 = ci * BKK;
        const uint32_t aD = sBase + (uint32_t)st * SSTRIDE;
        const uint32_t bD = aD + TILE_W * 4u;
#pragma unroll
        for (int q = 0; q < 8; q++) {
            int slot = tid + q * 128;           // 0..1023
            int row  = slot >> 3;
            int c8   = (slot & 7) << 3;
            uint32_t soff = (uint32_t)(row * (WSH * 4) + c8 * 2);
            int gm = mBase + row;
            const __half* asrc = (gm < M) ? (Ab + (size_t)gm * lda + k0 + c8) : Ab;
            CP_ASYNC16(aD + soff, asrc, (gm < M) ? 16 : 0);
            int gn = nBase + row;
            const __half* bsrc = (gn < N) ? (Bp + (size_t)gn * ldb + k0 + c8) : Bp;
            CP_ASYNC16(bD + soff, bsrc, (gn < N) ? 16 : 0);
        }
        CP_COMMIT();
    };

    // prologue: stages 0 and 1
    copy_chunk(0, 0);
    if (nc > 1) copy_chunk(1, 1); else CP_COMMIT();

    int st = 0;
    for (int i = 0; i < nc; i++) {
        CP_WAIT(1);
        __syncthreads();

        if (i + 2 < nc) copy_chunk(i + 2, (st + 2 >= NST) ? st + 2 - NST : st + 2);
        else            CP_COMMIT();

        const uint32_t stOff = (uint32_t)st * SSTRIDE;
#pragma unroll
        for (int ks = 0; ks < 4; ks++) {
            const uint32_t kOff = stOff + (uint32_t)ks * 32u;
            uint32_t a[4][4], b[8][2];
#pragma unroll
            for (int ii = 0; ii < 4; ii++)
                LDSM_X4(a[ii][0], a[ii][1], a[ii][2], a[ii][3], aAddr[ii] + kOff);
#pragma unroll
            for (int q = 0; q < 4; q++)
                LDSM_X4(b[2 * q][0], b[2 * q][1], b[2 * q + 1][0], b[2 * q + 1][1],
                        bAddr[q] + kOff);
#pragma unroll
            for (int ii = 0; ii < 4; ii++)
#pragma unroll
                for (int jj = 0; jj < 8; jj++)
                    mma_f16(acc[ii][jj], a[ii], b[jj]);
        }
        st = (st + 1 >= NST) ? 0 : st + 1;
    }

    if (outHalf) {
        __half* Ch = (__half*)Cv + cOff;
#pragma unroll
        for (int i = 0; i < 4; i++) {
            int r0 = mBase + (wm << 6) + (i << 4) + g;
            if (r0 >= M) continue;
#pragma unroll
            for (int j = 0; j < 8; j++) {
                int col = nBase + (wn << 6) + (j << 3) + (tig << 1);
                if (col < N) {
                    *(__half2*)(Ch + (size_t)r0 * ldc + col) =
                        __floats2half2_rn(acc[i][j][0] * cscale, acc[i][j][1] * cscale);
                    *(__half2*)(Ch + (size_t)(r0 + 8) * ldc + col) =
                        __floats2half2_rn(acc[i][j][2] * cscale, acc[i][j][3] * cscale);
                }
            }
        }
    } else {
        float* Cf = (float*)Cv + cOff;
#pragma unroll
        for (int i = 0; i < 4; i++) {
            int r0 = mBase + (wm << 6) + (i << 4) + g;
            if (r0 >= M) continue;
#pragma unroll
            for (int j = 0; j < 8; j++) {
                int col = nBase + (wn << 6) + (j << 3) + (tig << 1);
                if (col < N) {
                    *(float2*)(Cf + (size_t)r0 * ldc + col)       = make_float2(acc[i][j][0], acc[i][j][1]);
                    *(float2*)(Cf + (size_t)(r0 + 8) * ldc + col) = make_float2(acc[i][j][2], acc[i][j][3]);
                }
            }
        }
    }
}

// ---------------- flash attention (1D grid, global LPT order) ----------------
#define QS_STRIDE 100
#define VS_STRIDE 68
#define QS_B (128 * QS_STRIDE * 4)
#define VS_B (128 * VS_STRIDE * 4)
#define BUF_B (QS_B + VS_B)
#define SMEM_FLASH (QS_B + 2 * BUF_B)

__global__ void __launch_bounds__(256, 1)
flash_attn(const __half* __restrict__ Q, const __half* __restrict__ Kb,
           const __half* __restrict__ Vt, __half* __restrict__ Of)
{
    const int i = 7 - ((int)blockIdx.x >> 5);
    const int z = (int)blockIdx.x & 31;
    const int b = z >> 4, h = z & 15;

    extern __shared__ uint32_t smw[];
    const uint32_t sQ  = su32(smw);
    const uint32_t sB0 = sQ + QS_B;

    const int tid = threadIdx.x, lane = tid & 31, w = tid >> 5;
    const int g = lane >> 2, tig = lane & 3;

    const __half* Qg = Q  + (size_t)(b * Sb + i * 128) * (NH * QKD) + h * QKD;
    const __half* Kg = Kb + (size_t)z * Sb * QKD;
    const __half* Vg = Vt + (size_t)z * VD * Sb;

    const uint32_t aQbase = sQ + (uint32_t)(((w * 16 + (lane & 15)) * QS_STRIDE
                                             + ((lane >> 4) << 2)) * 4);
    const uint32_t bKoff = (uint32_t)((((lane & 7) + ((lane >> 4) << 3)) * QS_STRIDE
                                       + (((lane >> 3) & 1) << 2)) * 4);
    const uint32_t bVoff = (uint32_t)((((lane & 7) + ((lane >> 4) << 3)) * VS_STRIDE
                                       + (((lane >> 3) & 1) << 2)) * 4);

    auto load_K = [&](int j, uint32_t dst) {
        const __half* src = Kg + (size_t)j * 128 * QKD;
        for (int t = tid; t < 128 * 24; t += 256) {
            int row = t / 24, cc = t % 24;
            CP_ASYNC16(dst + (uint32_t)(row * QS_STRIDE + cc * 4) * 4,
                       src + (size_t)row * QKD + cc * 8, 16);
        }
    };
    auto load_V = [&](int j, uint32_t dst) {
        for (int t = tid; t < 128 * 16; t += 256) {
            int row = t / 16, cc = t % 16;
            CP_ASYNC16(dst + (uint32_t)(row * VS_STRIDE + cc * 4) * 4,
                       Vg + (size_t)row * Sb + j * 128 + cc * 8, 16);
        }
    };

    for (int t = tid; t < 128 * 24; t += 256) {
        int row = t / 24, cc = t % 24;
        CP_ASYNC16(sQ + (uint32_t)(row * QS_STRIDE + cc * 4) * 4,
                   Qg + (size_t)row * (NH * QKD) + cc * 8, 16);
    }
    load_K(0, sB0);
    load_V(0, sB0 + QS_B);
    CP_COMMIT();

    float m0 = -1e30f, m1 = -1e30f, l0 = 0.f, l1 = 0.f;
    float o[16][4];
#pragma unroll
    for (int nt = 0; nt < 16; nt++)
#pragma unroll
        for (int r = 0; r < 4; r++) o[nt][r] = 0.f;

    for (int j = 0; j <= i; j++) {
        const int p = j & 1;
        if (j < i) {
            const uint32_t nb = sB0 + (uint32_t)(p ^ 1) * BUF_B;
            load_K(j + 1, nb);
            load_V(j + 1, nb + QS_B);
            CP_COMMIT();
            CP_WAIT(1);
        } else {
            CP_WAIT(0);
        }
        __syncthreads();

        const uint32_t kbB = sB0 + (uint32_t)p * BUF_B;
        const uint32_t vbB = kbB + QS_B;

        float s[16][4];
#pragma unroll
        for (int nt = 0; nt < 16; nt++)
#pragma unroll
            for (int r = 0; r < 4; r++) s[nt][r] = 0.f;

#pragma unroll
        for (int ks = 0; ks < 12; ks++) {
            uint32_t a[4];
            LDSM_X4(a[0], a[1], a[2], a[3], aQbase + (uint32_t)ks * 32u);
#pragma unroll
            for (int t = 0; t < 8; t++) {
                uint32_t b0, b1, b2, b3;
                LDSM_X4(b0, b1, b2, b3,
                        kbB + (uint32_t)(t * 16 * QS_STRIDE * 4) + bKoff + (uint32_t)ks * 32u);
                uint32_t bb0[2] = {b0, b1}, bb1[2] = {b2, b3};
                mma_f16(s[2 * t],     a, bb0);
                mma_f16(s[2 * t + 1], a, bb1);
            }
        }

        if (j == i) {
            const int q0 = 16 * w + g, q1 = q0 + 8;
#pragma unroll
            for (int nt = 0; nt < 16; nt++) {
                int key = 8 * nt + 2 * tig;
                if (key     > q0) s[nt][0] = -1e30f;
                if (key + 1 > q0) s[nt][1] = -1e30f;
                if (key     > q1) s[nt][2] = -1e30f;
                if (key + 1 > q1) s[nt][3] = -1e30f;
            }
        }

        float rm0 = -1e30f, rm1 = -1e30f;
#pragma unroll
        for (int nt = 0; nt < 16; nt++) {
            rm0 = fmaxf(rm0, fmaxf(s[nt][0], s[nt][1]));
            rm1 = fmaxf(rm1, fmaxf(s[nt][2], s[nt][3]));
        }
        rm0 = fmaxf(rm0, __shfl_xor_sync(0xffffffffu, rm0, 1));
        rm0 = fmaxf(rm0, __shfl_xor_sync(0xffffffffu, rm0, 2));
        rm1 = fmaxf(rm1, __shfl_xor_sync(0xffffffffu, rm1, 1));
        rm1 = fmaxf(rm1, __shfl_xor_sync(0xffffffffu, rm1, 2));

        const float mn0 = fmaxf(m0, rm0), mn1 = fmaxf(m1, rm1);
        const float sc0 = __expf(m0 - mn0), sc1 = __expf(m1 - mn1);
        m0 = mn0; m1 = mn1;

        float ps0 = 0.f, ps1 = 0.f;
#pragma unroll
        for (int nt = 0; nt < 16; nt++) {
            s[nt][0] = __expf(s[nt][0] - m0);
            s[nt][1] = __expf(s[nt][1] - m0);
            s[nt][2] = __expf(s[nt][2] - m1);
            s[nt][3] = __expf(s[nt][3] - m1);
            ps0 += s[nt][0] + s[nt][1];
            ps1 += s[nt][2] + s[nt][3];
            o[nt][0] *= sc0; o[nt][1] *= sc0;
            o[nt][2] *= sc1; o[nt][3] *= sc1;
        }
        ps0 += __shfl_xor_sync(0xffffffffu, ps0, 1);
        ps0 += __shfl_xor_sync(0xffffffffu, ps0, 2);
        ps1 += __shfl_xor_sync(0xffffffffu, ps1, 1);
        ps1 += __shfl_xor_sync(0xffffffffu, ps1, 2);
        l0 = l0 * sc0 + ps0;
        l1 = l1 * sc1 + ps1;

#pragma unroll
        for (int kt = 0; kt < 8; kt++) {
            uint32_t a[4];
            a[0] = h2u(__floats2half2_rn(s[2 * kt][0],     s[2 * kt][1]));
            a[1] = h2u(__floats2half2_rn(s[2 * kt][2],     s[2 * kt][3]));
            a[2] = h2u(__floats2half2_rn(s[2 * kt + 1][0], s[2 * kt + 1][1]));
            a[3] = h2u(__floats2half2_rn(s[2 * kt + 1][2], s[2 * kt + 1][3]));
#pragma unroll
            for (int t = 0; t < 8; t++) {
                uint32_t b0, b1, b2, b3;
                LDSM_X4(b0, b1, b2, b3,
                        vbB + (uint32_t)(t * 16 * VS_STRIDE * 4) + bVoff + (uint32_t)kt * 32u);
                uint32_t bb0[2] = {b0, b1}, bb1[2] = {b2, b3};
                mma_f16(o[2 * t],     a, bb0);
                mma_f16(o[2 * t + 1], a, bb1);
            }
        }
        __syncthreads();
    }

    const float inv0 = 1.f / l0, inv1 = 1.f / l1;
    const size_t row0 = (size_t)(b * Sb + i * 128 + w * 16 + g);
    __half* out0 = Of + row0 * (NH * VD) + h * VD;
    __half* out1 = out0 + (size_t)8 * (NH * VD);
#pragma unroll
    for (int nt = 0; nt < 16; nt++) {
        int col = 8 * nt + 2 * tig;
        *(__half2*)(out0 + col) = __floats2half2_rn(o[nt][0] * inv0, o[nt][1] * inv0);
        *(__half2*)(out1 + col) = __floats2half2_rn(o[nt][2] * inv1, o[nt][3] * inv1);
    }
}

// ---------------- cvt main (hid, wqa, wkva -> g_hid, g_wqkv) -----------------
#define CM0 (MBS * Hd / 4)
#define CM1 (CM0 + QLR * Hd / 4)
#define CM2 (CM1 + DATT * Hd / 4)

__global__ void cvt_main(const float* __restrict__ s0, const float* __restrict__ s1,
                         const float* __restrict__ s2)
{
    __half *d;
    const float *s;
    int stride = gridDim.x * blockDim.x;
    for (int i = blockIdx.x * blockDim.x + threadIdx.x; i < CM2; i += stride) {
        int off;
        if (i < CM0)      { s = s0; off = i;       d = g_hid; }
        else if (i < CM1) { s = s1; off = i - CM0; d = g_wqkv; }
        else              { s = s2; off = i - CM1; d = g_wqkv + QLR * Hd; }
        float4 v = ((const float4*)s)[off];
        ((__half2*)d)[2 * off]     = __floats2half2_rn(v.x, v.y);
        ((__half2*)d)[2 * off + 1] = __floats2half2_rn(v.z, v.w);
    }
}

// ---------------- cvt rest (wqb, wo, wuk) -----------------
#define CR0 (NH * QKD * QLR / 4)
#define CR1 (CR0 + Hd * NH * VD / 4)
#define CR2 (CR1 + NH * NOPE * KVLR / 4)

__global__ void cvt_rest(const float* __restrict__ s0, const float* __restrict__ s1,
                         const float* __restrict__ s2)
{
    __half *d;
    const float *s;
    int stride = gridDim.x * blockDim.x;
    for (int i = blockIdx.x * blockDim.x + threadIdx.x; i < CR2; i += stride) {
        int off;
        if (i < CR0)      { s = s0; off = i;       d = g_wqb; }
        else if (i < CR1) { s = s1; off = i - CR0; d = g_wo; }
        else              { s = s2; off = i - CR1; d = g_wuk; }
        float4 v = ((const float4*)s)[off];
        ((__half2*)d)[2 * off]     = __floats2half2_rn(v.x, v.y);
        ((__half2*)d)[2 * off + 1] = __floats2half2_rn(v.z, v.w);
    }
}

// ---------------- transpose f32 -> f16 ----------------
__global__ void transpose_f32h(const float* __restrict__ in, long long sIn, int ldin,
                               __half* __restrict__ out, long long sOut, int ldout)
{
    __shared__ float t[32][33];
    const float* ib = in + (size_t)blockIdx.z * sIn;
    __half* ob = out + (size_t)blockIdx.z * sOut;
    int x0 = blockIdx.x * 32, y0 = blockIdx.y * 32;
    int tx = threadIdx.x, ty = threadIdx.y;
#pragma unroll
    for (int j = 0; j < 32; j += 8)
        t[ty + j][tx] = ib[(size_t)(y0 + ty + j) * ldin + x0 + tx];
    __syncthreads();
#pragma unroll
    for (int j = 0; j < 32; j += 8)
        ob[(size_t)(x0 + ty + j) * ldout + y0 + tx] = __float2half_rn(t[tx][ty + j]);
}

// ---------------- fused: LN(qa) + LN(kv_c) + rope(k_pe)*SCALE ----------------
__global__ void __launch_bounds__(128)
ln_all(const float* __restrict__ in /* g_qakva */,
       const float* __restrict__ wq, const float* __restrict__ wkv,
       const float* __restrict__ cosb, const float* __restrict__ sinb)
{
    const int r = blockIdx.x, tid = threadIdx.x;
    const int lane = tid & 31, warp = tid >> 5;
    __shared__ float sm4[4];
    __shared__ float stats[2];

    const float4* xq = (const float4*)(in + (size_t)r * NQK);
    float4 v[3];
    float s = 0.f;
#pragma unroll
    for (int q = 0; q < 3; q++) {
        v[q] = xq[tid + q * 128];
        s += v[q].x + v[q].y + v[q].z + v[q].w;
    }
#pragma unroll
    for (int o = 16; o > 0; o >>= 1) s += __shfl_xor_sync(0xffffffffu, s, o);
    if (lane == 0) sm4[warp] = s;
    __syncthreads();
    if (tid == 0) stats[0] = (sm4[0] + sm4[1] + sm4[2] + sm4[3]) / QLR;
    __syncthreads();
    float mean = stats[0];

    float vv = 0.f;
#pragma unroll
    for (int q = 0; q < 3; q++) {
        float dx = v[q].x - mean, dy = v[q].y - mean;
        float dz = v[q].z - mean, dw = v[q].w - mean;
        vv += dx * dx + dy * dy + dz * dz + dw * dw;
    }
#pragma unroll
    for (int o = 16; o > 0; o >>= 1) vv += __shfl_xor_sync(0xffffffffu, vv, o);
    if (lane == 0) sm4[warp] = vv;
    __syncthreads();
    if (tid == 0) stats[1] = rsqrtf((sm4[0] + sm4[1] + sm4[2] + sm4[3]) / QLR + 1e-5f);
    __syncthreads();
    float rstd = stats[1];

    __half2* yq = (__half2*)(g_qaln + (size_t)r * QLR);
#pragma unroll
    for (int q = 0; q < 3; q++) {
        float4 ww = ((const float4*)wq)[tid + q * 128];
        int c = tid + q * 128;
        yq[2 * c]     = __floats2half2_rn((v[q].x - mean) * rstd * ww.x,
                                          (v[q].y - mean) * rstd * ww.y);
        yq[2 * c + 1] = __floats2half2_rn((v[q].z - mean) * rstd * ww.z,
                                          (v[q].w - mean) * rstd * ww.w);
    }
    __syncthreads();

    float4 vk = ((const float4*)(in + (size_t)r * NQK + QLR))[tid];
    s = vk.x + vk.y + vk.z + vk.w;
#pragma unroll
    for (int o = 16; o > 0; o >>= 1) s += __shfl_xor_sync(0xffffffffu, s, o);
    if (lane == 0) sm4[warp] = s;
    __syncthreads();
    if (tid == 0) stats[0] = (sm4[0] + sm4[1] + sm4[2] + sm4[3]) / KVLR;
    __syncthreads();
    mean = stats[0];

    float dx = vk.x - mean, dy = vk.y - mean, dz = vk.z - mean, dw = vk.w - mean;
    vv = dx * dx + dy * dy + dz * dz + dw * dw;
#pragma unroll
    for (int o = 16; o > 0; o >>= 1) vv += __shfl_xor_sync(0xffffffffu, vv, o);
    if (lane == 0) sm4[warp] = vv;
    __syncthreads();
    if (tid == 0) stats[1] = rsqrtf((sm4[0] + sm4[1] + sm4[2] + sm4[3]) / KVLR + 1e-5f);
    __syncthreads();
    rstd = stats[1];

    __half2* yk = (__half2*)(g_kattn + (size_t)r * DATT);
    float4 wwk = ((const float4*)wkv)[tid];
    yk[2 * tid]     = __floats2half2_rn((vk.x - mean) * rstd * wwk.x,
                                        (vk.y - mean) * rstd * wwk.y);
    yk[2 * tid + 1] = __floats2half2_rn((vk.z - mean) * rstd * wwk.z,
                                        (vk.w - mean) * rstd * wwk.w);

    if (tid < ROPE) {
        const int i = tid;
        const int b = r >> 10, srow = r & (Sb - 1);
        const float* pe = in + (size_t)r * NQK + QLR + KVLR;
        float xx = pe[i];
        float other = pe[(i < 32) ? (i + 32) : (i - 32)];
        float rot = (i < 32) ? -other : other;
        __half hv = __float2half_rn((xx * cosb[r * ROPE + i] + rot * sinb[r * ROPE + i]) * SCALE);
#pragma unroll
        for (int h = 0; h < NH; h++)
            g_kb[(((size_t)(b * NH + h) * Sb) + srow) * QKD + NOPE + i] = hv;
    }
}

// ---------------- RoPE q_pe: in-place on g_q ----------------
__global__ void rope_q(const float* __restrict__ cosb, const float* __restrict__ sinb)
{
    int bs = blockIdx.x >> 4;
    int h  = blockIdx.x & 15;
    int i  = threadIdx.x;
    __half* base = g_q + (size_t)bs * (NH * QKD) + h * QKD + NOPE;
    float x = __half2float(base[i]);
    float other = __half2float(base[(i < 32) ? (i + 32) : (i - 32)]);
    __syncthreads();
    float rot = (i < 32) ? -other : other;
    base[i] = __float2half_rn(x * cosb[bs * ROPE + i] + rot * sinb[bs * ROPE + i]);
}

// ---------------- launch ----------------
extern "C" void kernel_launch(void* const* d_in, const int* in_sizes, int n_in,
                              void* d_out, int out_size)
{
    const float* hidden  = (const float*)d_in[0];
    const float* cosb    = (const float*)d_in[1];
    const float* sinb    = (const float*)d_in[2];
    const float* w_qa    = (const float*)d_in[3];
    const float* qalnw   = (const float*)d_in[4];
    const float* w_qb    = (const float*)d_in[5];
    const float* w_kva   = (const float*)d_in[6];
    const float* kvalnw  = (const float*)d_in[7];
    const float* W_UK_T  = (const float*)d_in[8];
    const float* W_UV    = (const float*)d_in[9];
    const float* w_o     = (const float*)d_in[10];
    float* out = (float*)d_out;

    float *p_qakva;
    __half *p_hid, *p_wqkv, *p_wqb, *p_wo, *p_wuk;
    __half *p_qaln, *p_q, *p_kattn, *p_kb, *p_vT, *p_of, *p_wuvT;
    cudaGetSymbolAddress((void**)&p_qakva, g_qakva);
    cudaGetSymbolAddress((void**)&p_hid,   g_hid);
    cudaGetSymbolAddress((void**)&p_wqkv,  g_wqkv);
    cudaGetSymbolAddress((void**)&p_wqb,   g_wqb);
    cudaGetSymbolAddress((void**)&p_wo,    g_wo);
    cudaGetSymbolAddress((void**)&p_wuk,   g_wuk);
    cudaGetSymbolAddress((void**)&p_qaln,  g_qaln);
    cudaGetSymbolAddress((void**)&p_q,     g_q);
    cudaGetSymbolAddress((void**)&p_kattn, g_kattn);
    cudaGetSymbolAddress((void**)&p_kb,    g_kb);
    cudaGetSymbolAddress((void**)&p_vT,    g_vT);
    cudaGetSymbolAddress((void**)&p_of,    g_outfl);
    cudaGetSymbolAddress((void**)&p_wuvT,  g_wuvT);

    cudaFuncSetAttribute(mma_gemm, cudaFuncAttributeMaxDynamicSharedMemorySize, SMEM_GEMM);
    cudaFuncSetAttribute(flash_attn, cudaFuncAttributeMaxDynamicSharedMemorySize, SMEM_FLASH);

    auto grid = [](int M, int N, int z) {
        return dim3((N + BN - 1) / BN, (M + BM - 1) / BM, z);
    };
    const int T = 128;

    cudaStream_t sB;
    cudaStreamCreateWithFlags(&sB, cudaStreamNonBlocking);
    cudaEvent_t evFork, evSideReady, evKV, evJoin;
    cudaEventCreateWithFlags(&evFork, cudaEventDisableTiming);
    cudaEventCreateWithFlags(&evSideReady, cudaEventDisableTiming);
    cudaEventCreateWithFlags(&evKV, cudaEventDisableTiming);
    cudaEventCreateWithFlags(&evJoin, cudaEventDisableTiming);

    cudaEventRecord(evFork, 0);
    cudaStreamWaitEvent(sB, evFork, 0);

    // side: convert wqb/wo/wuk + transpose W_UV (overlaps GEMM1)
    cvt_rest<<<1024, 256, 0, sB>>>(w_qb, w_o, W_UK_T);
    transpose_f32h<<<dim3(4, 16, NH), dim3(32, 8), 0, sB>>>(
        W_UV, (long long)KVLR * VD, VD, p_wuvT, (long long)VD * KVLR, KVLR);
    cudaEventRecord(evSideReady, sB);

    // main: convert hid + wqa|wkva
    cvt_main<<<1024, 256>>>(hidden, w_qa, w_kva);

    // 1+2) qakva(f32) = hid @ [wqa|wkva]^T   [2048,2112] K=2048
    mma_gemm<<<grid(MBS, NQK, 1), T, SMEM_GEMM>>>(
        p_hid, Hd, 0,1,0,1,  p_wqkv, Hd, 0,1,0,1,  p_qakva, NQK, 0,1,0,1,
        MBS, NQK, Hd, 0, 1.f);

    // 3+4+5) LN(qa), LN(kv_c), rope(k_pe)
    ln_all<<<MBS, 128>>>(p_qakva, qalnw, kvalnw, cosb, sinb);
    cudaEventRecord(evKV, 0);

    // side: V' and K'
    cudaStreamWaitEvent(sB, evKV, 0);
    mma_gemm<<<grid(VD, Sb, Bb * NH), T, SMEM_GEMM, sB>>>(
        p_wuvT, KVLR, 0,1, (long long)VD * KVLR, NH,
        p_kattn, DATT, (long long)Sb * DATT, NH, 0, 1,
        p_vT, Sb, (long long)VD * Sb, 1, 0, 1,
        VD, Sb, KVLR, 1, 1.f);
    mma_gemm<<<grid(Sb, NOPE, Bb * NH), T, SMEM_GEMM, sB>>>(
        p_kattn, DATT, (long long)Sb * DATT, NH, 0, 1,
        p_wuk, KVLR, 0,1, (long long)NOPE * KVLR, NH,
        p_kb, QKD, (long long)Sb * QKD, 1, 0, 1,
        Sb, NOPE, KVLR, 1, SCALE);
    cudaEventRecord(evJoin, sB);

    // main: q projection + rope
    cudaStreamWaitEvent(0, evSideReady, 0);
    mma_gemm<<<grid(MBS, NH * QKD, 1), T, SMEM_GEMM>>>(
        p_qaln, QLR, 0,1,0,1,  p_wqb, QLR, 0,1,0,1,  p_q, NH * QKD, 0,1,0,1,
        MBS, NH * QKD, QLR, 1, 1.f);
    rope_q<<<MBS * NH, 64>>>(cosb, sinb);

    cudaStreamWaitEvent(0, evJoin, 0);

    // 9-11) fused flash attention
    flash_attn<<<256, 256, SMEM_FLASH>>>(p_q, p_kb, p_vT, p_of);

    // 13) out(f32) = outfl @ wo^T  [2048,2048] K=2048
    mma_gemm<<<grid(MBS, Hd, 1), T, SMEM_GEMM>>>(
        p_of, NH * VD, 0,1,0,1,  p_wo, NH * VD, 0,1,0,1,  out, Hd, 0,1,0,1,
        MBS, Hd, NH * VD, 0, 1.f);
}